// round 3
// baseline (speedup 1.0000x reference)
#include <cuda_runtime.h>
#include <math.h>

// ---------------- scratch buffers (device globals; no allocation) ----------------
__device__ float g_h1[10485760];        // (n,32,L) ping
__device__ float g_h2[10485760];        // (n,32,L) pong
__device__ float g_res[10485760];       // dilated residual
__device__ float g_skip[83755008];      // (256c, 256b, 1279j)  j indexed from END
__device__ float g_y1[41680896];        // (128c, 256b, 1272t)
__device__ float g_p1[20801536];        // (128c, 256b, 635t)
__device__ float g_y2[5201920];         // (32c, 256b, 635t)
__device__ float g_p2[2596864];         // (32c, 256b, 317t)
__device__ float g_fc1[262144];         // (1024m, 256b)
__device__ float g_fc2[65536];          // (256m, 256b)

// ---------------- start conv: h[b,c,t] = sum_i w[c,i] * x[b,i,t] ----------------
__global__ void start_conv_kernel(const float* __restrict__ x, const float* __restrict__ w,
                                  float* __restrict__ h)
{
    int idx = blockIdx.x * 256 + threadIdx.x;
    if (idx >= 256 * 32 * 1280) return;
    int t = idx % 1280;
    int c = (idx / 1280) & 31;
    int b = idx / (1280 * 32);
    const float* xb = x + b * 5 * 1280 + t;
    const float* wc = w + c * 5;
    float s = 0.f;
#pragma unroll
    for (int i = 0; i < 5; i++) s += wc[i] * xb[i * 1280];
    h[idx] = s;
}

// ---------------- dilate: out[b',c,t'] = in_pad[flat % n_in, c, flat / n_in - pad] ----
__global__ void dilate_kernel(const float* __restrict__ in, float* __restrict__ out,
                              int n_in, int L_in, int n_out, int L_out, int pad)
{
    int idx = blockIdx.x * 256 + threadIdx.x;
    int total = n_out * 32 * L_out;
    if (idx >= total) return;
    int t = idx % L_out;
    int c = (idx / L_out) & 31;
    int b = idx / (L_out * 32);
    int flat = t * n_out + b;
    int bi = flat % n_in;
    int ti = flat / n_in - pad;
    out[idx] = (ti >= 0) ? in[(bi * 32 + c) * L_in + ti] : 0.f;
}

// ---------------- fused k=2 conv + tanh*sigmoid gate ----------------
// R: (n,32,Lr). O: (n,32,Lout=Lr-1). Weights (32o,32i,2tap).
__global__ void __launch_bounds__(256) conv2_gate_kernel(
    const float* __restrict__ R, const float* __restrict__ Wf, const float* __restrict__ Wg,
    float* __restrict__ O, int Lr, int Lout)
{
    __shared__ float Rs[32][34];
    __shared__ float wf0[32][32], wf1[32][32], wg0[32][32], wg1[32][32];
    int b = blockIdx.y;
    int t0 = blockIdx.x * 32;
    int tid = threadIdx.x;
    for (int i = tid; i < 1024; i += 256) {
        int c = i >> 5, k = i & 31;
        wf0[k][c] = Wf[(c * 32 + k) * 2];
        wf1[k][c] = Wf[(c * 32 + k) * 2 + 1];
        wg0[k][c] = Wg[(c * 32 + k) * 2];
        wg1[k][c] = Wg[(c * 32 + k) * 2 + 1];
    }
    const float* Rb = R + b * 32 * Lr;
    for (int i = tid; i < 32 * 33; i += 256) {
        int ch = i / 33, tt = i % 33;
        int t = t0 + tt;
        Rs[ch][tt] = (t < Lr) ? Rb[ch * Lr + t] : 0.f;
    }
    __syncthreads();
    int c = tid & 31, g = tid >> 5;
    float aF[4] = {0, 0, 0, 0}, aG[4] = {0, 0, 0, 0};
#pragma unroll
    for (int k = 0; k < 32; k++) {
        float f0 = wf0[k][c], f1 = wf1[k][c], h0 = wg0[k][c], h1 = wg1[k][c];
        float r[5];
#pragma unroll
        for (int j = 0; j < 5; j++) r[j] = Rs[k][g * 4 + j];
#pragma unroll
        for (int j = 0; j < 4; j++) {
            aF[j] += f0 * r[j] + f1 * r[j + 1];
            aG[j] += h0 * r[j] + h1 * r[j + 1];
        }
    }
    float* Ob = O + (b * 32 + c) * Lout;
#pragma unroll
    for (int j = 0; j < 4; j++) {
        int t = t0 + g * 4 + j;
        if (t < Lout) {
            float sg = 1.f / (1.f + __expf(-aG[j]));
            Ob[t] = tanhf(aF[j]) * sg;
        }
    }
}

// ---------------- residual 1x1 conv + add (in place on Hn) ----------------
// Hn[b,c,t] = sum_k Wr[c,k]*Hn[b,k,t] + R[b,c,t+1]
__global__ void __launch_bounds__(256) resadd_kernel(
    float* __restrict__ Hn, const float* __restrict__ R, const float* __restrict__ Wr,
    int Lout, int Lr)
{
    __shared__ float S[32][33];
    __shared__ float W[32][32];
    int b = blockIdx.y;
    int t0 = blockIdx.x * 32;
    int tid = threadIdx.x;
    for (int i = tid; i < 1024; i += 256) {
        int c = i >> 5, k = i & 31;
        W[k][c] = Wr[c * 32 + k];
    }
    float* Hb = Hn + b * 32 * Lout;
    for (int i = tid; i < 1024; i += 256) {
        int ch = i >> 5, tt = i & 31;
        int t = t0 + tt;
        S[ch][tt] = (t < Lout) ? Hb[ch * Lout + t] : 0.f;
    }
    __syncthreads();
    int c = tid & 31, g = tid >> 5;
    float acc[4] = {0, 0, 0, 0};
#pragma unroll
    for (int k = 0; k < 32; k++) {
        float w = W[k][c];
#pragma unroll
        for (int j = 0; j < 4; j++) acc[j] += w * S[k][g * 4 + j];
    }
    const float* Rb = R + (b * 32 + c) * Lr;
#pragma unroll
    for (int j = 0; j < 4; j++) {
        int t = t0 + g * 4 + j;
        if (t < Lout) Hb[c * Lout + t] = acc[j] + Rb[t + 1];
    }
}

// ---------------- generic 64x64 tiled GEMM: C[m,p] = sum_k A[m,k]*B(k,p) ----------------
template <class BL, class EP>
__global__ void __launch_bounds__(256) gemm64_kernel(const float* __restrict__ A,
                                                     int M, int K, int N, BL bl, EP ep)
{
    __shared__ float As[32][68];
    __shared__ float Bs[32][68];
    int mBase = blockIdx.y << 6;
    int pBase = blockIdx.x << 6;
    int tid = threadIdx.x;
    int tx = tid & 15, ty = tid >> 4;
    float acc[4][4];
#pragma unroll
    for (int i = 0; i < 4; i++)
#pragma unroll
        for (int j = 0; j < 4; j++) acc[i][j] = 0.f;

    for (int kb = 0; kb < K; kb += 32) {
#pragma unroll
        for (int i = 0; i < 8; i++) {
            int idx = tid + (i << 8);
            int m = idx >> 5, k = idx & 31;
            int mm = mBase + m;
            As[k][m] = (mm < M) ? A[mm * K + kb + k] : 0.f;
        }
#pragma unroll
        for (int i = 0; i < 8; i++) {
            int idx = tid + (i << 8);
            int k = idx >> 6, p = idx & 63;
            Bs[k][p] = bl(kb + k, pBase + p);
        }
        __syncthreads();
#pragma unroll
        for (int k = 0; k < 32; k++) {
            float4 a4 = *(const float4*)&As[k][ty << 2];
            float4 b4 = *(const float4*)&Bs[k][tx << 2];
            float a[4] = {a4.x, a4.y, a4.z, a4.w};
            float bb[4] = {b4.x, b4.y, b4.z, b4.w};
#pragma unroll
            for (int i = 0; i < 4; i++)
#pragma unroll
                for (int j = 0; j < 4; j++) acc[i][j] += a[i] * bb[j];
        }
        __syncthreads();
    }
#pragma unroll
    for (int i = 0; i < 4; i++) {
        int m = mBase + (ty << 2) + i;
        if (m >= M) continue;
#pragma unroll
        for (int j = 0; j < 4; j++) {
            int p = pBase + (tx << 2) + j;
            if (p < N) ep.store(m, p, acc[i][j]);
        }
    }
}

// ---- B loaders / epilogues ----

// skip conv: B(k,p) = s[b, k, ts] with inverse-dilate gather from Hn (n_r,32,Lh)
struct BLSkip {
    const float* hn;
    int n_r, Lh, Ls, Nn;
    __device__ float operator()(int k, int p) const {
        if (p >= Nn) return 0.f;
        int b = p / Ls, j = p - b * Ls;
        int ts = Ls - 1 - j;
        int flat = ts * 256 + b;
        int bi = flat % n_r;
        int ti = flat / n_r;
        return hn[(bi * 32 + k) * Lh + ti];
    }
};
struct EPSkip {
    float* skip;
    int Ls, accf;
    __device__ void store(int m, int p, float v) const {
        int b = p / Ls, j = p - b * Ls;
        int idx = (m * 256 + b) * 1279 + j;
        skip[idx] = accf ? (skip[idx] + v) : v;
    }
};

// end1: B(k,p) = relu(skip[k, b, j=1271-t]) ; p=(b,t), t in [0,1272)
struct BLEnd1 {
    const float* skip;
    __device__ float operator()(int k, int p) const {
        int b = p / 1272, t = p - b * 1272;
        int j = 1271 - t;
        float v = skip[(k * 256 + b) * 1279 + j];
        return fmaxf(v, 0.f);
    }
};
struct EPEnd1 {
    const float* bias;
    float* out;
    __device__ void store(int m, int p, float v) const {
        int b = p / 1272, t = p - b * 1272;
        out[(m * 256 + b) * 1272 + t] = fmaxf(v + bias[m], 0.f);
    }
};

// end2: B(k,p) = p1[k, b, t] ; p=(b,t), t in [0,635)
struct BLEnd2 {
    const float* p1;
    __device__ float operator()(int k, int p) const {
        int b = p / 635, t = p - b * 635;
        return p1[(k * 256 + b) * 635 + t];
    }
};
struct EPEnd2 {
    const float* bias;
    float* out;
    __device__ void store(int m, int p, float v) const {
        int b = p / 635, t = p - b * 635;
        out[(m * 256 + b) * 635 + t] = fmaxf(v + bias[m], 0.f);
    }
};

// fc1: B(k,b) = p2[c=k/317, b, t=k%317]
struct BLFC1 {
    const float* p2;
    __device__ float operator()(int k, int p) const {
        if (p >= 256) return 0.f;
        int c = k / 317, t = k - c * 317;
        return p2[(c * 256 + p) * 317 + t];
    }
};
// fc2: B(k,b) = f1[k*256+b]
struct BLFC2 {
    const float* f1;
    __device__ float operator()(int k, int p) const {
        if (p >= 256) return 0.f;
        return f1[k * 256 + p];
    }
};
struct EPFC {
    const float* bias;
    float* out;
    __device__ void store(int m, int p, float v) const {
        out[m * 256 + p] = fmaxf(v + bias[m], 0.f);
    }
};

// ---------------- maxpool k=3 s=2 (VALID) over last dim ----------------
__global__ void pool_kernel(const float* __restrict__ in, float* __restrict__ out,
                            int Lin, int Lout, int total)
{
    int idx = blockIdx.x * 256 + threadIdx.x;
    if (idx >= total) return;
    int t = idx % Lout;
    int rb = idx / Lout;
    const float* p = in + rb * Lin + 2 * t;
    out[idx] = fmaxf(fmaxf(p[0], p[1]), p[2]);
}

// ---------------- fc3 + softmax + argmax, writes final output ----------------
// out layout (float32): [0:512) logits (b,2), [512:1024) probs (b,2), [1024:1280) argmax
__global__ void fc3_softmax_kernel(const float* __restrict__ F2, const float* __restrict__ W3,
                                   const float* __restrict__ B3, float* __restrict__ out)
{
    int b = threadIdx.x;
    float l0 = B3[0], l1 = B3[1];
    for (int k = 0; k < 256; k++) {
        float v = F2[k * 256 + b];
        l0 += W3[k] * v;
        l1 += W3[256 + k] * v;
    }
    out[2 * b] = l0;
    out[2 * b + 1] = l1;
    float mx = fmaxf(l0, l1);
    float e0 = __expf(l0 - mx), e1 = __expf(l1 - mx);
    float inv = 1.f / (e0 + e1);
    out[512 + 2 * b] = e0 * inv;
    out[512 + 2 * b + 1] = e1 * inv;
    out[1024 + b] = (l1 > l0) ? 1.f : 0.f;
}

// ---------------- host orchestration ----------------
extern "C" void kernel_launch(void* const* d_in, const int* in_sizes, int n_in,
                              void* d_out, int out_size)
{
    const float* x        = (const float*)d_in[0];
    const float* start_w  = (const float*)d_in[1];
    const float* filter_w = (const float*)d_in[2];
    const float* gate_w   = (const float*)d_in[3];
    const float* res_w    = (const float*)d_in[4];
    const float* skip_w   = (const float*)d_in[5];
    const float* end1_w   = (const float*)d_in[6];
    const float* end1_b   = (const float*)d_in[7];
    const float* end2_w   = (const float*)d_in[8];
    const float* end2_b   = (const float*)d_in[9];
    const float* fc_w1    = (const float*)d_in[10];
    const float* fc_b1    = (const float*)d_in[11];
    const float* fc_w2    = (const float*)d_in[12];
    const float* fc_b2    = (const float*)d_in[13];
    const float* fc_w3    = (const float*)d_in[14];
    const float* fc_b3    = (const float*)d_in[15];

    float *h1, *h2, *res, *skip, *y1, *p1, *y2, *p2, *f1, *f2;
    cudaGetSymbolAddress((void**)&h1, g_h1);
    cudaGetSymbolAddress((void**)&h2, g_h2);
    cudaGetSymbolAddress((void**)&res, g_res);
    cudaGetSymbolAddress((void**)&skip, g_skip);
    cudaGetSymbolAddress((void**)&y1, g_y1);
    cudaGetSymbolAddress((void**)&p1, g_p1);
    cudaGetSymbolAddress((void**)&y2, g_y2);
    cudaGetSymbolAddress((void**)&p2, g_p2);
    cudaGetSymbolAddress((void**)&f1, g_fc1);
    cudaGetSymbolAddress((void**)&f2, g_fc2);

    // start conv
    {
        int total = 256 * 32 * 1280;
        start_conv_kernel<<<(total + 255) / 256, 256>>>(x, start_w, h1);
    }

    float* H = h1;
    float* HN = h2;
    int n = 256, Lh = 1280;
    const int DD[6] = {1, 2, 4, 1, 2, 4};
    const int II[6] = {1, 1, 2, 4, 1, 2};

    for (int i = 0; i < 6; i++) {
        int d = DD[i], idil = II[i];
        const float* R;
        int n_r, L_r;
        if (d == idil) {
            R = H; n_r = n; L_r = Lh;
        } else if (d > idil) {
            int f = d / idil;                        // 2
            int newl = ((Lh + f - 1) / f) * f;
            int pad = newl - Lh;
            n_r = n * f;
            L_r = newl / f;
            int total = n_r * 32 * L_r;
            dilate_kernel<<<(total + 255) / 256, 256>>>(H, res, n, Lh, n_r, L_r, pad);
            R = res;
        } else {
            int inv = idil / d;                      // 4 (layer 3)
            n_r = n / inv;
            L_r = Lh * inv;
            int total = n_r * 32 * L_r;
            dilate_kernel<<<(total + 255) / 256, 256>>>(H, res, n, Lh, n_r, L_r, 0);
            R = res;
        }
        int Lout = L_r - 1;
        dim3 cg((Lout + 31) / 32, n_r);
        conv2_gate_kernel<<<cg, 256>>>(R, filter_w + i * 2048, gate_w + i * 2048, HN, L_r, Lout);

        // skip contribution (inverse-dilate gather folded into B-loader)
        int Ls = Lout * (n_r / 256);
        int Nn = 256 * Ls;
        BLSkip bl = {HN, n_r, Lout, Ls, Nn};
        EPSkip ep = {skip, Ls, (i > 0) ? 1 : 0};
        dim3 gg((Nn + 63) / 64, 4);                  // M = 256
        gemm64_kernel<<<gg, 256>>>(skip_w + i * 8192, 256, 32, Nn, bl, ep);

        if (i < 5) {
            resadd_kernel<<<cg, 256>>>(HN, R, res_w + i * 1024, Lout, L_r);
        }
        float* tmp = H; H = HN; HN = tmp;
        n = n_r; Lh = Lout;
    }

    // end1: relu(W(128x256) x relu(skip) + b), time reversed back to forward order
    {
        BLEnd1 bl = {skip};
        EPEnd1 ep = {end1_b, y1};
        dim3 gg((256 * 1272) / 64, 2);
        gemm64_kernel<<<gg, 256>>>(end1_w, 128, 256, 256 * 1272, bl, ep);
    }
    // pool1: 1272 -> 635
    {
        int total = 128 * 256 * 635;
        pool_kernel<<<(total + 255) / 256, 256>>>(y1, p1, 1272, 635, total);
    }
    // end2
    {
        BLEnd2 bl = {p1};
        EPEnd2 ep = {end2_b, y2};
        dim3 gg((256 * 635 + 63) / 64, 1);
        gemm64_kernel<<<gg, 256>>>(end2_w, 32, 128, 256 * 635, bl, ep);
    }
    // pool2: 635 -> 317
    {
        int total = 32 * 256 * 317;
        pool_kernel<<<(total + 255) / 256, 256>>>(y2, p2, 635, 317, total);
    }
    // fc1: (1024 x 10144) @ flat, relu
    {
        BLFC1 bl = {p2};
        EPFC ep = {fc_b1, f1};
        dim3 gg(4, 16);
        gemm64_kernel<<<gg, 256>>>(fc_w1, 1024, 10144, 256, bl, ep);
    }
    // fc2: (256 x 1024), relu
    {
        BLFC2 bl = {f1};
        EPFC ep = {fc_b2, f2};
        dim3 gg(4, 4);
        gemm64_kernel<<<gg, 256>>>(fc_w2, 256, 1024, 256, bl, ep);
    }
    // fc3 + softmax + argmax -> d_out
    fc3_softmax_kernel<<<1, 256>>>(f2, fc_w3, fc_b3, (float*)d_out);
}

// round 4
// speedup vs baseline: 1.9052x; 1.9052x over previous
#include <cuda_runtime.h>
#include <math.h>

#define NP 325632   // 1272 * 256 : columns of the big GEMMs, p = t*256 + b

// ---------------- scratch (device globals; no allocation) ----------------
__device__ float g_r1[10485760];     // residual ping (n,32,L)
__device__ float g_r2[10485760];     // residual pong
__device__ float g_hn[62914560];     // 6 x gate outputs, natural [b][c][t]
__device__ float g_G[62521344];      // 192 x NP : transposed/aligned gate outs
__device__ float g_skip[83361792];   // 256 x NP : relu(skip)
__device__ float g_y1[41680896];     // 128 x NP
__device__ float g_p1[20801536];     // 128 x 635 x 256
__device__ float g_y2[5201920];      // 32 x 635 x 256
__device__ float g_p2[2596864];      // 32 x 317 x 256
__device__ float g_f1p[2097152];     // fc1 split-K partials 8 x 1024 x 256
__device__ float g_f1[262144];       // 1024 x 256
__device__ float g_f2p[262144];      // fc2 partials 4 x 256 x 256
__device__ float g_f2[65536];        // 256 x 256

// ---------------- start conv: h[b,c,t] = sum_i w[c,i] * x[b,i,t] ----------------
__global__ void start_conv_kernel(const float* __restrict__ x, const float* __restrict__ w,
                                  float* __restrict__ h)
{
    int idx = blockIdx.x * 256 + threadIdx.x;
    if (idx >= 256 * 32 * 1280) return;
    int t = idx % 1280;
    int c = (idx / 1280) & 31;
    int b = idx / (1280 * 32);
    const float* xb = x + b * 5 * 1280 + t;
    const float* wc = w + c * 5;
    float s = 0.f;
#pragma unroll
    for (int i = 0; i < 5; i++) s += wc[i] * xb[i * 1280];
    h[idx] = s;
}

// ---------------- fused dilate-gather + k=2 gated conv + residual 1x1 ----------------
// Hprev: (n_in,32,L_prev). Output Hn: (n_r,32,Lout) gate out; Hres: (n_r,32,Lout) residual.
__global__ void __launch_bounds__(256) dilgate_kernel(
    const float* __restrict__ Hprev,
    const float* __restrict__ Wf, const float* __restrict__ Wg, const float* __restrict__ Wr,
    float* __restrict__ Hn, float* __restrict__ Hres,
    int nin_mask, int lg_in, int pad, int L_prev,
    int n_r, int L_r, int Lout, int writeRes)
{
    __shared__ float Rs[32][34];
    __shared__ float wf0[32][32], wf1[32][32], wg0[32][32], wg1[32][32];
    __shared__ float wrs[32][32];
    __shared__ float Hs[32][33];

    int b  = blockIdx.y;
    int t0 = blockIdx.x * 32;
    int tid = threadIdx.x;

    for (int i = tid; i < 1024; i += 256) {
        int c = i >> 5, k = i & 31;
        wf0[k][c] = Wf[(c * 32 + k) * 2];
        wf1[k][c] = Wf[(c * 32 + k) * 2 + 1];
        wg0[k][c] = Wg[(c * 32 + k) * 2];
        wg1[k][c] = Wg[(c * 32 + k) * 2 + 1];
        wrs[k][c] = Wr[c * 32 + k];
    }
    // dilate-gather the residual tile: R[b,ch,t], t = t0..t0+32
    for (int i = tid; i < 32 * 33; i += 256) {
        int ch = i / 33, tt = i - ch * 33;
        int t = t0 + tt;
        float v = 0.f;
        if (t < L_r) {
            int flat = t * n_r + b;
            int bi = flat & nin_mask;
            int ti = (flat >> lg_in) - pad;
            if (ti >= 0) v = Hprev[(bi * 32 + ch) * L_prev + ti];
        }
        Rs[ch][tt] = v;
    }
    __syncthreads();

    int c = tid >> 3;        // 0..31  (channel)
    int g = tid & 7;         // 0..7   (t-group of 4)
    float aF[4] = {0, 0, 0, 0}, aG[4] = {0, 0, 0, 0};
#pragma unroll
    for (int k = 0; k < 32; k++) {
        float f0 = wf0[k][c], f1 = wf1[k][c], h0 = wg0[k][c], h1 = wg1[k][c];
        float r[5];
#pragma unroll
        for (int j = 0; j < 5; j++) r[j] = Rs[k][(g << 2) + j];
#pragma unroll
        for (int j = 0; j < 4; j++) {
            aF[j] += f0 * r[j] + f1 * r[j + 1];
            aG[j] += h0 * r[j] + h1 * r[j + 1];
        }
    }
    float hv[4];
#pragma unroll
    for (int j = 0; j < 4; j++) {
        float sg = 1.f / (1.f + __expf(-aG[j]));
        hv[j] = tanhf(aF[j]) * sg;
        Hs[c][(g << 2) + j] = hv[j];
    }
    float* On = Hn + (b * 32 + c) * Lout;
#pragma unroll
    for (int j = 0; j < 4; j++) {
        int local = (g << 2) + j;
        int t = t0 + local;
        if (t < Lout) On[t] = hv[j];
    }
    __syncthreads();
    if (writeRes) {
        float ar[4] = {0, 0, 0, 0};
#pragma unroll
        for (int k = 0; k < 32; k++) {
            float w = wrs[k][c];
#pragma unroll
            for (int j = 0; j < 4; j++) ar[j] += w * Hs[k][(g << 2) + j];
        }
        float* Or = Hres + (b * 32 + c) * Lout;
#pragma unroll
        for (int j = 0; j < 4; j++) {
            int local = (g << 2) + j;
            int t = t0 + local;
            if (t < Lout) Or[t] = ar[j] + Rs[c][local + 1];
        }
    }
}

// ---------------- transpose Hn (b,c,t) -> G row-window [c][flat-off], flat=t*n_r+b ----
__global__ void transpose_kernel(const float* __restrict__ Hn, float* __restrict__ Gl,
                                 int n_r, int Lout, int off)
{
    __shared__ float S[32][33];
    int t0 = blockIdx.x << 5;
    int b0 = blockIdx.y << 5;
    int c  = blockIdx.z;
    int col = threadIdx.x & 31;
    int r0  = threadIdx.x >> 5;     // 0..7
#pragma unroll
    for (int l = 0; l < 4; l++) {
        int r = r0 + (l << 3);
        int t = t0 + col;
        S[r][col] = (t < Lout) ? Hn[((b0 + r) * 32 + c) * Lout + t] : 0.f;
    }
    __syncthreads();
    float* Gc = Gl + c * NP;
#pragma unroll
    for (int l = 0; l < 4; l++) {
        int r = r0 + (l << 3);      // t offset within tile
        int t = t0 + r;
        if (t < Lout) {
            int p = t * n_r + b0 + col - off;
            if (p >= 0) Gc[p] = S[col][r];
        }
    }
}

// ---------------- 128x128 GEMM, 8x8 micro-tile, functor A/B loaders + epilogue --------
template <class AL, class BL, class EP>
__global__ void __launch_bounds__(256, 2) gemm128_kernel(int nkb, AL al, BL bl, EP ep)
{
    __shared__ float As[16][132];
    __shared__ float Bs[16][132];
    int mBase = blockIdx.y << 7;
    int pBase = blockIdx.x << 7;
    int tid = threadIdx.x;
    int tx = tid & 15, ty = tid >> 4;
    float acc[8][8];
#pragma unroll
    for (int i = 0; i < 8; i++)
#pragma unroll
        for (int j = 0; j < 8; j++) acc[i][j] = 0.f;

    for (int kb = 0; kb < nkb; kb++) {
        int k0 = kb << 4;
#pragma unroll
        for (int l = 0; l < 8; l++) {
            int idx = (l << 8) + tid;
            int m = idx >> 4, k = idx & 15;
            As[k][m] = al(mBase + m, k0 + k);
        }
#pragma unroll
        for (int l = 0; l < 8; l++) {
            int idx = (l << 8) + tid;
            int p = idx & 127, k = idx >> 7;
            Bs[k][p] = bl(k0 + k, pBase + p);
        }
        __syncthreads();
#pragma unroll
        for (int k = 0; k < 16; k++) {
            float a[8], bb[8];
            *(float4*)(a)      = *(const float4*)&As[k][ty << 2];
            *(float4*)(a + 4)  = *(const float4*)&As[k][(ty << 2) + 64];
            *(float4*)(bb)     = *(const float4*)&Bs[k][tx << 2];
            *(float4*)(bb + 4) = *(const float4*)&Bs[k][(tx << 2) + 64];
#pragma unroll
            for (int i = 0; i < 8; i++)
#pragma unroll
                for (int j = 0; j < 8; j++) acc[i][j] += a[i] * bb[j];
        }
        __syncthreads();
    }
#pragma unroll
    for (int i = 0; i < 8; i++) {
        int m = mBase + ((i >> 2) << 6) + (ty << 2) + (i & 3);
#pragma unroll
        for (int j2 = 0; j2 < 2; j2++) {
            float4 v = make_float4(acc[i][j2 * 4], acc[i][j2 * 4 + 1],
                                   acc[i][j2 * 4 + 2], acc[i][j2 * 4 + 3]);
            int p = pBase + (j2 << 6) + (tx << 2);
            ep.store4(m, p, v);
        }
    }
}

struct ALSkipW {   // A(m, k=(i,c)) = skip_w[i][m][c]
    const float* w;
    __device__ float operator()(int m, int k) const {
        return w[((k >> 5) << 13) + (m << 5) + (k & 31)];
    }
};
struct ALRow {
    const float* A; int K;
    __device__ float operator()(int m, int k) const { return A[m * K + k]; }
};
struct BLRowNP {
    const float* B;
    __device__ float operator()(int k, int p) const { return B[k * NP + p]; }
};
struct EPRelu4 {
    float* out;
    __device__ void store4(int m, int p, float4 v) const {
        v.x = fmaxf(v.x, 0.f); v.y = fmaxf(v.y, 0.f);
        v.z = fmaxf(v.z, 0.f); v.w = fmaxf(v.w, 0.f);
        *(float4*)&out[m * NP + p] = v;
    }
};
struct EPBiasRelu4 {
    const float* bias; float* out;
    __device__ void store4(int m, int p, float4 v) const {
        float bb = bias[m];
        v.x = fmaxf(v.x + bb, 0.f); v.y = fmaxf(v.y + bb, 0.f);
        v.z = fmaxf(v.z + bb, 0.f); v.w = fmaxf(v.w + bb, 0.f);
        *(float4*)&out[m * NP + p] = v;
    }
};

// ---------------- 64x64 GEMM with split-K (small/medium GEMMs) ----------------
template <class AL, class BL, class EP>
__global__ void __launch_bounds__(256) gemm64_kernel(int totKB, int splitKB, AL al, BL bl, EP ep)
{
    __shared__ float As[32][68];
    __shared__ float Bs[32][68];
    int mBase = blockIdx.y << 6;
    int pBase = blockIdx.x << 6;
    int kb0 = blockIdx.z * splitKB;
    int kb1 = kb0 + splitKB; if (kb1 > totKB) kb1 = totKB;
    int tid = threadIdx.x;
    int tx = tid & 15, ty = tid >> 4;
    float acc[4][4];
#pragma unroll
    for (int i = 0; i < 4; i++)
#pragma unroll
        for (int j = 0; j < 4; j++) acc[i][j] = 0.f;

    for (int kb = kb0; kb < kb1; kb++) {
        int k0 = kb << 5;
#pragma unroll
        for (int i = 0; i < 8; i++) {
            int idx = tid + (i << 8);
            int m = idx >> 5, k = idx & 31;
            As[k][m] = al(mBase + m, k0 + k);
        }
#pragma unroll
        for (int i = 0; i < 8; i++) {
            int idx = tid + (i << 8);
            int k = idx >> 6, p = idx & 63;
            Bs[k][p] = bl(k0 + k, pBase + p);
        }
        __syncthreads();
#pragma unroll
        for (int k = 0; k < 32; k++) {
            float4 a4 = *(const float4*)&As[k][ty << 2];
            float4 b4 = *(const float4*)&Bs[k][tx << 2];
            float a[4] = {a4.x, a4.y, a4.z, a4.w};
            float bb[4] = {b4.x, b4.y, b4.z, b4.w};
#pragma unroll
            for (int i = 0; i < 4; i++)
#pragma unroll
                for (int j = 0; j < 4; j++) acc[i][j] += a[i] * bb[j];
        }
        __syncthreads();
    }
#pragma unroll
    for (int i = 0; i < 4; i++) {
        int m = mBase + (ty << 2) + i;
#pragma unroll
        for (int j = 0; j < 4; j++) {
            int p = pBase + (tx << 2) + j;
            ep.store(m, p, acc[i][j]);
        }
    }
}

struct ALRowG {    // row-major A with M guard
    const float* A; int K, M;
    __device__ float operator()(int m, int k) const {
        return (m < M) ? A[m * K + k] : 0.f;
    }
};
struct BLRow {
    const float* B; int N;
    __device__ float operator()(int k, int p) const { return B[k * N + p]; }
};
struct EPBiasReluG {
    const float* bias; float* out; int N, M;
    __device__ void store(int m, int p, float v) const {
        if (m < M) out[m * N + p] = fmaxf(v + bias[m], 0.f);
    }
};
struct EPPart {    // split-K partials: out[z][m][p<256]
    float* out; int Mstride;
    __device__ void store(int m, int p, float v) const {
        out[blockIdx.z * Mstride + m * 256 + p] = v;
    }
};

// ---------------- maxpool k=3 s=2 over middle dim, layout [m][t][256b] ----------------
__global__ void pool_kernel(const float* __restrict__ in, float* __restrict__ out,
                            int Lin, int Lout, int total)
{
    int idx = blockIdx.x * 256 + threadIdx.x;
    if (idx >= total) return;
    int b = idx & 255;
    int q = idx >> 8;
    int tp = q % Lout;
    int m = q / Lout;
    const float* p = in + (m * Lin + 2 * tp) * 256 + b;
    out[idx] = fmaxf(fmaxf(p[0], p[256]), p[512]);
}

// ---------------- split-K reduce + bias + relu ----------------
__global__ void reduce_kernel(const float* __restrict__ part, const float* __restrict__ bias,
                              float* __restrict__ out, int S, int Mstride, int total)
{
    int idx = blockIdx.x * 256 + threadIdx.x;
    if (idx >= total) return;
    int m = idx >> 8;
    float s = 0.f;
    for (int z = 0; z < S; z++) s += part[z * Mstride + idx];
    out[idx] = fmaxf(s + bias[m], 0.f);
}

// ---------------- fc3 + softmax + argmax ----------------
__global__ void fc3_softmax_kernel(const float* __restrict__ F2, const float* __restrict__ W3,
                                   const float* __restrict__ B3, float* __restrict__ out)
{
    int b = threadIdx.x;
    float l0 = B3[0], l1 = B3[1];
    for (int k = 0; k < 256; k++) {
        float v = F2[k * 256 + b];
        l0 += W3[k] * v;
        l1 += W3[256 + k] * v;
    }
    out[2 * b] = l0;
    out[2 * b + 1] = l1;
    float mx = fmaxf(l0, l1);
    float e0 = __expf(l0 - mx), e1 = __expf(l1 - mx);
    float inv = 1.f / (e0 + e1);
    out[512 + 2 * b] = e0 * inv;
    out[512 + 2 * b + 1] = e1 * inv;
    out[1024 + b] = (l1 > l0) ? 1.f : 0.f;
}

// ---------------- host orchestration ----------------
extern "C" void kernel_launch(void* const* d_in, const int* in_sizes, int n_in,
                              void* d_out, int out_size)
{
    const float* x        = (const float*)d_in[0];
    const float* start_w  = (const float*)d_in[1];
    const float* filter_w = (const float*)d_in[2];
    const float* gate_w   = (const float*)d_in[3];
    const float* res_w    = (const float*)d_in[4];
    const float* skip_w   = (const float*)d_in[5];
    const float* end1_w   = (const float*)d_in[6];
    const float* end1_b   = (const float*)d_in[7];
    const float* end2_w   = (const float*)d_in[8];
    const float* end2_b   = (const float*)d_in[9];
    const float* fc_w1    = (const float*)d_in[10];
    const float* fc_b1    = (const float*)d_in[11];
    const float* fc_w2    = (const float*)d_in[12];
    const float* fc_b2    = (const float*)d_in[13];
    const float* fc_w3    = (const float*)d_in[14];
    const float* fc_b3    = (const float*)d_in[15];

    float *r1, *r2, *hn, *G, *skip, *y1, *p1, *y2, *p2, *f1p, *f1, *f2p, *f2;
    cudaGetSymbolAddress((void**)&r1, g_r1);
    cudaGetSymbolAddress((void**)&r2, g_r2);
    cudaGetSymbolAddress((void**)&hn, g_hn);
    cudaGetSymbolAddress((void**)&G, g_G);
    cudaGetSymbolAddress((void**)&skip, g_skip);
    cudaGetSymbolAddress((void**)&y1, g_y1);
    cudaGetSymbolAddress((void**)&p1, g_p1);
    cudaGetSymbolAddress((void**)&y2, g_y2);
    cudaGetSymbolAddress((void**)&p2, g_p2);
    cudaGetSymbolAddress((void**)&f1p, g_f1p);
    cudaGetSymbolAddress((void**)&f1, g_f1);
    cudaGetSymbolAddress((void**)&f2p, g_f2p);
    cudaGetSymbolAddress((void**)&f2, g_f2);

    // start conv -> r1
    start_conv_kernel<<<(256 * 32 * 1280 + 255) / 256, 256>>>(x, start_w, r1);

    // per-layer constants
    //               n_in  lg pad Lprev  n_r   L_r  Lout   off
    const int NIN[6]  = {256, 256, 512, 1024, 256, 512};
    const int LG[6]   = {8, 8, 9, 10, 8, 9};
    const int PAD[6]  = {0, 1, 1, 0, 1, 1};
    const int LPRV[6] = {1280, 1279, 639, 319, 1275, 637};
    const int NR[6]   = {256, 512, 1024, 256, 512, 1024};
    const int LR[6]   = {1280, 640, 320, 1276, 638, 319};
    const int LOUT[6] = {1279, 639, 319, 1275, 637, 318};
    const int OFF[6]  = {1792, 1536, 1024, 768, 512, 0};

    float* Hp = r1;
    float* Hq = r2;
    for (int i = 0; i < 6; i++) {
        float* Hn_i = hn + i * 10485760;
        dim3 gd((LOUT[i] + 31) / 32, NR[i]);
        dilgate_kernel<<<gd, 256>>>(Hp, filter_w + i * 2048, gate_w + i * 2048,
                                    res_w + i * 1024, Hn_i, Hq,
                                    NIN[i] - 1, LG[i], PAD[i], LPRV[i],
                                    NR[i], LR[i], LOUT[i], (i < 5) ? 1 : 0);
        dim3 gt((LOUT[i] + 31) / 32, NR[i] / 32, 32);
        transpose_kernel<<<gt, 256>>>(Hn_i, G + i * 32 * NP, NR[i], LOUT[i], OFF[i]);
        float* t = Hp; Hp = Hq; Hq = t;
    }

    // skip GEMM: 256 x 192 x NP, relu epilogue
    {
        ALSkipW al = {skip_w};
        BLRowNP bl = {G};
        EPRelu4 ep = {skip};
        dim3 gg(NP / 128, 2);
        gemm128_kernel<<<gg, 256>>>(12, al, bl, ep);
    }
    // end1: 128 x 256 x NP, bias+relu
    {
        ALRow al = {end1_w, 256};
        BLRowNP bl = {skip};
        EPBiasRelu4 ep = {end1_b, y1};
        dim3 gg(NP / 128, 1);
        gemm128_kernel<<<gg, 256>>>(16, al, bl, ep);
    }
    // pool1: [128][1272][256] -> [128][635][256]
    {
        int total = 128 * 635 * 256;
        pool_kernel<<<(total + 255) / 256, 256>>>(y1, p1, 1272, 635, total);
    }
    // end2: 32 x 128 x 162560
    {
        ALRowG al = {end2_w, 128, 32};
        BLRow bl = {p1, 635 * 256};
        EPBiasReluG ep = {end2_b, y2, 635 * 256, 32};
        dim3 gg(635 * 256 / 64, 1, 1);
        gemm64_kernel<<<gg, 256>>>(4, 4, al, bl, ep);
    }
    // pool2: [32][635][256] -> [32][317][256]
    {
        int total = 32 * 317 * 256;
        pool_kernel<<<(total + 255) / 256, 256>>>(y2, p2, 635, 317, total);
    }
    // fc1: 1024 x 10144 x 256, split-K=8
    {
        ALRowG al = {fc_w1, 10144, 1024};
        BLRow bl = {p2, 256};
        EPPart ep = {f1p, 1024 * 256};
        dim3 gg(4, 16, 8);
        gemm64_kernel<<<gg, 256>>>(317, 40, al, bl, ep);
        int total = 1024 * 256;
        reduce_kernel<<<(total + 255) / 256, 256>>>(f1p, fc_b1, f1, 8, total, total);
    }
    // fc2: 256 x 1024 x 256, split-K=4
    {
        ALRowG al = {fc_w2, 1024, 256};
        BLRow bl = {f1, 256};
        EPPart ep = {f2p, 256 * 256};
        dim3 gg(4, 4, 4);
        gemm64_kernel<<<gg, 256>>>(32, 8, al, bl, ep);
        int total = 256 * 256;
        reduce_kernel<<<(total + 255) / 256, 256>>>(f2p, fc_b2, f2, 4, total, total);
    }
    // fc3 + softmax + argmax
    fc3_softmax_kernel<<<1, 256>>>(f2, fc_w3, fc_b3, (float*)d_out);
}

// round 5
// speedup vs baseline: 2.7681x; 1.4529x over previous
#include <cuda_runtime.h>
#include <math.h>

#define NP 325632   // 1272 * 256 : columns of the big GEMMs, p = t*256 + b

// ---------------- scratch (device globals; no allocation) ----------------
__device__ float g_r1[10485760];     // stream ping [32][<=327680]
__device__ float g_r2[10485760];     // stream pong
__device__ float g_G[62521344];      // 192 x NP : gate outputs, flat layout
__device__ float g_skip[83361792];   // 256 x NP : relu(skip)
__device__ float g_y1[41680896];     // 128 x NP (also reused as xT early)
__device__ float g_p1[20801536];     // 128 x 635 x 256
__device__ float g_y2[5201920];      // 32 x 635 x 256
__device__ float g_p2[2596864];      // 32 x 317 x 256
__device__ float g_f1p[2097152];     // fc1 split-K partials 8 x 1024 x 256
__device__ float g_f1[262144];       // 1024 x 256
__device__ float g_f2p[262144];      // fc2 partials 4 x 256 x 256
__device__ float g_f2[65536];        // 256 x 256

// ---------------- x (b,5,t) -> xT[i][p = t*256 + b] ----------------
__global__ void xpose_kernel(const float* __restrict__ x, float* __restrict__ xT)
{
    __shared__ float S[32][33];
    int i  = blockIdx.z;
    int t0 = blockIdx.x << 5;
    int b0 = blockIdx.y << 5;
    int col = threadIdx.x & 31;
    int r0  = threadIdx.x >> 5;
#pragma unroll
    for (int l = 0; l < 4; l++) {
        int bb = r0 + (l << 3);
        S[bb][col] = x[(b0 + bb) * 6400 + i * 1280 + t0 + col];
    }
    __syncthreads();
#pragma unroll
    for (int l = 0; l < 4; l++) {
        int tt = r0 + (l << 3);
        xT[i * 327680 + (t0 + tt) * 256 + b0 + col] = S[col][tt];
    }
}

// ---------------- start conv in flat layout: X0[c][p] = sum_i w[c,i]*xT[i][p] -------
__global__ void startflat_kernel(const float* __restrict__ xT, const float* __restrict__ w,
                                 float* __restrict__ X0)
{
    int p = blockIdx.x * 256 + threadIdx.x;
    int c = blockIdx.y;
    float acc = 0.f;
#pragma unroll
    for (int i = 0; i < 5; i++) acc += __ldg(&w[c * 5 + i]) * xT[i * 327680 + p];
    X0[c * 327680 + p] = acc;
}

// ---------------- fused flat-stream layer: gated k=2 conv + res 1x1 ----------------
// X: [32][Pin] input stream. Gout: [32][NP] gate output rows (this layer's slice).
// Rout: [32][Q] residual output stream.
// taps at (q - s) and (q - s + nr); res adds X[q - s + nr].
__device__ __forceinline__ float fast_gate(float f, float g)
{
    float ef = __expf(f + f);
    float th = 1.f - __fdividef(2.f, ef + 1.f);
    float sg = __fdividef(1.f, 1.f + __expf(-g));
    return th * sg;
}

__global__ void __launch_bounds__(128, 4) layer_kernel(
    const float* __restrict__ X,
    const float* __restrict__ Wf, const float* __restrict__ Wg, const float* __restrict__ Wr,
    float* __restrict__ Gout, float* __restrict__ Rout,
    int Pin, int Q, int nr, int s, int off, int writeRes)
{
    __shared__ float4 ws4[1024];        // [k][c] {f0,f1,g0,g1}; reused for wr in stage2
    __shared__ float  XaH[32][128];     // Xa tile, then H
    __shared__ float  Xb[32][128];

    int tid = threadIdx.x;
    int q0 = blockIdx.x << 7;

    for (int i = tid; i < 1024; i += 128) {
        int k = i >> 5, c = i & 31;
        int base = (c * 32 + k) * 2;
        ws4[i] = make_float4(Wf[base], Wf[base + 1], Wg[base], Wg[base + 1]);
    }
    int qa = q0 - s + tid;
#pragma unroll 4
    for (int r = 0; r < 32; r++) {
        const float* Xr = X + r * Pin;
        XaH[r][tid] = (qa >= 0) ? Xr[qa] : 0.f;
        Xb[r][tid]  = Xr[qa + nr];
    }
    __syncthreads();

    int tx = tid & 15, ty = tid >> 4;
    int cbase = ty << 2;
    int pcol = tx << 3;

    float aF[4][8], aG[4][8];
#pragma unroll
    for (int cc = 0; cc < 4; cc++)
#pragma unroll
        for (int j = 0; j < 8; j++) { aF[cc][j] = 0.f; aG[cc][j] = 0.f; }

#pragma unroll 2
    for (int k = 0; k < 32; k++) {
        float xav[8], xbv[8];
        *(float4*)&xav[0] = *(const float4*)&XaH[k][pcol];
        *(float4*)&xav[4] = *(const float4*)&XaH[k][pcol + 4];
        *(float4*)&xbv[0] = *(const float4*)&Xb[k][pcol];
        *(float4*)&xbv[4] = *(const float4*)&Xb[k][pcol + 4];
#pragma unroll
        for (int cc = 0; cc < 4; cc++) {
            float4 w = ws4[(k << 5) + cbase + cc];
#pragma unroll
            for (int j = 0; j < 8; j++) {
                aF[cc][j] += w.x * xav[j];
                aF[cc][j] += w.y * xbv[j];
                aG[cc][j] += w.z * xav[j];
                aG[cc][j] += w.w * xbv[j];
            }
        }
    }

    // activation
    float hv[4][8];
#pragma unroll
    for (int cc = 0; cc < 4; cc++)
#pragma unroll
        for (int j = 0; j < 8; j++) hv[cc][j] = fast_gate(aF[cc][j], aG[cc][j]);

    // write gate output directly into G (global p = q - off)
#pragma unroll
    for (int cc = 0; cc < 4; cc++) {
        int c = cbase + cc;
#pragma unroll
        for (int j2 = 0; j2 < 2; j2++) {
            int q = q0 + pcol + (j2 << 2);
            if (q >= off) {
                float4 v = make_float4(hv[cc][j2 * 4], hv[cc][j2 * 4 + 1],
                                       hv[cc][j2 * 4 + 2], hv[cc][j2 * 4 + 3]);
                *(float4*)&Gout[c * NP + q - off] = v;
            }
        }
    }

    if (writeRes) {
        __syncthreads();       // all stage-1 reads of XaH / ws4 done
        // H -> XaH; wr -> ws4 region
#pragma unroll
        for (int cc = 0; cc < 4; cc++) {
            int c = cbase + cc;
            *(float4*)&XaH[c][pcol]     = make_float4(hv[cc][0], hv[cc][1], hv[cc][2], hv[cc][3]);
            *(float4*)&XaH[c][pcol + 4] = make_float4(hv[cc][4], hv[cc][5], hv[cc][6], hv[cc][7]);
        }
        float* wrs = (float*)ws4;
        for (int i = tid; i < 1024; i += 128) {
            int k = i >> 5, c = i & 31;
            wrs[i] = Wr[c * 32 + k];
        }
        __syncthreads();

        float aR[4][8];
#pragma unroll
        for (int cc = 0; cc < 4; cc++)
#pragma unroll
            for (int j = 0; j < 8; j++) aR[cc][j] = 0.f;

#pragma unroll 2
        for (int k = 0; k < 32; k++) {
            float h8[8];
            *(float4*)&h8[0] = *(const float4*)&XaH[k][pcol];
            *(float4*)&h8[4] = *(const float4*)&XaH[k][pcol + 4];
#pragma unroll
            for (int cc = 0; cc < 4; cc++) {
                float w = wrs[(k << 5) + cbase + cc];
#pragma unroll
                for (int j = 0; j < 8; j++) aR[cc][j] += w * h8[j];
            }
        }
#pragma unroll
        for (int cc = 0; cc < 4; cc++) {
            int c = cbase + cc;
#pragma unroll
            for (int j2 = 0; j2 < 2; j2++) {
                float4 xb = *(const float4*)&Xb[c][pcol + (j2 << 2)];
                float4 v = make_float4(aR[cc][j2 * 4] + xb.x, aR[cc][j2 * 4 + 1] + xb.y,
                                       aR[cc][j2 * 4 + 2] + xb.z, aR[cc][j2 * 4 + 3] + xb.w);
                *(float4*)&Rout[c * Q + q0 + pcol + (j2 << 2)] = v;
            }
        }
    }
}

// ---------------- 128x128 GEMM, 8x8 micro-tile ----------------
template <class AL, class BL, class EP>
__global__ void __launch_bounds__(256, 2) gemm128_kernel(int nkb, AL al, BL bl, EP ep)
{
    __shared__ float As[16][132];
    __shared__ float Bs[16][132];
    int mBase = blockIdx.y << 7;
    int pBase = blockIdx.x << 7;
    int tid = threadIdx.x;
    int tx = tid & 15, ty = tid >> 4;
    float acc[8][8];
#pragma unroll
    for (int i = 0; i < 8; i++)
#pragma unroll
        for (int j = 0; j < 8; j++) acc[i][j] = 0.f;

    for (int kb = 0; kb < nkb; kb++) {
        int k0 = kb << 4;
#pragma unroll
        for (int l = 0; l < 8; l++) {
            int idx = (l << 8) + tid;
            int m = idx >> 4, k = idx & 15;
            As[k][m] = al(mBase + m, k0 + k);
        }
#pragma unroll
        for (int l = 0; l < 8; l++) {
            int idx = (l << 8) + tid;
            int p = idx & 127, k = idx >> 7;
            Bs[k][p] = bl(k0 + k, pBase + p);
        }
        __syncthreads();
#pragma unroll
        for (int k = 0; k < 16; k++) {
            float a[8], bb[8];
            *(float4*)(a)      = *(const float4*)&As[k][ty << 2];
            *(float4*)(a + 4)  = *(const float4*)&As[k][(ty << 2) + 64];
            *(float4*)(bb)     = *(const float4*)&Bs[k][tx << 2];
            *(float4*)(bb + 4) = *(const float4*)&Bs[k][(tx << 2) + 64];
#pragma unroll
            for (int i = 0; i < 8; i++)
#pragma unroll
                for (int j = 0; j < 8; j++) acc[i][j] += a[i] * bb[j];
        }
        __syncthreads();
    }
#pragma unroll
    for (int i = 0; i < 8; i++) {
        int m = mBase + ((i >> 2) << 6) + (ty << 2) + (i & 3);
#pragma unroll
        for (int j2 = 0; j2 < 2; j2++) {
            float4 v = make_float4(acc[i][j2 * 4], acc[i][j2 * 4 + 1],
                                   acc[i][j2 * 4 + 2], acc[i][j2 * 4 + 3]);
            int p = pBase + (j2 << 6) + (tx << 2);
            ep.store4(m, p, v);
        }
    }
}

struct ALSkipW {   // A(m, k=(i,c)) = skip_w[i][m][c]
    const float* w;
    __device__ float operator()(int m, int k) const {
        return w[((k >> 5) << 13) + (m << 5) + (k & 31)];
    }
};
struct ALRow {
    const float* A; int K;
    __device__ float operator()(int m, int k) const { return A[m * K + k]; }
};
struct BLRowNP {
    const float* B;
    __device__ float operator()(int k, int p) const { return B[k * NP + p]; }
};
struct EPRelu4 {
    float* out;
    __device__ void store4(int m, int p, float4 v) const {
        v.x = fmaxf(v.x, 0.f); v.y = fmaxf(v.y, 0.f);
        v.z = fmaxf(v.z, 0.f); v.w = fmaxf(v.w, 0.f);
        *(float4*)&out[m * NP + p] = v;
    }
};
struct EPBiasRelu4 {
    const float* bias; float* out;
    __device__ void store4(int m, int p, float4 v) const {
        float bb = bias[m];
        v.x = fmaxf(v.x + bb, 0.f); v.y = fmaxf(v.y + bb, 0.f);
        v.z = fmaxf(v.z + bb, 0.f); v.w = fmaxf(v.w + bb, 0.f);
        *(float4*)&out[m * NP + p] = v;
    }
};

// ---------------- 64x64 GEMM with split-K ----------------
template <class AL, class BL, class EP>
__global__ void __launch_bounds__(256) gemm64_kernel(int totKB, int splitKB, AL al, BL bl, EP ep)
{
    __shared__ float As[32][68];
    __shared__ float Bs[32][68];
    int mBase = blockIdx.y << 6;
    int pBase = blockIdx.x << 6;
    int kb0 = blockIdx.z * splitKB;
    int kb1 = kb0 + splitKB; if (kb1 > totKB) kb1 = totKB;
    int tid = threadIdx.x;
    int tx = tid & 15, ty = tid >> 4;
    float acc[4][4];
#pragma unroll
    for (int i = 0; i < 4; i++)
#pragma unroll
        for (int j = 0; j < 4; j++) acc[i][j] = 0.f;

    for (int kb = kb0; kb < kb1; kb++) {
        int k0 = kb << 5;
#pragma unroll
        for (int i = 0; i < 8; i++) {
            int idx = tid + (i << 8);
            int m = idx >> 5, k = idx & 31;
            As[k][m] = al(mBase + m, k0 + k);
        }
#pragma unroll
        for (int i = 0; i < 8; i++) {
            int idx = tid + (i << 8);
            int k = idx >> 6, p = idx & 63;
            Bs[k][p] = bl(k0 + k, pBase + p);
        }
        __syncthreads();
#pragma unroll
        for (int k = 0; k < 32; k++) {
            float4 a4 = *(const float4*)&As[k][ty << 2];
            float4 b4 = *(const float4*)&Bs[k][tx << 2];
            float a[4] = {a4.x, a4.y, a4.z, a4.w};
            float bb[4] = {b4.x, b4.y, b4.z, b4.w};
#pragma unroll
            for (int i = 0; i < 4; i++)
#pragma unroll
                for (int j = 0; j < 4; j++) acc[i][j] += a[i] * bb[j];
        }
        __syncthreads();
    }
#pragma unroll
    for (int i = 0; i < 4; i++) {
        int m = mBase + (ty << 2) + i;
#pragma unroll
        for (int j = 0; j < 4; j++) {
            int p = pBase + (tx << 2) + j;
            ep.store(m, p, acc[i][j]);
        }
    }
}

struct ALRowG {
    const float* A; int K, M;
    __device__ float operator()(int m, int k) const {
        return (m < M) ? A[m * K + k] : 0.f;
    }
};
struct BLRow {
    const float* B; int N;
    __device__ float operator()(int k, int p) const { return B[k * N + p]; }
};
struct EPBiasReluG {
    const float* bias; float* out; int N, M;
    __device__ void store(int m, int p, float v) const {
        if (m < M) out[m * N + p] = fmaxf(v + bias[m], 0.f);
    }
};
struct EPPart {
    float* out; int Mstride;
    __device__ void store(int m, int p, float v) const {
        out[blockIdx.z * Mstride + m * 256 + p] = v;
    }
};

// ---------------- maxpool k=3 s=2 over middle dim, layout [m][t][256b] ----------------
__global__ void pool_kernel(const float* __restrict__ in, float* __restrict__ out,
                            int Lin, int Lout, int total)
{
    int idx = blockIdx.x * 256 + threadIdx.x;
    if (idx >= total) return;
    int b = idx & 255;
    int q = idx >> 8;
    int tp = q % Lout;
    int m = q / Lout;
    const float* p = in + (m * Lin + 2 * tp) * 256 + b;
    out[idx] = fmaxf(fmaxf(p[0], p[256]), p[512]);
}

// ---------------- split-K reduce + bias + relu ----------------
__global__ void reduce_kernel(const float* __restrict__ part, const float* __restrict__ bias,
                              float* __restrict__ out, int S, int Mstride, int total)
{
    int idx = blockIdx.x * 256 + threadIdx.x;
    if (idx >= total) return;
    int m = idx >> 8;
    float s = 0.f;
    for (int z = 0; z < S; z++) s += part[z * Mstride + idx];
    out[idx] = fmaxf(s + bias[m], 0.f);
}

// ---------------- fc3 + softmax + argmax ----------------
__global__ void fc3_softmax_kernel(const float* __restrict__ F2, const float* __restrict__ W3,
                                   const float* __restrict__ B3, float* __restrict__ out)
{
    int b = threadIdx.x;
    float l0 = B3[0], l1 = B3[1];
    for (int k = 0; k < 256; k++) {
        float v = F2[k * 256 + b];
        l0 += W3[k] * v;
        l1 += W3[256 + k] * v;
    }
    out[2 * b] = l0;
    out[2 * b + 1] = l1;
    float mx = fmaxf(l0, l1);
    float e0 = __expf(l0 - mx), e1 = __expf(l1 - mx);
    float inv = 1.f / (e0 + e1);
    out[512 + 2 * b] = e0 * inv;
    out[512 + 2 * b + 1] = e1 * inv;
    out[1024 + b] = (l1 > l0) ? 1.f : 0.f;
}

// ---------------- host orchestration ----------------
extern "C" void kernel_launch(void* const* d_in, const int* in_sizes, int n_in,
                              void* d_out, int out_size)
{
    const float* x        = (const float*)d_in[0];
    const float* start_w  = (const float*)d_in[1];
    const float* filter_w = (const float*)d_in[2];
    const float* gate_w   = (const float*)d_in[3];
    const float* res_w    = (const float*)d_in[4];
    const float* skip_w   = (const float*)d_in[5];
    const float* end1_w   = (const float*)d_in[6];
    const float* end1_b   = (const float*)d_in[7];
    const float* end2_w   = (const float*)d_in[8];
    const float* end2_b   = (const float*)d_in[9];
    const float* fc_w1    = (const float*)d_in[10];
    const float* fc_b1    = (const float*)d_in[11];
    const float* fc_w2    = (const float*)d_in[12];
    const float* fc_b2    = (const float*)d_in[13];
    const float* fc_w3    = (const float*)d_in[14];
    const float* fc_b3    = (const float*)d_in[15];

    float *r1, *r2, *G, *skip, *y1, *p1, *y2, *p2, *f1p, *f1, *f2p, *f2;
    cudaGetSymbolAddress((void**)&r1, g_r1);
    cudaGetSymbolAddress((void**)&r2, g_r2);
    cudaGetSymbolAddress((void**)&G, g_G);
    cudaGetSymbolAddress((void**)&skip, g_skip);
    cudaGetSymbolAddress((void**)&y1, g_y1);
    cudaGetSymbolAddress((void**)&p1, g_p1);
    cudaGetSymbolAddress((void**)&y2, g_y2);
    cudaGetSymbolAddress((void**)&p2, g_p2);
    cudaGetSymbolAddress((void**)&f1p, g_f1p);
    cudaGetSymbolAddress((void**)&f1, g_f1);
    cudaGetSymbolAddress((void**)&f2p, g_f2p);
    cudaGetSymbolAddress((void**)&f2, g_f2);

    // x -> xT (flat, use y1 as scratch) -> start conv -> r1
    {
        dim3 gx(40, 8, 5);
        xpose_kernel<<<gx, 256>>>(x, y1);
        dim3 gs(1280, 32);
        startflat_kernel<<<gs, 256>>>(y1, start_w, r1);
    }

    // flat-stream layer constants
    const int PIN[6] = {327680, 327424, 327168, 326656, 326400, 326144};
    const int QQ[6]  = {327424, 327168, 326656, 326400, 326144, 325632};
    const int NR[6]  = {256, 512, 1024, 256, 512, 1024};
    const int SS[6]  = {0, 256, 512, 0, 256, 512};
    const int OFF[6] = {1792, 1536, 1024, 768, 512, 0};

    float* Hp = r1;
    float* Hq = r2;
    for (int i = 0; i < 6; i++) {
        int nblk = QQ[i] >> 7;
        layer_kernel<<<nblk, 128>>>(Hp, filter_w + i * 2048, gate_w + i * 2048,
                                    res_w + i * 1024, G + i * 32 * NP, Hq,
                                    PIN[i], QQ[i], NR[i], SS[i], OFF[i],
                                    (i < 5) ? 1 : 0);
        float* t = Hp; Hp = Hq; Hq = t;
    }

    // skip GEMM: 256 x 192 x NP, relu epilogue
    {
        ALSkipW al = {skip_w};
        BLRowNP bl = {G};
        EPRelu4 ep = {skip};
        dim3 gg(NP / 128, 2);
        gemm128_kernel<<<gg, 256>>>(12, al, bl, ep);
    }
    // end1: 128 x 256 x NP, bias+relu
    {
        ALRow al = {end1_w, 256};
        BLRowNP bl = {skip};
        EPBiasRelu4 ep = {end1_b, y1};
        dim3 gg(NP / 128, 1);
        gemm128_kernel<<<gg, 256>>>(16, al, bl, ep);
    }
    // pool1: [128][1272][256] -> [128][635][256]
    {
        int total = 128 * 635 * 256;
        pool_kernel<<<(total + 255) / 256, 256>>>(y1, p1, 1272, 635, total);
    }
    // end2: 32 x 128 x 162560
    {
        ALRowG al = {end2_w, 128, 32};
        BLRow bl = {p1, 635 * 256};
        EPBiasReluG ep = {end2_b, y2, 635 * 256, 32};
        dim3 gg(635 * 256 / 64, 1, 1);
        gemm64_kernel<<<gg, 256>>>(4, 4, al, bl, ep);
    }
    // pool2: [32][635][256] -> [32][317][256]
    {
        int total = 32 * 317 * 256;
        pool_kernel<<<(total + 255) / 256, 256>>>(y2, p2, 635, 317, total);
    }
    // fc1: 1024 x 10144 x 256, split-K=8
    {
        ALRowG al = {fc_w1, 10144, 1024};
        BLRow bl = {p2, 256};
        EPPart ep = {f1p, 1024 * 256};
        dim3 gg(4, 16, 8);
        gemm64_kernel<<<gg, 256>>>(317, 40, al, bl, ep);
        int total = 1024 * 256;
        reduce_kernel<<<(total + 255) / 256, 256>>>(f1p, fc_b1, f1, 8, total, total);
    }
    // fc2: 256 x 1024 x 256, split-K=4
    {
        ALRowG al = {fc_w2, 1024, 256};
        BLRow bl = {f1, 256};
        EPPart ep = {f2p, 256 * 256};
        dim3 gg(4, 4, 4);
        gemm64_kernel<<<gg, 256>>>(32, 8, al, bl, ep);
        int total = 256 * 256;
        reduce_kernel<<<(total + 255) / 256, 256>>>(f2p, fc_b2, f2, 4, total, total);
    }
    // fc3 + softmax + argmax
    fc3_softmax_kernel<<<1, 256>>>(f2, fc_w3, fc_b3, (float*)d_out);
}

// round 7
// speedup vs baseline: 3.6179x; 1.3070x over previous
#include <cuda_runtime.h>
#include <cuda_bf16.h>
#include <math.h>
#include <stdint.h>

#define NP 325632   // 1272 * 256 : columns of the big GEMMs, p = t*256 + b

// ---------------- scratch (device globals; no allocation) ----------------
__device__ float g_r1[10485760];     // stream ping [32][<=327680]
__device__ float g_r2[10485760];     // stream pong
__device__ float g_G[62521344];      // bf16 planes: GtH [NP][192], GtL [NP][192]
__device__ float g_skip[83361792];   // bf16 planes: SktH [NP][256], SktL [NP][256]
__device__ float g_y1[41680896];     // 128 x NP (also reused as xT early)
__device__ float g_p1[20801536];     // 128 x 635 x 256
__device__ float g_y2[5201920];      // 32 x 635 x 256
__device__ float g_p2[2596864];      // 32 x 317 x 256
__device__ float g_f1p[2097152];     // fc1 split-K partials 8 x 1024 x 256
__device__ float g_f1[262144];       // 1024 x 256
__device__ float g_f2p[262144];      // fc2 partials 4 x 256 x 256
__device__ float g_f2[65536];        // 256 x 256
__device__ __nv_bfloat16 g_wtc[163840]; // wskH[49152] wskL[49152] we1H[32768] we1L[32768]

// ================= mma.sync helpers (sm_80+ portable; no tcgen05) =================
__device__ __forceinline__ uint32_t s2u(const void* p) {
    uint32_t a;
    asm("{ .reg .u64 t; cvta.to.shared.u64 t, %1; cvt.u32.u64 %0, t; }" : "=r"(a) : "l"(p));
    return a;
}
__device__ __forceinline__ void ldm_x4(uint32_t* r, uint32_t addr) {
    asm volatile("ldmatrix.sync.aligned.m8n8.x4.shared.b16 {%0,%1,%2,%3}, [%4];"
                 : "=r"(r[0]), "=r"(r[1]), "=r"(r[2]), "=r"(r[3]) : "r"(addr));
}
__device__ __forceinline__ void ldm_x2(uint32_t* r, uint32_t addr) {
    asm volatile("ldmatrix.sync.aligned.m8n8.x2.shared.b16 {%0,%1}, [%2];"
                 : "=r"(r[0]), "=r"(r[1]) : "r"(addr));
}
__device__ __forceinline__ void mma16816(float* c, const uint32_t* a, const uint32_t* b) {
    asm volatile(
        "mma.sync.aligned.m16n8k16.row.col.f32.bf16.bf16.f32 "
        "{%0,%1,%2,%3}, {%4,%5,%6,%7}, {%8,%9}, {%0,%1,%2,%3};"
        : "+f"(c[0]), "+f"(c[1]), "+f"(c[2]), "+f"(c[3])
        : "r"(a[0]), "r"(a[1]), "r"(a[2]), "r"(a[3]), "r"(b[0]), "r"(b[1]));
}
__device__ __forceinline__ uint32_t pk16(__nv_bfloat16 a, __nv_bfloat16 b) {
    __nv_bfloat162 t;
    t.x = a; t.y = b;
    return *reinterpret_cast<uint32_t*>(&t);
}

// ---------------- x (b,5,t) -> xT[i][p = t*256 + b] ----------------
__global__ void xpose_kernel(const float* __restrict__ x, float* __restrict__ xT)
{
    __shared__ float S[32][33];
    int i  = blockIdx.z;
    int t0 = blockIdx.x << 5;
    int b0 = blockIdx.y << 5;
    int col = threadIdx.x & 31;
    int r0  = threadIdx.x >> 5;
#pragma unroll
    for (int l = 0; l < 4; l++) {
        int bb = r0 + (l << 3);
        S[bb][col] = x[(b0 + bb) * 6400 + i * 1280 + t0 + col];
    }
    __syncthreads();
#pragma unroll
    for (int l = 0; l < 4; l++) {
        int tt = r0 + (l << 3);
        xT[i * 327680 + (t0 + tt) * 256 + b0 + col] = S[col][tt];
    }
}

// ---------------- start conv in flat layout ----------------
__global__ void startflat_kernel(const float* __restrict__ xT, const float* __restrict__ w,
                                 float* __restrict__ X0)
{
    int p = blockIdx.x * 256 + threadIdx.x;
    int c = blockIdx.y;
    float acc = 0.f;
#pragma unroll
    for (int i = 0; i < 5; i++) acc += __ldg(&w[c * 5 + i]) * xT[i * 327680 + p];
    X0[c * 327680 + p] = acc;
}

// ---------------- weight prep: bf16 hi/lo K-major ----------------
__global__ void prepw_kernel(const float* __restrict__ sw, const float* __restrict__ e1,
                             __nv_bfloat16* __restrict__ wt)
{
    int idx = blockIdx.x * 256 + threadIdx.x;
    if (idx < 49152) {
        int m = idx / 192, k = idx - m * 192;
        float v = sw[(k >> 5) * 8192 + m * 32 + (k & 31)];
        __nv_bfloat16 h = __float2bfloat16(v);
        wt[idx] = h;
        wt[49152 + idx] = __float2bfloat16(v - __bfloat162float(h));
    } else if (idx < 81920) {
        int i2 = idx - 49152;
        float v = e1[i2];
        __nv_bfloat16 h = __float2bfloat16(v);
        wt[98304 + i2] = h;
        wt[131072 + i2] = __float2bfloat16(v - __bfloat162float(h));
    }
}

// ---------------- fused flat-stream layer ----------------
__device__ __forceinline__ float fast_gate(float f, float g)
{
    float ef = __expf(f + f);
    float th = 1.f - __fdividef(2.f, ef + 1.f);
    float sg = __fdividef(1.f, 1.f + __expf(-g));
    return th * sg;
}

__global__ void __launch_bounds__(128, 4) layer_kernel(
    const float* __restrict__ X,
    const float* __restrict__ Wf, const float* __restrict__ Wg, const float* __restrict__ Wr,
    __nv_bfloat16* __restrict__ gtH, __nv_bfloat16* __restrict__ gtL,
    float* __restrict__ Rout,
    int Pin, int Q, int nr, int s, int off, int lay64, int writeRes)
{
    __shared__ float4 ws4[1024];        // {f0,f1,g0,g1}; reused for wr in stage2
    __shared__ float  XaH[32][128];     // Xa tile, then H
    __shared__ float  Xb[32][128];

    int tid = threadIdx.x;
    int q0 = blockIdx.x << 7;

    for (int i = tid; i < 1024; i += 128) {
        int k = i >> 5, c = i & 31;
        int base = (c * 32 + k) * 2;
        ws4[i] = make_float4(Wf[base], Wf[base + 1], Wg[base], Wg[base + 1]);
    }
    int qa = q0 - s + tid;
#pragma unroll 4
    for (int r = 0; r < 32; r++) {
        const float* Xr = X + r * Pin;
        XaH[r][tid] = (qa >= 0) ? Xr[qa] : 0.f;
        Xb[r][tid]  = Xr[qa + nr];
    }
    __syncthreads();

    int tx = tid & 15, ty = tid >> 4;
    int cbase = ty << 2;
    int pcol = tx << 3;

    float aF[4][8], aG[4][8];
#pragma unroll
    for (int cc = 0; cc < 4; cc++)
#pragma unroll
        for (int j = 0; j < 8; j++) { aF[cc][j] = 0.f; aG[cc][j] = 0.f; }

#pragma unroll 2
    for (int k = 0; k < 32; k++) {
        float xav[8], xbv[8];
        *(float4*)&xav[0] = *(const float4*)&XaH[k][pcol];
        *(float4*)&xav[4] = *(const float4*)&XaH[k][pcol + 4];
        *(float4*)&xbv[0] = *(const float4*)&Xb[k][pcol];
        *(float4*)&xbv[4] = *(const float4*)&Xb[k][pcol + 4];
#pragma unroll
        for (int cc = 0; cc < 4; cc++) {
            float4 w = ws4[(k << 5) + cbase + cc];
#pragma unroll
            for (int j = 0; j < 8; j++) {
                aF[cc][j] += w.x * xav[j];
                aF[cc][j] += w.y * xbv[j];
                aG[cc][j] += w.z * xav[j];
                aG[cc][j] += w.w * xbv[j];
            }
        }
    }

    float hv[4][8];
#pragma unroll
    for (int cc = 0; cc < 4; cc++)
#pragma unroll
        for (int j = 0; j < 8; j++) hv[cc][j] = fast_gate(aF[cc][j], aG[cc][j]);

    __syncthreads();       // stage-1 reads of XaH / ws4 done
    // stage H into XaH
#pragma unroll
    for (int cc = 0; cc < 4; cc++) {
        int c = cbase + cc;
        *(float4*)&XaH[c][pcol]     = make_float4(hv[cc][0], hv[cc][1], hv[cc][2], hv[cc][3]);
        *(float4*)&XaH[c][pcol + 4] = make_float4(hv[cc][4], hv[cc][5], hv[cc][6], hv[cc][7]);
    }
    float* wrs = (float*)ws4;
    if (writeRes) {
        for (int i = tid; i < 1024; i += 128) {
            int k = i >> 5, c = i & 31;
            wrs[i] = Wr[c * 32 + k];
        }
    }
    __syncthreads();

    // ---- write G rows (K-major bf16 hi/lo): Gt[pg][lay*32 + c] ----
    {
        int pg = q0 + tid - off;
        if (pg >= 0) {
            uint32_t hw[16], lw[16];
#pragma unroll
            for (int j = 0; j < 16; j++) {
                float v0 = XaH[2 * j][tid];
                float v1 = XaH[2 * j + 1][tid];
                __nv_bfloat16 h0 = __float2bfloat16(v0);
                __nv_bfloat16 h1 = __float2bfloat16(v1);
                hw[j] = pk16(h0, h1);
                lw[j] = pk16(__float2bfloat16(v0 - __bfloat162float(h0)),
                             __float2bfloat16(v1 - __bfloat162float(h1)));
            }
            char* dh = (char*)gtH + (long)pg * 384 + lay64;
            char* dl = (char*)gtL + (long)pg * 384 + lay64;
#pragma unroll
            for (int q4 = 0; q4 < 4; q4++) {
                *(float4*)(dh + (q4 << 4)) = ((float4*)hw)[q4];
                *(float4*)(dl + (q4 << 4)) = ((float4*)lw)[q4];
            }
        }
    }

    if (writeRes) {
        float aR[4][8];
#pragma unroll
        for (int cc = 0; cc < 4; cc++)
#pragma unroll
            for (int j = 0; j < 8; j++) aR[cc][j] = 0.f;

#pragma unroll 2
        for (int k = 0; k < 32; k++) {
            float h8[8];
            *(float4*)&h8[0] = *(const float4*)&XaH[k][pcol];
            *(float4*)&h8[4] = *(const float4*)&XaH[k][pcol + 4];
#pragma unroll
            for (int cc = 0; cc < 4; cc++) {
                float w = wrs[(k << 5) + cbase + cc];
#pragma unroll
                for (int j = 0; j < 8; j++) aR[cc][j] += w * h8[j];
            }
        }
#pragma unroll
        for (int cc = 0; cc < 4; cc++) {
            int c = cbase + cc;
#pragma unroll
            for (int j2 = 0; j2 < 2; j2++) {
                float4 xb = *(const float4*)&Xb[c][pcol + (j2 << 2)];
                float4 v = make_float4(aR[cc][j2 * 4] + xb.x, aR[cc][j2 * 4 + 1] + xb.y,
                                       aR[cc][j2 * 4 + 2] + xb.z, aR[cc][j2 * 4 + 3] + xb.w);
                *(float4*)&Rout[c * Q + q0 + pcol + (j2 << 2)] = v;
            }
        }
    }
}

// ---------------- warp-MMA split-bf16 GEMM ----------------
// D[p][m] = sum_k B(p,k) * W(m,k). B/W as (hi,lo) bf16 planes, K-major rows.
// MODE 0: skip (K=192, Mtot=256) -> relu -> bf16 hi/lo out rows [p][256].
// MODE 1: end1 (K=256, Mtot=128) -> +bias, relu -> fp32 out [m][NP].
// Block: 256 thr = 8 warps (2p x 4m), block tile 128p x 128m, warp tile 64p x 32m.
template <int MODE>
__global__ void __launch_bounds__(256, 1) mma_gemm(
    const __nv_bfloat16* __restrict__ BH, const __nv_bfloat16* __restrict__ BLo,
    const __nv_bfloat16* __restrict__ WHp, const __nv_bfloat16* __restrict__ WLp,
    const float* __restrict__ bias,
    __nv_bfloat16* __restrict__ outH, __nv_bfloat16* __restrict__ outL,
    float* __restrict__ outF)
{
    constexpr int KTOT = MODE ? 256 : 192;
    constexpr int NCH  = KTOT / 32;
    constexpr int PLSTR = 128 * 40 * 2;   // smem plane stride bytes

    __shared__ __align__(16) __nv_bfloat16 sB[2][128][40];
    __shared__ __align__(16) __nv_bfloat16 sW[2][128][40];

    int tid = threadIdx.x;
    int warp = tid >> 5, lane = tid & 31;
    int p0 = blockIdx.x << 7;
    int m0 = blockIdx.y << 7;
    int warp_p = (warp & 1) << 6;
    int warp_m = (warp >> 1) << 5;

    uint32_t baseB = s2u(&sB[0][0][0]);
    uint32_t baseW = s2u(&sW[0][0][0]);

    const __nv_bfloat16* gB[2] = {BH + (long)p0 * KTOT, BLo + (long)p0 * KTOT};
    const __nv_bfloat16* gW[2] = {WHp + (long)m0 * KTOT, WLp + (long)m0 * KTOT};

    float acc[4][4][4];
#pragma unroll
    for (int pt = 0; pt < 4; pt++)
#pragma unroll
        for (int nt = 0; nt < 4; nt++)
#pragma unroll
            for (int j = 0; j < 4; j++) acc[pt][nt][j] = 0.f;

    int arow = lane & 15;
    int acol = (lane >> 4) << 3;
    int brow = lane & 7;
    int bcol = ((lane >> 3) & 1) << 3;

    for (int kc = 0; kc < NCH; kc++) {
        if (kc) __syncthreads();
        int ksrc = kc << 5;
#pragma unroll
        for (int i = 0; i < 4; i++) {
            int idx = tid + (i << 8);
            int plane = idx >> 9;
            int r = (idx >> 2) & 127;
            int q = (idx & 3) << 3;
            *(float4*)&sB[plane][r][q] = *(const float4*)(gB[plane] + (long)r * KTOT + ksrc + q);
            *(float4*)&sW[plane][r][q] = *(const float4*)(gW[plane] + (long)r * KTOT + ksrc + q);
        }
        __syncthreads();

#pragma unroll
        for (int ks = 0; ks < 2; ks++) {
            uint32_t aH[4][4], aL[4][4], bH[4][2], bL[4][2];
#pragma unroll
            for (int pt = 0; pt < 4; pt++) {
                uint32_t offs = (uint32_t)(((warp_p + (pt << 4) + arow) * 40 + (ks << 4) + acol) << 1);
                ldm_x4(aH[pt], baseB + offs);
                ldm_x4(aL[pt], baseB + PLSTR + offs);
            }
#pragma unroll
            for (int nt = 0; nt < 4; nt++) {
                uint32_t offs = (uint32_t)(((warp_m + (nt << 3) + brow) * 40 + (ks << 4) + bcol) << 1);
                ldm_x2(bH[nt], baseW + offs);
                ldm_x2(bL[nt], baseW + PLSTR + offs);
            }
#pragma unroll
            for (int pt = 0; pt < 4; pt++)
#pragma unroll
                for (int nt = 0; nt < 4; nt++) {
                    mma16816(acc[pt][nt], aH[pt], bH[nt]);
                    mma16816(acc[pt][nt], aL[pt], bH[nt]);
                    mma16816(acc[pt][nt], aH[pt], bL[nt]);
                }
        }
    }

    // ---- epilogue ----
    int prow = lane >> 2;
    int mcol = (lane & 3) << 1;
#pragma unroll
    for (int pt = 0; pt < 4; pt++) {
#pragma unroll
        for (int half = 0; half < 2; half++) {
            int p = p0 + warp_p + (pt << 4) + prow + (half << 3);
#pragma unroll
            for (int nt = 0; nt < 4; nt++) {
                float v0 = acc[pt][nt][half * 2];
                float v1 = acc[pt][nt][half * 2 + 1];
                int m = m0 + warp_m + (nt << 3) + mcol;
                if (MODE == 0) {
                    v0 = fmaxf(v0, 0.f);
                    v1 = fmaxf(v1, 0.f);
                    __nv_bfloat16 h0 = __float2bfloat16(v0);
                    __nv_bfloat16 h1 = __float2bfloat16(v1);
                    *(uint32_t*)((char*)outH + (long)p * 512 + m * 2) = pk16(h0, h1);
                    *(uint32_t*)((char*)outL + (long)p * 512 + m * 2) =
                        pk16(__float2bfloat16(v0 - __bfloat162float(h0)),
                             __float2bfloat16(v1 - __bfloat162float(h1)));
                } else {
                    outF[(long)m * NP + p] = fmaxf(v0 + __ldg(&bias[m]), 0.f);
                    outF[(long)(m + 1) * NP + p] = fmaxf(v1 + __ldg(&bias[m + 1]), 0.f);
                }
            }
        }
    }
}

// ---------------- 64x64 GEMM with split-K ----------------
template <class AL, class BL, class EP>
__global__ void __launch_bounds__(256) gemm64_kernel(int totKB, int splitKB, AL al, BL bl, EP ep)
{
    __shared__ float As[32][68];
    __shared__ float Bs[32][68];
    int mBase = blockIdx.y << 6;
    int pBase = blockIdx.x << 6;
    int kb0 = blockIdx.z * splitKB;
    int kb1 = kb0 + splitKB; if (kb1 > totKB) kb1 = totKB;
    int tid = threadIdx.x;
    int tx = tid & 15, ty = tid >> 4;
    float acc[4][4];
#pragma unroll
    for (int i = 0; i < 4; i++)
#pragma unroll
        for (int j = 0; j < 4; j++) acc[i][j] = 0.f;

    for (int kb = kb0; kb < kb1; kb++) {
        int k0 = kb << 5;
#pragma unroll
        for (int i = 0; i < 8; i++) {
            int idx = tid + (i << 8);
            int m = idx >> 5, k = idx & 31;
            As[k][m] = al(mBase + m, k0 + k);
        }
#pragma unroll
        for (int i = 0; i < 8; i++) {
            int idx = tid + (i << 8);
            int k = idx >> 6, p = idx & 63;
            Bs[k][p] = bl(k0 + k, pBase + p);
        }
        __syncthreads();
#pragma unroll
        for (int k = 0; k < 32; k++) {
            float4 a4 = *(const float4*)&As[k][ty << 2];
            float4 b4 = *(const float4*)&Bs[k][tx << 2];
            float a[4] = {a4.x, a4.y, a4.z, a4.w};
            float bb[4] = {b4.x, b4.y, b4.z, b4.w};
#pragma unroll
            for (int i = 0; i < 4; i++)
#pragma unroll
                for (int j = 0; j < 4; j++) acc[i][j] += a[i] * bb[j];
        }
        __syncthreads();
    }
#pragma unroll
    for (int i = 0; i < 4; i++) {
        int m = mBase + (ty << 2) + i;
#pragma unroll
        for (int j = 0; j < 4; j++) {
            int p = pBase + (tx << 2) + j;
            ep.store(m, p, acc[i][j]);
        }
    }
}

struct ALRowG {
    const float* A; int K, M;
    __device__ float operator()(int m, int k) const {
        return (m < M) ? A[m * K + k] : 0.f;
    }
};
struct BLRow {
    const float* B; int N;
    __device__ float operator()(int k, int p) const { return B[k * N + p]; }
};
struct EPBiasReluG {
    const float* bias; float* out; int N, M;
    __device__ void store(int m, int p, float v) const {
        if (m < M) out[m * N + p] = fmaxf(v + bias[m], 0.f);
    }
};
struct EPPart {
    float* out; int Mstride;
    __device__ void store(int m, int p, float v) const {
        out[blockIdx.z * Mstride + m * 256 + p] = v;
    }
};

// ---------------- maxpool k=3 s=2 over middle dim, layout [m][t][256b] ----------------
__global__ void pool_kernel(const float* __restrict__ in, float* __restrict__ out,
                            int Lin, int Lout, int total)
{
    int idx = blockIdx.x * 256 + threadIdx.x;
    if (idx >= total) return;
    int b = idx & 255;
    int q = idx >> 8;
    int tp = q % Lout;
    int m = q / Lout;
    const float* p = in + (m * Lin + 2 * tp) * 256 + b;
    out[idx] = fmaxf(fmaxf(p[0], p[256]), p[512]);
}

// ---------------- split-K reduce + bias + relu ----------------
__global__ void reduce_kernel(const float* __restrict__ part, const float* __restrict__ bias,
                              float* __restrict__ out, int S, int Mstride, int total)
{
    int idx = blockIdx.x * 256 + threadIdx.x;
    if (idx >= total) return;
    int m = idx >> 8;
    float s = 0.f;
    for (int z = 0; z < S; z++) s += part[z * Mstride + idx];
    out[idx] = fmaxf(s + bias[m], 0.f);
}

// ---------------- fc3 + softmax + argmax ----------------
__global__ void fc3_softmax_kernel(const float* __restrict__ F2, const float* __restrict__ W3,
                                   const float* __restrict__ B3, float* __restrict__ out)
{
    int b = threadIdx.x;
    float l0 = B3[0], l1 = B3[1];
    for (int k = 0; k < 256; k++) {
        float v = F2[k * 256 + b];
        l0 += W3[k] * v;
        l1 += W3[256 + k] * v;
    }
    out[2 * b] = l0;
    out[2 * b + 1] = l1;
    float mx = fmaxf(l0, l1);
    float e0 = __expf(l0 - mx), e1 = __expf(l1 - mx);
    float inv = 1.f / (e0 + e1);
    out[512 + 2 * b] = e0 * inv;
    out[512 + 2 * b + 1] = e1 * inv;
    out[1024 + b] = (l1 > l0) ? 1.f : 0.f;
}

// ---------------- host orchestration ----------------
extern "C" void kernel_launch(void* const* d_in, const int* in_sizes, int n_in,
                              void* d_out, int out_size)
{
    const float* x        = (const float*)d_in[0];
    const float* start_w  = (const float*)d_in[1];
    const float* filter_w = (const float*)d_in[2];
    const float* gate_w   = (const float*)d_in[3];
    const float* res_w    = (const float*)d_in[4];
    const float* skip_w   = (const float*)d_in[5];
    const float* end1_w   = (const float*)d_in[6];
    const float* end1_b   = (const float*)d_in[7];
    const float* end2_w   = (const float*)d_in[8];
    const float* end2_b   = (const float*)d_in[9];
    const float* fc_w1    = (const float*)d_in[10];
    const float* fc_b1    = (const float*)d_in[11];
    const float* fc_w2    = (const float*)d_in[12];
    const float* fc_b2    = (const float*)d_in[13];
    const float* fc_w3    = (const float*)d_in[14];
    const float* fc_b3    = (const float*)d_in[15];

    float *r1, *r2, *G, *skip, *y1, *p1, *y2, *p2, *f1p, *f1, *f2p, *f2;
    __nv_bfloat16* wtc;
    cudaGetSymbolAddress((void**)&r1, g_r1);
    cudaGetSymbolAddress((void**)&r2, g_r2);
    cudaGetSymbolAddress((void**)&G, g_G);
    cudaGetSymbolAddress((void**)&skip, g_skip);
    cudaGetSymbolAddress((void**)&y1, g_y1);
    cudaGetSymbolAddress((void**)&p1, g_p1);
    cudaGetSymbolAddress((void**)&y2, g_y2);
    cudaGetSymbolAddress((void**)&p2, g_p2);
    cudaGetSymbolAddress((void**)&f1p, g_f1p);
    cudaGetSymbolAddress((void**)&f1, g_f1);
    cudaGetSymbolAddress((void**)&f2p, g_f2p);
    cudaGetSymbolAddress((void**)&f2, g_f2);
    cudaGetSymbolAddress((void**)&wtc, g_wtc);

    __nv_bfloat16* gtH = (__nv_bfloat16*)G;
    __nv_bfloat16* gtL = gtH + (long)NP * 192;
    __nv_bfloat16* sktH = (__nv_bfloat16*)skip;
    __nv_bfloat16* sktL = sktH + (long)NP * 256;
    __nv_bfloat16* wskH = wtc;
    __nv_bfloat16* wskL = wtc + 49152;
    __nv_bfloat16* we1H = wtc + 98304;
    __nv_bfloat16* we1L = wtc + 131072;

    // x -> xT (flat, use y1 as scratch) -> start conv -> r1
    {
        dim3 gx(40, 8, 5);
        xpose_kernel<<<gx, 256>>>(x, y1);
        dim3 gs(1280, 32);
        startflat_kernel<<<gs, 256>>>(y1, start_w, r1);
    }
    prepw_kernel<<<320, 256>>>(skip_w, end1_w, wtc);

    // flat-stream layer constants
    const int PIN[6] = {327680, 327424, 327168, 326656, 326400, 326144};
    const int QQ[6]  = {327424, 327168, 326656, 326400, 326144, 325632};
    const int NR[6]  = {256, 512, 1024, 256, 512, 1024};
    const int SS[6]  = {0, 256, 512, 0, 256, 512};
    const int OFF[6] = {1792, 1536, 1024, 768, 512, 0};

    float* Hp = r1;
    float* Hq = r2;
    for (int i = 0; i < 6; i++) {
        int nblk = QQ[i] >> 7;
        layer_kernel<<<nblk, 128>>>(Hp, filter_w + i * 2048, gate_w + i * 2048,
                                    res_w + i * 1024, gtH, gtL, Hq,
                                    PIN[i], QQ[i], NR[i], SS[i], OFF[i], i * 64,
                                    (i < 5) ? 1 : 0);
        float* t = Hp; Hp = Hq; Hq = t;
    }

    // skip GEMM (tensor pipe via mma.sync): 256 x 192 x NP, relu -> Skt hi/lo
    mma_gemm<0><<<dim3(NP / 128, 2), 256>>>(gtH, gtL, wskH, wskL, nullptr, sktH, sktL, nullptr);
    // end1 GEMM: 128 x 256 x NP, bias+relu -> y1 fp32
    mma_gemm<1><<<dim3(NP / 128, 1), 256>>>(sktH, sktL, we1H, we1L, end1_b, nullptr, nullptr, y1);

    // pool1: [128][1272][256] -> [128][635][256]
    {
        int total = 128 * 635 * 256;
        pool_kernel<<<(total + 255) / 256, 256>>>(y1, p1, 1272, 635, total);
    }
    // end2: 32 x 128 x 162560
    {
        ALRowG al = {end2_w, 128, 32};
        BLRow bl = {p1, 635 * 256};
        EPBiasReluG ep = {end2_b, y2, 635 * 256, 32};
        dim3 gg(635 * 256 / 64, 1, 1);
        gemm64_kernel<<<gg, 256>>>(4, 4, al, bl, ep);
    }
    // pool2: [32][635][256] -> [32][317][256]
    {
        int total = 32 * 317 * 256;
        pool_kernel<<<(total + 255) / 256, 256>>>(y2, p2, 635, 317, total);
    }
    // fc1: 1024 x 10144 x 256, split-K=8
    {
        ALRowG al = {fc_w1, 10144, 1024};
        BLRow bl = {p2, 256};
        EPPart ep = {f1p, 1024 * 256};
        dim3 gg(4, 16, 8);
        gemm64_kernel<<<gg, 256>>>(317, 40, al, bl, ep);
        int total = 1024 * 256;
        reduce_kernel<<<(total + 255) / 256, 256>>>(f1p, fc_b1, f1, 8, total, total);
    }
    // fc2: 256 x 1024 x 256, split-K=4
    {
        ALRowG al = {fc_w2, 1024, 256};
        BLRow bl = {f1, 256};
        EPPart ep = {f2p, 256 * 256};
        dim3 gg(4, 4, 4);
        gemm64_kernel<<<gg, 256>>>(32, 8, al, bl, ep);
        int total = 256 * 256;
        reduce_kernel<<<(total + 255) / 256, 256>>>(f2p, fc_b2, f2, 4, total, total);
    }
    // fc3 + softmax + argmax
    fc3_softmax_kernel<<<1, 256>>>(f2, fc_w3, fc_b3, (float*)d_out);
}

// round 8
// speedup vs baseline: 4.9634x; 1.3719x over previous
#include <cuda_runtime.h>
#include <cuda_bf16.h>
#include <math.h>
#include <stdint.h>

#define NP 325632   // 1272 * 256 : columns of the big GEMMs, p = t*256 + b

// ---------------- scratch (device globals; no allocation) ----------------
__device__ float g_r1[10485760];     // stream ping: bf16 planes XH/XL [q][32]
__device__ float g_r2[10485760];     // stream pong
__device__ float g_G[62521344];      // bf16 planes: GtH [NP][192], GtL [NP][192]
__device__ float g_skip[83361792];   // bf16 planes: SktH [NP][256], SktL [NP][256]
__device__ float g_y1[41680896];     // 128 x NP (also reused as xT early)
__device__ float g_p1[20801536];     // 128 x 635 x 256
__device__ float g_y2[5201920];      // 32 x 635 x 256
__device__ float g_p2[2596864];      // 32 x 317 x 256
__device__ float g_f1p[2097152];     // fc1 split-K partials 8 x 1024 x 256
__device__ float g_f1[262144];       // 1024 x 256
__device__ float g_f2p[262144];      // fc2 partials 4 x 256 x 256
__device__ float g_f2[65536];        // 256 x 256
__device__ __nv_bfloat16 g_wtc[163840]; // wskH[49152] wskL[49152] we1H[32768] we1L[32768]
__device__ __nv_bfloat16 g_wlay[61440]; // per-layer: WfgH[4096] WfgL[4096] WrH[1024] WrL[1024]

// ================= mma.sync helpers (sm_80+ portable) =================
__device__ __forceinline__ uint32_t s2u(const void* p) {
    uint32_t a;
    asm("{ .reg .u64 t; cvta.to.shared.u64 t, %1; cvt.u32.u64 %0, t; }" : "=r"(a) : "l"(p));
    return a;
}
__device__ __forceinline__ void ldm_x4(uint32_t* r, uint32_t addr) {
    asm volatile("ldmatrix.sync.aligned.m8n8.x4.shared.b16 {%0,%1,%2,%3}, [%4];"
                 : "=r"(r[0]), "=r"(r[1]), "=r"(r[2]), "=r"(r[3]) : "r"(addr));
}
__device__ __forceinline__ void ldm_x2(uint32_t* r, uint32_t addr) {
    asm volatile("ldmatrix.sync.aligned.m8n8.x2.shared.b16 {%0,%1}, [%2];"
                 : "=r"(r[0]), "=r"(r[1]) : "r"(addr));
}
__device__ __forceinline__ void mma16816(float* c, const uint32_t* a, const uint32_t* b) {
    asm volatile(
        "mma.sync.aligned.m16n8k16.row.col.f32.bf16.bf16.f32 "
        "{%0,%1,%2,%3}, {%4,%5,%6,%7}, {%8,%9}, {%0,%1,%2,%3};"
        : "+f"(c[0]), "+f"(c[1]), "+f"(c[2]), "+f"(c[3])
        : "r"(a[0]), "r"(a[1]), "r"(a[2]), "r"(a[3]), "r"(b[0]), "r"(b[1]));
}
__device__ __forceinline__ uint32_t pk16(__nv_bfloat16 a, __nv_bfloat16 b) {
    __nv_bfloat162 t;
    t.x = a; t.y = b;
    return *reinterpret_cast<uint32_t*>(&t);
}

// ---------------- x (b,5,t) -> xT[i][p = t*256 + b] ----------------
__global__ void xpose_kernel(const float* __restrict__ x, float* __restrict__ xT)
{
    __shared__ float S[32][33];
    int i  = blockIdx.z;
    int t0 = blockIdx.x << 5;
    int b0 = blockIdx.y << 5;
    int col = threadIdx.x & 31;
    int r0  = threadIdx.x >> 5;
#pragma unroll
    for (int l = 0; l < 4; l++) {
        int bb = r0 + (l << 3);
        S[bb][col] = x[(b0 + bb) * 6400 + i * 1280 + t0 + col];
    }
    __syncthreads();
#pragma unroll
    for (int l = 0; l < 4; l++) {
        int tt = r0 + (l << 3);
        xT[i * 327680 + (t0 + tt) * 256 + b0 + col] = S[col][tt];
    }
}

// ---------------- start conv -> stream planes [q][32] bf16 hi/lo ----------------
__global__ void startflat_kernel(const float* __restrict__ xT, const float* __restrict__ w,
                                 __nv_bfloat16* __restrict__ XH, __nv_bfloat16* __restrict__ XL)
{
    int idx = blockIdx.x * 256 + threadIdx.x;   // 327680*32
    int q = idx >> 5, c = idx & 31;
    float acc = 0.f;
#pragma unroll
    for (int i = 0; i < 5; i++) acc += __ldg(&w[c * 5 + i]) * xT[i * 327680 + q];
    __nv_bfloat16 h = __float2bfloat16(acc);
    XH[idx] = h;
    XL[idx] = __float2bfloat16(acc - __bfloat162float(h));
}

// ---------------- weight prep for skip/end1 (unchanged) ----------------
__global__ void prepw_kernel(const float* __restrict__ sw, const float* __restrict__ e1,
                             __nv_bfloat16* __restrict__ wt)
{
    int idx = blockIdx.x * 256 + threadIdx.x;
    if (idx < 49152) {
        int m = idx / 192, k = idx - m * 192;
        float v = sw[(k >> 5) * 8192 + m * 32 + (k & 31)];
        __nv_bfloat16 h = __float2bfloat16(v);
        wt[idx] = h;
        wt[49152 + idx] = __float2bfloat16(v - __bfloat162float(h));
    } else if (idx < 81920) {
        int i2 = idx - 49152;
        float v = e1[i2];
        __nv_bfloat16 h = __float2bfloat16(v);
        wt[98304 + i2] = h;
        wt[131072 + i2] = __float2bfloat16(v - __bfloat162float(h));
    }
}

// ---------------- per-layer weight prep: Wfg [64m][64k] + Wr [32][32], hi/lo ---------
__global__ void prepl_kernel(const float* __restrict__ fw, const float* __restrict__ gw,
                             const float* __restrict__ rw, __nv_bfloat16* __restrict__ wl)
{
    int idx = blockIdx.x * 256 + threadIdx.x;
    if (idx < 24576) {
        int lay = idx >> 12;
        int r = idx & 4095;
        int m = r >> 6, k = r & 63;
        const float* src = ((m < 32) ? fw : gw) + lay * 2048 + (m & 31) * 64 + (k & 31) * 2 + (k >> 5);
        float v = *src;
        __nv_bfloat16 h = __float2bfloat16(v);
        wl[lay * 10240 + r] = h;
        wl[lay * 10240 + 4096 + r] = __float2bfloat16(v - __bfloat162float(h));
    } else if (idx < 30720) {
        int j = idx - 24576;
        int lay = j >> 10;
        int r = j & 1023;
        float v = rw[lay * 1024 + r];
        __nv_bfloat16 h = __float2bfloat16(v);
        wl[lay * 10240 + 8192 + r] = h;
        wl[lay * 10240 + 9216 + r] = __float2bfloat16(v - __bfloat162float(h));
    }
}

// ---------------- fused layer via mma.sync ----------------
__device__ __forceinline__ float fast_gate(float f, float g)
{
    float ef = __expf(f + f);
    float th = 1.f - __fdividef(2.f, ef + 1.f);
    float sg = __fdividef(1.f, 1.f + __expf(-g));
    return th * sg;
}

// smem layout (dynamic, bytes):
#define L_OFF_X  0        // 2 planes x 128 rows x 144B  (X tap-a | tap-b, bf16)
#define L_XPL    18432
#define L_OFF_W  36864    // 2 planes x 64 rows x 144B   (Wfg)
#define L_WPL    9216
#define L_OFF_WR 55296    // 2 planes x 32 rows x 80B    (Wr)
#define L_WRPL   2560
#define L_OFF_H  60416    // 2 planes x 128 rows x 80B   (h hi/lo)
#define L_HPL    10240
#define L_OFF_R  80896    // 2 planes x 128 rows x 80B   (res hi/lo)
#define L_RPL    10240
#define L_SMEM   101376

__global__ void __launch_bounds__(256, 1) layer_mma(
    const __nv_bfloat16* __restrict__ XH, const __nv_bfloat16* __restrict__ XL,
    const __nv_bfloat16* __restrict__ wlay,
    __nv_bfloat16* __restrict__ gtH, __nv_bfloat16* __restrict__ gtL,
    __nv_bfloat16* __restrict__ RoutH, __nv_bfloat16* __restrict__ RoutL,
    int nr, int s, int off, int lay64, int writeRes)
{
    extern __shared__ char sm[];
    uint32_t sb = s2u(sm);
    int tid = threadIdx.x;
    int q0 = blockIdx.x << 7;

    // ---- load X tiles: rows [q][tap-a 64B | tap-b 64B], 2 planes ----
#pragma unroll
    for (int l = 0; l < 8; l++) {
        int idx = tid + (l << 8);          // 2048 chunks of 16B
        int plane = idx >> 10;
        int r = (idx >> 3) & 127;
        int seg = idx & 7;
        int tap = seg >> 2;
        int qa = q0 + r - s + (tap ? nr : 0);
        char* dst = sm + L_OFF_X + plane * L_XPL + r * 144 + seg * 16;
        if (!tap && qa < 0) {
            *(float4*)dst = make_float4(0.f, 0.f, 0.f, 0.f);
        } else {
            const __nv_bfloat16* src = (plane ? XL : XH) + (long)qa * 32 + ((seg & 3) << 3);
            *(float4*)dst = *(const float4*)src;
        }
    }
    // ---- load Wfg: 64 rows x 128B, 2 planes ----
#pragma unroll
    for (int l = 0; l < 4; l++) {
        int idx = tid + (l << 8);          // 1024 chunks
        int plane = idx >> 9;
        int r = (idx >> 3) & 63;
        int cc = idx & 7;
        *(float4*)(sm + L_OFF_W + plane * L_WPL + r * 144 + cc * 16) =
            *(const float4*)(wlay + plane * 4096 + r * 64 + cc * 8);
    }
    // ---- load Wr: 32 rows x 64B, 2 planes ----
    if (tid < 256) {
        int idx = tid;                      // 256 chunks
        int plane = idx >> 7;
        int r = (idx >> 2) & 31;
        int cc = idx & 3;
        *(float4*)(sm + L_OFF_WR + plane * L_WRPL + r * 80 + cc * 16) =
            *(const float4*)(wlay + 8192 + plane * 1024 + r * 32 + cc * 8);
    }
    __syncthreads();

    int warp = tid >> 5, lane = tid & 31;
    int warp_q = (warp & 3) << 5;
    int g = warp >> 2;
    int arow = lane & 15, acol = (lane >> 4) << 3;
    int brow = lane & 7, bcol = ((lane >> 3) & 1) << 3;

    // ---- stage 1: gated conv, D[q][64], K=64, hi/lo 3-pass ----
    float acc[2][4][4];
#pragma unroll
    for (int pt = 0; pt < 2; pt++)
#pragma unroll
        for (int nt = 0; nt < 4; nt++)
#pragma unroll
            for (int j = 0; j < 4; j++) acc[pt][nt][j] = 0.f;

#pragma unroll
    for (int kc = 0; kc < 4; kc++) {
        uint32_t aH[2][4], aL[2][4], bH[4][2], bL[4][2];
#pragma unroll
        for (int pt = 0; pt < 2; pt++) {
            uint32_t o = L_OFF_X + (uint32_t)((warp_q + (pt << 4) + arow) * 144 + (((kc << 4) + acol) << 1));
            ldm_x4(aH[pt], sb + o);
            ldm_x4(aL[pt], sb + L_XPL + o);
        }
#pragma unroll
        for (int nt = 0; nt < 4; nt++) {
            int msm = (nt < 2) ? (g * 16 + nt * 8) : (32 + g * 16 + (nt - 2) * 8);
            uint32_t o = L_OFF_W + (uint32_t)((msm + brow) * 144 + (((kc << 4) + bcol) << 1));
            ldm_x2(bH[nt], sb + o);
            ldm_x2(bL[nt], sb + L_WPL + o);
        }
#pragma unroll
        for (int pt = 0; pt < 2; pt++)
#pragma unroll
            for (int nt = 0; nt < 4; nt++) {
                mma16816(acc[pt][nt], aH[pt], bH[nt]);
                mma16816(acc[pt][nt], aL[pt], bH[nt]);
                mma16816(acc[pt][nt], aH[pt], bL[nt]);
            }
    }

    // ---- activation (F at nt, G at nt+2; same q, same channel) -> sH hi/lo ----
#pragma unroll
    for (int pt = 0; pt < 2; pt++)
#pragma unroll
        for (int nt = 0; nt < 2; nt++)
#pragma unroll
            for (int jh = 0; jh < 2; jh++) {
                float F0 = acc[pt][nt][jh * 2], F1 = acc[pt][nt][jh * 2 + 1];
                float G0 = acc[pt][nt + 2][jh * 2], G1 = acc[pt][nt + 2][jh * 2 + 1];
                float h0 = fast_gate(F0, G0);
                float h1 = fast_gate(F1, G1);
                int q = warp_q + (pt << 4) + (lane >> 2) + (jh << 3);
                int c0 = g * 16 + nt * 8 + ((lane & 3) << 1);
                __nv_bfloat16 b0 = __float2bfloat16(h0);
                __nv_bfloat16 b1 = __float2bfloat16(h1);
                *(uint32_t*)(sm + L_OFF_H + q * 80 + c0 * 2) = pk16(b0, b1);
                *(uint32_t*)(sm + L_OFF_H + L_HPL + q * 80 + c0 * 2) =
                    pk16(__float2bfloat16(h0 - __bfloat162float(b0)),
                         __float2bfloat16(h1 - __bfloat162float(b1)));
            }
    __syncthreads();

    // ---- G-matrix row copy: gt[pg][lay*32..+31] hi/lo ----
#pragma unroll
    for (int l = 0; l < 4; l++) {
        int idx = tid + (l << 8);          // 1024 chunks
        int plane = idx >> 9;
        int r = (idx >> 2) & 127;
        int cc = idx & 3;
        int pg = q0 + r - off;
        if (pg >= 0) {
            float4 v = *(float4*)(sm + L_OFF_H + plane * L_HPL + r * 80 + cc * 16);
            char* d = (char*)(plane ? gtL : gtH) + (long)pg * 384 + lay64 + cc * 16;
            *(float4*)d = v;
        }
    }

    if (writeRes) {
        // ---- stage 2: res 1x1, D2[q][32], K=32, hi/lo 3-pass ----
        float acc2[2][2][4];
#pragma unroll
        for (int pt = 0; pt < 2; pt++)
#pragma unroll
            for (int nt = 0; nt < 2; nt++)
#pragma unroll
                for (int j = 0; j < 4; j++) acc2[pt][nt][j] = 0.f;

#pragma unroll
        for (int kc = 0; kc < 2; kc++) {
            uint32_t aH[2][4], aL[2][4], bH[2][2], bL[2][2];
#pragma unroll
            for (int pt = 0; pt < 2; pt++) {
                uint32_t o = L_OFF_H + (uint32_t)((warp_q + (pt << 4) + arow) * 80 + (((kc << 4) + acol) << 1));
                ldm_x4(aH[pt], sb + o);
                ldm_x4(aL[pt], sb + L_HPL + o);
            }
#pragma unroll
            for (int nt = 0; nt < 2; nt++) {
                uint32_t o = L_OFF_WR + (uint32_t)((g * 16 + nt * 8 + brow) * 80 + (((kc << 4) + bcol) << 1));
                ldm_x2(bH[nt], sb + o);
                ldm_x2(bL[nt], sb + L_WRPL + o);
            }
#pragma unroll
            for (int pt = 0; pt < 2; pt++)
#pragma unroll
                for (int nt = 0; nt < 2; nt++) {
                    mma16816(acc2[pt][nt], aH[pt], bH[nt]);
                    mma16816(acc2[pt][nt], aL[pt], bH[nt]);
                    mma16816(acc2[pt][nt], aH[pt], bL[nt]);
                }
        }

        // ---- add tap-b X (fp32 = hi+lo), split, stage to sRes ----
#pragma unroll
        for (int pt = 0; pt < 2; pt++)
#pragma unroll
            for (int nt = 0; nt < 2; nt++)
#pragma unroll
                for (int jh = 0; jh < 2; jh++) {
                    int q = warp_q + (pt << 4) + (lane >> 2) + (jh << 3);
                    int c0 = g * 16 + nt * 8 + ((lane & 3) << 1);
                    const __nv_bfloat16* xh = (const __nv_bfloat16*)(sm + L_OFF_X + q * 144 + (32 + c0) * 2);
                    const __nv_bfloat16* xl = (const __nv_bfloat16*)(sm + L_OFF_X + L_XPL + q * 144 + (32 + c0) * 2);
                    float xb0 = __bfloat162float(xh[0]) + __bfloat162float(xl[0]);
                    float xb1 = __bfloat162float(xh[1]) + __bfloat162float(xl[1]);
                    float v0 = acc2[pt][nt][jh * 2] + xb0;
                    float v1 = acc2[pt][nt][jh * 2 + 1] + xb1;
                    __nv_bfloat16 b0 = __float2bfloat16(v0);
                    __nv_bfloat16 b1 = __float2bfloat16(v1);
                    *(uint32_t*)(sm + L_OFF_R + q * 80 + c0 * 2) = pk16(b0, b1);
                    *(uint32_t*)(sm + L_OFF_R + L_RPL + q * 80 + c0 * 2) =
                        pk16(__float2bfloat16(v0 - __bfloat162float(b0)),
                             __float2bfloat16(v1 - __bfloat162float(b1)));
                }
        __syncthreads();

        // ---- copy sRes rows -> Rout planes [q][32] ----
#pragma unroll
        for (int l = 0; l < 4; l++) {
            int idx = tid + (l << 8);
            int plane = idx >> 9;
            int r = (idx >> 2) & 127;
            int cc = idx & 3;
            float4 v = *(float4*)(sm + L_OFF_R + plane * L_RPL + r * 80 + cc * 16);
            __nv_bfloat16* d = (plane ? RoutL : RoutH) + (long)(q0 + r) * 32 + cc * 8;
            *(float4*)d = v;
        }
    }
}

// ---------------- warp-MMA split-bf16 GEMM (skip / end1, unchanged from R6) -------
template <int MODE>
__global__ void __launch_bounds__(256, 1) mma_gemm(
    const __nv_bfloat16* __restrict__ BH, const __nv_bfloat16* __restrict__ BLo,
    const __nv_bfloat16* __restrict__ WHp, const __nv_bfloat16* __restrict__ WLp,
    const float* __restrict__ bias,
    __nv_bfloat16* __restrict__ outH, __nv_bfloat16* __restrict__ outL,
    float* __restrict__ outF)
{
    constexpr int KTOT = MODE ? 256 : 192;
    constexpr int NCH  = KTOT / 32;
    constexpr int PLSTR = 128 * 40 * 2;

    __shared__ __align__(16) __nv_bfloat16 sB[2][128][40];
    __shared__ __align__(16) __nv_bfloat16 sW[2][128][40];

    int tid = threadIdx.x;
    int warp = tid >> 5, lane = tid & 31;
    int p0 = blockIdx.x << 7;
    int m0 = blockIdx.y << 7;
    int warp_p = (warp & 1) << 6;
    int warp_m = (warp >> 1) << 5;

    uint32_t baseB = s2u(&sB[0][0][0]);
    uint32_t baseW = s2u(&sW[0][0][0]);

    const __nv_bfloat16* gB[2] = {BH + (long)p0 * KTOT, BLo + (long)p0 * KTOT};
    const __nv_bfloat16* gW[2] = {WHp + (long)m0 * KTOT, WLp + (long)m0 * KTOT};

    float acc[4][4][4];
#pragma unroll
    for (int pt = 0; pt < 4; pt++)
#pragma unroll
        for (int nt = 0; nt < 4; nt++)
#pragma unroll
            for (int j = 0; j < 4; j++) acc[pt][nt][j] = 0.f;

    int arow = lane & 15;
    int acol = (lane >> 4) << 3;
    int brow = lane & 7;
    int bcol = ((lane >> 3) & 1) << 3;

    for (int kc = 0; kc < NCH; kc++) {
        if (kc) __syncthreads();
        int ksrc = kc << 5;
#pragma unroll
        for (int i = 0; i < 4; i++) {
            int idx = tid + (i << 8);
            int plane = idx >> 9;
            int r = (idx >> 2) & 127;
            int q = (idx & 3) << 3;
            *(float4*)&sB[plane][r][q] = *(const float4*)(gB[plane] + (long)r * KTOT + ksrc + q);
            *(float4*)&sW[plane][r][q] = *(const float4*)(gW[plane] + (long)r * KTOT + ksrc + q);
        }
        __syncthreads();

#pragma unroll
        for (int ks = 0; ks < 2; ks++) {
            uint32_t aH[4][4], aL[4][4], bH[4][2], bL[4][2];
#pragma unroll
            for (int pt = 0; pt < 4; pt++) {
                uint32_t offs = (uint32_t)(((warp_p + (pt << 4) + arow) * 40 + (ks << 4) + acol) << 1);
                ldm_x4(aH[pt], baseB + offs);
                ldm_x4(aL[pt], baseB + PLSTR + offs);
            }
#pragma unroll
            for (int nt = 0; nt < 4; nt++) {
                uint32_t offs = (uint32_t)(((warp_m + (nt << 3) + brow) * 40 + (ks << 4) + bcol) << 1);
                ldm_x2(bH[nt], baseW + offs);
                ldm_x2(bL[nt], baseW + PLSTR + offs);
            }
#pragma unroll
            for (int pt = 0; pt < 4; pt++)
#pragma unroll
                for (int nt = 0; nt < 4; nt++) {
                    mma16816(acc[pt][nt], aH[pt], bH[nt]);
                    mma16816(acc[pt][nt], aL[pt], bH[nt]);
                    mma16816(acc[pt][nt], aH[pt], bL[nt]);
                }
        }
    }

    int prow = lane >> 2;
    int mcol = (lane & 3) << 1;
#pragma unroll
    for (int pt = 0; pt < 4; pt++) {
#pragma unroll
        for (int half = 0; half < 2; half++) {
            int p = p0 + warp_p + (pt << 4) + prow + (half << 3);
#pragma unroll
            for (int nt = 0; nt < 4; nt++) {
                float v0 = acc[pt][nt][half * 2];
                float v1 = acc[pt][nt][half * 2 + 1];
                int m = m0 + warp_m + (nt << 3) + mcol;
                if (MODE == 0) {
                    v0 = fmaxf(v0, 0.f);
                    v1 = fmaxf(v1, 0.f);
                    __nv_bfloat16 h0 = __float2bfloat16(v0);
                    __nv_bfloat16 h1 = __float2bfloat16(v1);
                    *(uint32_t*)((char*)outH + (long)p * 512 + m * 2) = pk16(h0, h1);
                    *(uint32_t*)((char*)outL + (long)p * 512 + m * 2) =
                        pk16(__float2bfloat16(v0 - __bfloat162float(h0)),
                             __float2bfloat16(v1 - __bfloat162float(h1)));
                } else {
                    outF[(long)m * NP + p] = fmaxf(v0 + __ldg(&bias[m]), 0.f);
                    outF[(long)(m + 1) * NP + p] = fmaxf(v1 + __ldg(&bias[m + 1]), 0.f);
                }
            }
        }
    }
}

// ---------------- 64x64 GEMM with split-K ----------------
template <class AL, class BL, class EP>
__global__ void __launch_bounds__(256) gemm64_kernel(int totKB, int splitKB, AL al, BL bl, EP ep)
{
    __shared__ float As[32][68];
    __shared__ float Bs[32][68];
    int mBase = blockIdx.y << 6;
    int pBase = blockIdx.x << 6;
    int kb0 = blockIdx.z * splitKB;
    int kb1 = kb0 + splitKB; if (kb1 > totKB) kb1 = totKB;
    int tid = threadIdx.x;
    int tx = tid & 15, ty = tid >> 4;
    float acc[4][4];
#pragma unroll
    for (int i = 0; i < 4; i++)
#pragma unroll
        for (int j = 0; j < 4; j++) acc[i][j] = 0.f;

    for (int kb = kb0; kb < kb1; kb++) {
        int k0 = kb << 5;
#pragma unroll
        for (int i = 0; i < 8; i++) {
            int idx = tid + (i << 8);
            int m = idx >> 5, k = idx & 31;
            As[k][m] = al(mBase + m, k0 + k);
        }
#pragma unroll
        for (int i = 0; i < 8; i++) {
            int idx = tid + (i << 8);
            int k = idx >> 6, p = idx & 63;
            Bs[k][p] = bl(k0 + k, pBase + p);
        }
        __syncthreads();
#pragma unroll
        for (int k = 0; k < 32; k++) {
            float4 a4 = *(const float4*)&As[k][ty << 2];
            float4 b4 = *(const float4*)&Bs[k][tx << 2];
            float a[4] = {a4.x, a4.y, a4.z, a4.w};
            float bb[4] = {b4.x, b4.y, b4.z, b4.w};
#pragma unroll
            for (int i = 0; i < 4; i++)
#pragma unroll
                for (int j = 0; j < 4; j++) acc[i][j] += a[i] * bb[j];
        }
        __syncthreads();
    }
#pragma unroll
    for (int i = 0; i < 4; i++) {
        int m = mBase + (ty << 2) + i;
#pragma unroll
        for (int j = 0; j < 4; j++) {
            int p = pBase + (tx << 2) + j;
            ep.store(m, p, acc[i][j]);
        }
    }
}

struct ALRowG {
    const float* A; int K, M;
    __device__ float operator()(int m, int k) const {
        return (m < M) ? A[m * K + k] : 0.f;
    }
};
struct BLRow {
    const float* B; int N;
    __device__ float operator()(int k, int p) const { return B[k * N + p]; }
};
struct EPBiasReluG {
    const float* bias; float* out; int N, M;
    __device__ void store(int m, int p, float v) const {
        if (m < M) out[m * N + p] = fmaxf(v + bias[m], 0.f);
    }
};
struct EPPart {
    float* out; int Mstride;
    __device__ void store(int m, int p, float v) const {
        out[blockIdx.z * Mstride + m * 256 + p] = v;
    }
};

// ---------------- maxpool k=3 s=2 over middle dim, layout [m][t][256b] ----------------
__global__ void pool_kernel(const float* __restrict__ in, float* __restrict__ out,
                            int Lin, int Lout, int total)
{
    int idx = blockIdx.x * 256 + threadIdx.x;
    if (idx >= total) return;
    int b = idx & 255;
    int q = idx >> 8;
    int tp = q % Lout;
    int m = q / Lout;
    const float* p = in + (m * Lin + 2 * tp) * 256 + b;
    out[idx] = fmaxf(fmaxf(p[0], p[256]), p[512]);
}

// ---------------- split-K reduce + bias + relu ----------------
__global__ void reduce_kernel(const float* __restrict__ part, const float* __restrict__ bias,
                              float* __restrict__ out, int S, int Mstride, int total)
{
    int idx = blockIdx.x * 256 + threadIdx.x;
    if (idx >= total) return;
    int m = idx >> 8;
    float s = 0.f;
    for (int z = 0; z < S; z++) s += part[z * Mstride + idx];
    out[idx] = fmaxf(s + bias[m], 0.f);
}

// ---------------- fc3 + softmax + argmax ----------------
__global__ void fc3_softmax_kernel(const float* __restrict__ F2, const float* __restrict__ W3,
                                   const float* __restrict__ B3, float* __restrict__ out)
{
    int b = threadIdx.x;
    float l0 = B3[0], l1 = B3[1];
    for (int k = 0; k < 256; k++) {
        float v = F2[k * 256 + b];
        l0 += W3[k] * v;
        l1 += W3[256 + k] * v;
    }
    out[2 * b] = l0;
    out[2 * b + 1] = l1;
    float mx = fmaxf(l0, l1);
    float e0 = __expf(l0 - mx), e1 = __expf(l1 - mx);
    float inv = 1.f / (e0 + e1);
    out[512 + 2 * b] = e0 * inv;
    out[512 + 2 * b + 1] = e1 * inv;
    out[1024 + b] = (l1 > l0) ? 1.f : 0.f;
}

// ---------------- host orchestration ----------------
extern "C" void kernel_launch(void* const* d_in, const int* in_sizes, int n_in,
                              void* d_out, int out_size)
{
    const float* x        = (const float*)d_in[0];
    const float* start_w  = (const float*)d_in[1];
    const float* filter_w = (const float*)d_in[2];
    const float* gate_w   = (const float*)d_in[3];
    const float* res_w    = (const float*)d_in[4];
    const float* skip_w   = (const float*)d_in[5];
    const float* end1_w   = (const float*)d_in[6];
    const float* end1_b   = (const float*)d_in[7];
    const float* end2_w   = (const float*)d_in[8];
    const float* end2_b   = (const float*)d_in[9];
    const float* fc_w1    = (const float*)d_in[10];
    const float* fc_b1    = (const float*)d_in[11];
    const float* fc_w2    = (const float*)d_in[12];
    const float* fc_b2    = (const float*)d_in[13];
    const float* fc_w3    = (const float*)d_in[14];
    const float* fc_b3    = (const float*)d_in[15];

    float *r1, *r2, *G, *skip, *y1, *p1, *y2, *p2, *f1p, *f1, *f2p, *f2;
    __nv_bfloat16 *wtc, *wl;
    cudaGetSymbolAddress((void**)&r1, g_r1);
    cudaGetSymbolAddress((void**)&r2, g_r2);
    cudaGetSymbolAddress((void**)&G, g_G);
    cudaGetSymbolAddress((void**)&skip, g_skip);
    cudaGetSymbolAddress((void**)&y1, g_y1);
    cudaGetSymbolAddress((void**)&p1, g_p1);
    cudaGetSymbolAddress((void**)&y2, g_y2);
    cudaGetSymbolAddress((void**)&p2, g_p2);
    cudaGetSymbolAddress((void**)&f1p, g_f1p);
    cudaGetSymbolAddress((void**)&f1, g_f1);
    cudaGetSymbolAddress((void**)&f2p, g_f2p);
    cudaGetSymbolAddress((void**)&f2, g_f2);
    cudaGetSymbolAddress((void**)&wtc, g_wtc);
    cudaGetSymbolAddress((void**)&wl, g_wlay);

    __nv_bfloat16* gtH = (__nv_bfloat16*)G;
    __nv_bfloat16* gtL = gtH + (long)NP * 192;
    __nv_bfloat16* sktH = (__nv_bfloat16*)skip;
    __nv_bfloat16* sktL = sktH + (long)NP * 256;
    __nv_bfloat16* wskH = wtc;
    __nv_bfloat16* wskL = wtc + 49152;
    __nv_bfloat16* we1H = wtc + 98304;
    __nv_bfloat16* we1L = wtc + 131072;

    __nv_bfloat16* s1H = (__nv_bfloat16*)r1;
    __nv_bfloat16* s1L = s1H + 10485760;
    __nv_bfloat16* s2H = (__nv_bfloat16*)r2;
    __nv_bfloat16* s2L = s2H + 10485760;

    cudaFuncSetAttribute(layer_mma, cudaFuncAttributeMaxDynamicSharedMemorySize, L_SMEM);

    // x -> xT (fp32, y1 scratch) -> start conv -> stream planes in r1
    {
        dim3 gx(40, 8, 5);
        xpose_kernel<<<gx, 256>>>(x, y1);
        startflat_kernel<<<40960, 256>>>(y1, start_w, s1H, s1L);
    }
    prepw_kernel<<<320, 256>>>(skip_w, end1_w, wtc);
    prepl_kernel<<<120, 256>>>(filter_w, gate_w, res_w, wl);

    // flat-stream layer constants
    const int QQ[6]  = {327424, 327168, 326656, 326400, 326144, 325632};
    const int NR[6]  = {256, 512, 1024, 256, 512, 1024};
    const int SS[6]  = {0, 256, 512, 0, 256, 512};
    const int OFF[6] = {1792, 1536, 1024, 768, 512, 0};

    __nv_bfloat16 *curH = s1H, *curL = s1L, *nxtH = s2H, *nxtL = s2L;
    for (int i = 0; i < 6; i++) {
        int nblk = QQ[i] >> 7;
        layer_mma<<<nblk, 256, L_SMEM>>>(curH, curL, wl + i * 10240,
                                         gtH, gtL, nxtH, nxtL,
                                         NR[i], SS[i], OFF[i], i * 64, (i < 5) ? 1 : 0);
        __nv_bfloat16* t;
        t = curH; curH = nxtH; nxtH = t;
        t = curL; curL = nxtL; nxtL = t;
    }

    // skip GEMM: 256 x 192 x NP, relu -> Skt hi/lo
    mma_gemm<0><<<dim3(NP / 128, 2), 256>>>(gtH, gtL, wskH, wskL, nullptr, sktH, sktL, nullptr);
    // end1 GEMM: 128 x 256 x NP, bias+relu -> y1 fp32
    mma_gemm<1><<<dim3(NP / 128, 1), 256>>>(sktH, sktL, we1H, we1L, end1_b, nullptr, nullptr, y1);

    // pool1: [128][1272][256] -> [128][635][256]
    {
        int total = 128 * 635 * 256;
        pool_kernel<<<(total + 255) / 256, 256>>>(y1, p1, 1272, 635, total);
    }
    // end2: 32 x 128 x 162560
    {
        ALRowG al = {end2_w, 128, 32};
        BLRow bl = {p1, 635 * 256};
        EPBiasReluG ep = {end2_b, y2, 635 * 256, 32};
        dim3 gg(635 * 256 / 64, 1, 1);
        gemm64_kernel<<<gg, 256>>>(4, 4, al, bl, ep);
    }
    // pool2: [32][635][256] -> [32][317][256]
    {
        int total = 32 * 317 * 256;
        pool_kernel<<<(total + 255) / 256, 256>>>(y2, p2, 635, 317, total);
    }
    // fc1: 1024 x 10144 x 256, split-K=8
    {
        ALRowG al = {fc_w1, 10144, 1024};
        BLRow bl = {p2, 256};
        EPPart ep = {f1p, 1024 * 256};
        dim3 gg(4, 16, 8);
        gemm64_kernel<<<gg, 256>>>(317, 40, al, bl, ep);
        int total = 1024 * 256;
        reduce_kernel<<<(total + 255) / 256, 256>>>(f1p, fc_b1, f1, 8, total, total);
    }
    // fc2: 256 x 1024 x 256, split-K=4
    {
        ALRowG al = {fc_w2, 1024, 256};
        BLRow bl = {f1, 256};
        EPPart ep = {f2p, 256 * 256};
        dim3 gg(4, 4, 4);
        gemm64_kernel<<<gg, 256>>>(32, 8, al, bl, ep);
        int total = 256 * 256;
        reduce_kernel<<<(total + 255) / 256, 256>>>(f2p, fc_b2, f2, 4, total, total);
    }
    // fc3 + softmax + argmax
    fc3_softmax_kernel<<<1, 256>>>(f2, fc_w3, fc_b3, (float*)d_out);
}

// round 10
// speedup vs baseline: 6.0575x; 1.2204x over previous
#include <cuda_runtime.h>
#include <cuda_bf16.h>
#include <math.h>
#include <stdint.h>

#define NP 325632   // 1272 * 256 : columns of the big GEMMs, p = t*256 + b

// ---------------- scratch (device globals; no allocation) ----------------
__device__ float g_r1[10485760];     // stream ping: bf16 planes XH/XL [q][32]
__device__ float g_r2[10485760];     // stream pong
__device__ float g_G[62521344];      // bf16 planes: GtH [NP][192], GtL [NP][192]
__device__ float g_skip[83361792];   // reused: wfc1H/L bf16 [1024][10144], we2H/L [32][128]
__device__ float g_y1[41680896];     // bf16 planes y1H/[NP][128], y1L
__device__ float g_p1[20801536];     // (spare)
__device__ float g_y2[5201920];      // bf16 planes y2H/[162560][32], y2L
__device__ float g_p2[2596864];      // bf16 planes p2H/[81152][32], p2L
__device__ float g_f1p[2097152];     // fc1 split-K partials 8 x 1024 x 256
__device__ float g_f1[262144];       // 1024 x 256
__device__ float g_f2p[262144];      // fc2 partials 4 x 256 x 256
__device__ float g_f2[65536];        // 256 x 256
__device__ __nv_bfloat16 g_wtc[163840]; // wskH[49152] wskL[49152] we1H[32768] we1L[32768]
__device__ __nv_bfloat16 g_wlay[61440]; // per-layer: WfgH[4096] WfgL[4096] WrH[1024] WrL[1024]

// ================= mma.sync helpers (sm_80+ portable) =================
__device__ __forceinline__ uint32_t s2u(const void* p) {
    uint32_t a;
    asm("{ .reg .u64 t; cvta.to.shared.u64 t, %1; cvt.u32.u64 %0, t; }" : "=r"(a) : "l"(p));
    return a;
}
__device__ __forceinline__ void ldm_x4(uint32_t* r, uint32_t addr) {
    asm volatile("ldmatrix.sync.aligned.m8n8.x4.shared.b16 {%0,%1,%2,%3}, [%4];"
                 : "=r"(r[0]), "=r"(r[1]), "=r"(r[2]), "=r"(r[3]) : "r"(addr));
}
__device__ __forceinline__ void ldm_x2(uint32_t* r, uint32_t addr) {
    asm volatile("ldmatrix.sync.aligned.m8n8.x2.shared.b16 {%0,%1}, [%2];"
                 : "=r"(r[0]), "=r"(r[1]) : "r"(addr));
}
__device__ __forceinline__ void mma16816(float* c, const uint32_t* a, const uint32_t* b) {
    asm volatile(
        "mma.sync.aligned.m16n8k16.row.col.f32.bf16.bf16.f32 "
        "{%0,%1,%2,%3}, {%4,%5,%6,%7}, {%8,%9}, {%0,%1,%2,%3};"
        : "+f"(c[0]), "+f"(c[1]), "+f"(c[2]), "+f"(c[3])
        : "r"(a[0]), "r"(a[1]), "r"(a[2]), "r"(a[3]), "r"(b[0]), "r"(b[1]));
}
__device__ __forceinline__ uint32_t pk16(__nv_bfloat16 a, __nv_bfloat16 b) {
    __nv_bfloat162 t;
    t.x = a; t.y = b;
    return *reinterpret_cast<uint32_t*>(&t);
}
__device__ __forceinline__ float2 bf2f(uint32_t u) {
    __nv_bfloat162 t = *reinterpret_cast<__nv_bfloat162*>(&u);
    return make_float2(__bfloat162float(t.x), __bfloat162float(t.y));
}
__device__ __forceinline__ void split2(float v0, float v1, uint32_t& h, uint32_t& l) {
    __nv_bfloat16 h0 = __float2bfloat16(v0), h1 = __float2bfloat16(v1);
    h = pk16(h0, h1);
    l = pk16(__float2bfloat16(v0 - __bfloat162float(h0)),
             __float2bfloat16(v1 - __bfloat162float(h1)));
}

// ---------------- x (b,5,t) -> xT[i][p = t*256 + b] ----------------
__global__ void xpose_kernel(const float* __restrict__ x, float* __restrict__ xT)
{
    __shared__ float S[32][33];
    int i  = blockIdx.z;
    int t0 = blockIdx.x << 5;
    int b0 = blockIdx.y << 5;
    int col = threadIdx.x & 31;
    int r0  = threadIdx.x >> 5;
#pragma unroll
    for (int l = 0; l < 4; l++) {
        int bb = r0 + (l << 3);
        S[bb][col] = x[(b0 + bb) * 6400 + i * 1280 + t0 + col];
    }
    __syncthreads();
#pragma unroll
    for (int l = 0; l < 4; l++) {
        int tt = r0 + (l << 3);
        xT[i * 327680 + (t0 + tt) * 256 + b0 + col] = S[col][tt];
    }
}

// ---------------- start conv -> stream planes [q][32] bf16 hi/lo ----------------
__global__ void startflat_kernel(const float* __restrict__ xT, const float* __restrict__ w,
                                 __nv_bfloat16* __restrict__ XH, __nv_bfloat16* __restrict__ XL)
{
    int idx = blockIdx.x * 256 + threadIdx.x;   // 327680*32
    int q = idx >> 5, c = idx & 31;
    float acc = 0.f;
#pragma unroll
    for (int i = 0; i < 5; i++) acc += __ldg(&w[c * 5 + i]) * xT[i * 327680 + q];
    __nv_bfloat16 h = __float2bfloat16(acc);
    XH[idx] = h;
    XL[idx] = __float2bfloat16(acc - __bfloat162float(h));
}

// ---------------- weight prep for skip/end1 ----------------
__global__ void prepw_kernel(const float* __restrict__ sw, const float* __restrict__ e1,
                             __nv_bfloat16* __restrict__ wt)
{
    int idx = blockIdx.x * 256 + threadIdx.x;
    if (idx < 49152) {
        int m = idx / 192, k = idx - m * 192;
        float v = sw[(k >> 5) * 8192 + m * 32 + (k & 31)];
        __nv_bfloat16 h = __float2bfloat16(v);
        wt[idx] = h;
        wt[49152 + idx] = __float2bfloat16(v - __bfloat162float(h));
    } else if (idx < 81920) {
        int i2 = idx - 49152;
        float v = e1[i2];
        __nv_bfloat16 h = __float2bfloat16(v);
        wt[98304 + i2] = h;
        wt[131072 + i2] = __float2bfloat16(v - __bfloat162float(h));
    }
}

// ---------------- per-layer weight prep: Wfg [64m][64k] + Wr [32][32], hi/lo ---------
__global__ void prepl_kernel(const float* __restrict__ fw, const float* __restrict__ gw,
                             const float* __restrict__ rw, __nv_bfloat16* __restrict__ wl)
{
    int idx = blockIdx.x * 256 + threadIdx.x;
    if (idx < 24576) {
        int lay = idx >> 12;
        int r = idx & 4095;
        int m = r >> 6, k = r & 63;
        const float* src = ((m < 32) ? fw : gw) + lay * 2048 + (m & 31) * 64 + (k & 31) * 2 + (k >> 5);
        float v = *src;
        __nv_bfloat16 h = __float2bfloat16(v);
        wl[lay * 10240 + r] = h;
        wl[lay * 10240 + 4096 + r] = __float2bfloat16(v - __bfloat162float(h));
    } else if (idx < 30720) {
        int j = idx - 24576;
        int lay = j >> 10;
        int r = j & 1023;
        float v = rw[lay * 1024 + r];
        __nv_bfloat16 h = __float2bfloat16(v);
        wl[lay * 10240 + 8192 + r] = h;
        wl[lay * 10240 + 9216 + r] = __float2bfloat16(v - __bfloat162float(h));
    }
}

// ---------------- fc1 weight prep: [m][c*317+t] -> bf16 hi/lo [m][t*32+c] ----------
__global__ void prepfc_kernel(const float* __restrict__ w1,
                              __nv_bfloat16* __restrict__ WH, __nv_bfloat16* __restrict__ WL)
{
    __shared__ float S[32][33];
    int m = blockIdx.y;
    int t0 = blockIdx.x << 5;
    int a = threadIdx.x & 31;
    int b8 = threadIdx.x >> 5;
#pragma unroll
    for (int l = 0; l < 4; l++) {
        int c = b8 + (l << 3);
        int t = t0 + a;
        S[c][a] = (t < 317) ? w1[m * 10144 + c * 317 + t] : 0.f;
    }
    __syncthreads();
#pragma unroll
    for (int l = 0; l < 4; l++) {
        int tt = b8 + (l << 3);
        int t = t0 + tt;
        if (t < 317) {
            float v = S[a][tt];
            __nv_bfloat16 h = __float2bfloat16(v);
            WH[m * 10144 + t * 32 + a] = h;
            WL[m * 10144 + t * 32 + a] = __float2bfloat16(v - __bfloat162float(h));
        }
    }
}

// ---------------- end2 weight prep ----------------
__global__ void prepe2_kernel(const float* __restrict__ e2,
                              __nv_bfloat16* __restrict__ H, __nv_bfloat16* __restrict__ L)
{
    int i = blockIdx.x * 256 + threadIdx.x;
    if (i < 4096) {
        float v = e2[i];
        __nv_bfloat16 h = __float2bfloat16(v);
        H[i] = h;
        L[i] = __float2bfloat16(v - __bfloat162float(h));
    }
}

// ---------------- fused layer via mma.sync ----------------
__device__ __forceinline__ float fast_gate(float f, float g)
{
    float ef = __expf(f + f);
    float th = 1.f - __fdividef(2.f, ef + 1.f);
    float sg = __fdividef(1.f, 1.f + __expf(-g));
    return th * sg;
}

#define L_OFF_X  0
#define L_XPL    18432
#define L_OFF_W  36864
#define L_WPL    9216
#define L_OFF_WR 55296
#define L_WRPL   2560
#define L_OFF_H  60416
#define L_HPL    10240
#define L_OFF_R  80896
#define L_RPL    10240
#define L_SMEM   101376

__global__ void __launch_bounds__(256, 1) layer_mma(
    const __nv_bfloat16* __restrict__ XH, const __nv_bfloat16* __restrict__ XL,
    const __nv_bfloat16* __restrict__ wlay,
    __nv_bfloat16* __restrict__ gtH, __nv_bfloat16* __restrict__ gtL,
    __nv_bfloat16* __restrict__ RoutH, __nv_bfloat16* __restrict__ RoutL,
    int nr, int s, int off, int lay64, int writeRes)
{
    extern __shared__ char sm[];
    uint32_t sb = s2u(sm);
    int tid = threadIdx.x;
    int q0 = blockIdx.x << 7;

#pragma unroll
    for (int l = 0; l < 8; l++) {
        int idx = tid + (l << 8);
        int plane = idx >> 10;
        int r = (idx >> 3) & 127;
        int seg = idx & 7;
        int tap = seg >> 2;
        int qa = q0 + r - s + (tap ? nr : 0);
        char* dst = sm + L_OFF_X + plane * L_XPL + r * 144 + seg * 16;
        if (!tap && qa < 0) {
            *(float4*)dst = make_float4(0.f, 0.f, 0.f, 0.f);
        } else {
            const __nv_bfloat16* src = (plane ? XL : XH) + (long)qa * 32 + ((seg & 3) << 3);
            *(float4*)dst = *(const float4*)src;
        }
    }
#pragma unroll
    for (int l = 0; l < 4; l++) {
        int idx = tid + (l << 8);
        int plane = idx >> 9;
        int r = (idx >> 3) & 63;
        int cc = idx & 7;
        *(float4*)(sm + L_OFF_W + plane * L_WPL + r * 144 + cc * 16) =
            *(const float4*)(wlay + plane * 4096 + r * 64 + cc * 8);
    }
    {
        int idx = tid;
        int plane = idx >> 7;
        int r = (idx >> 2) & 31;
        int cc = idx & 3;
        *(float4*)(sm + L_OFF_WR + plane * L_WRPL + r * 80 + cc * 16) =
            *(const float4*)(wlay + 8192 + plane * 1024 + r * 32 + cc * 8);
    }
    __syncthreads();

    int warp = tid >> 5, lane = tid & 31;
    int warp_q = (warp & 3) << 5;
    int g = warp >> 2;
    int arow = lane & 15, acol = (lane >> 4) << 3;
    int brow = lane & 7, bcol = ((lane >> 3) & 1) << 3;

    float acc[2][4][4];
#pragma unroll
    for (int pt = 0; pt < 2; pt++)
#pragma unroll
        for (int nt = 0; nt < 4; nt++)
#pragma unroll
            for (int j = 0; j < 4; j++) acc[pt][nt][j] = 0.f;

#pragma unroll
    for (int kc = 0; kc < 4; kc++) {
        uint32_t aH[2][4], aL[2][4], bH[4][2], bL[4][2];
#pragma unroll
        for (int pt = 0; pt < 2; pt++) {
            uint32_t o = L_OFF_X + (uint32_t)((warp_q + (pt << 4) + arow) * 144 + (((kc << 4) + acol) << 1));
            ldm_x4(aH[pt], sb + o);
            ldm_x4(aL[pt], sb + L_XPL + o);
        }
#pragma unroll
        for (int nt = 0; nt < 4; nt++) {
            int msm = (nt < 2) ? (g * 16 + nt * 8) : (32 + g * 16 + (nt - 2) * 8);
            uint32_t o = L_OFF_W + (uint32_t)((msm + brow) * 144 + (((kc << 4) + bcol) << 1));
            ldm_x2(bH[nt], sb + o);
            ldm_x2(bL[nt], sb + L_WPL + o);
        }
#pragma unroll
        for (int pt = 0; pt < 2; pt++)
#pragma unroll
            for (int nt = 0; nt < 4; nt++) {
                mma16816(acc[pt][nt], aH[pt], bH[nt]);
                mma16816(acc[pt][nt], aL[pt], bH[nt]);
                mma16816(acc[pt][nt], aH[pt], bL[nt]);
            }
    }

#pragma unroll
    for (int pt = 0; pt < 2; pt++)
#pragma unroll
        for (int nt = 0; nt < 2; nt++)
#pragma unroll
            for (int jh = 0; jh < 2; jh++) {
                float F0 = acc[pt][nt][jh * 2], F1 = acc[pt][nt][jh * 2 + 1];
                float G0 = acc[pt][nt + 2][jh * 2], G1 = acc[pt][nt + 2][jh * 2 + 1];
                float h0 = fast_gate(F0, G0);
                float h1 = fast_gate(F1, G1);
                int q = warp_q + (pt << 4) + (lane >> 2) + (jh << 3);
                int c0 = g * 16 + nt * 8 + ((lane & 3) << 1);
                uint32_t hw, lw;
                split2(h0, h1, hw, lw);
                *(uint32_t*)(sm + L_OFF_H + q * 80 + c0 * 2) = hw;
                *(uint32_t*)(sm + L_OFF_H + L_HPL + q * 80 + c0 * 2) = lw;
            }
    __syncthreads();

#pragma unroll
    for (int l = 0; l < 4; l++) {
        int idx = tid + (l << 8);
        int plane = idx >> 9;
        int r = (idx >> 2) & 127;
        int cc = idx & 3;
        int pg = q0 + r - off;
        if (pg >= 0) {
            float4 v = *(float4*)(sm + L_OFF_H + plane * L_HPL + r * 80 + cc * 16);
            char* d = (char*)(plane ? gtL : gtH) + (long)pg * 384 + lay64 + cc * 16;
            *(float4*)d = v;
        }
    }

    if (writeRes) {
        float acc2[2][2][4];
#pragma unroll
        for (int pt = 0; pt < 2; pt++)
#pragma unroll
            for (int nt = 0; nt < 2; nt++)
#pragma unroll
                for (int j = 0; j < 4; j++) acc2[pt][nt][j] = 0.f;

#pragma unroll
        for (int kc = 0; kc < 2; kc++) {
            uint32_t aH[2][4], aL[2][4], bH[2][2], bL[2][2];
#pragma unroll
            for (int pt = 0; pt < 2; pt++) {
                uint32_t o = L_OFF_H + (uint32_t)((warp_q + (pt << 4) + arow) * 80 + (((kc << 4) + acol) << 1));
                ldm_x4(aH[pt], sb + o);
                ldm_x4(aL[pt], sb + L_HPL + o);
            }
#pragma unroll
            for (int nt = 0; nt < 2; nt++) {
                uint32_t o = L_OFF_WR + (uint32_t)((g * 16 + nt * 8 + brow) * 80 + (((kc << 4) + bcol) << 1));
                ldm_x2(bH[nt], sb + o);
                ldm_x2(bL[nt], sb + L_WRPL + o);
            }
#pragma unroll
            for (int pt = 0; pt < 2; pt++)
#pragma unroll
                for (int nt = 0; nt < 2; nt++) {
                    mma16816(acc2[pt][nt], aH[pt], bH[nt]);
                    mma16816(acc2[pt][nt], aL[pt], bH[nt]);
                    mma16816(acc2[pt][nt], aH[pt], bL[nt]);
                }
        }

#pragma unroll
        for (int pt = 0; pt < 2; pt++)
#pragma unroll
            for (int nt = 0; nt < 2; nt++)
#pragma unroll
                for (int jh = 0; jh < 2; jh++) {
                    int q = warp_q + (pt << 4) + (lane >> 2) + (jh << 3);
                    int c0 = g * 16 + nt * 8 + ((lane & 3) << 1);
                    const __nv_bfloat16* xh = (const __nv_bfloat16*)(sm + L_OFF_X + q * 144 + (32 + c0) * 2);
                    const __nv_bfloat16* xl = (const __nv_bfloat16*)(sm + L_OFF_X + L_XPL + q * 144 + (32 + c0) * 2);
                    float xb0 = __bfloat162float(xh[0]) + __bfloat162float(xl[0]);
                    float xb1 = __bfloat162float(xh[1]) + __bfloat162float(xl[1]);
                    float v0 = acc2[pt][nt][jh * 2] + xb0;
                    float v1 = acc2[pt][nt][jh * 2 + 1] + xb1;
                    uint32_t hw, lw;
                    split2(v0, v1, hw, lw);
                    *(uint32_t*)(sm + L_OFF_R + q * 80 + c0 * 2) = hw;
                    *(uint32_t*)(sm + L_OFF_R + L_RPL + q * 80 + c0 * 2) = lw;
                }
        __syncthreads();

#pragma unroll
        for (int l = 0; l < 4; l++) {
            int idx = tid + (l << 8);
            int plane = idx >> 9;
            int r = (idx >> 2) & 127;
            int cc = idx & 3;
            float4 v = *(float4*)(sm + L_OFF_R + plane * L_RPL + r * 80 + cc * 16);
            __nv_bfloat16* d = (plane ? RoutL : RoutH) + (long)(q0 + r) * 32 + cc * 8;
            *(float4*)d = v;
        }
    }
}

// ---------------- fused skip+end1 megakernel ----------------
#define MG_OFF_SB 0
#define MG_SBPL   10240
#define MG_OFF_SW 20480
#define MG_SWPL   20480
#define MG_OFF_S  61440
#define MG_SPL    67584
#define MG_SMEM   196608

__global__ void __launch_bounds__(256, 1) mega_gemm(
    const __nv_bfloat16* __restrict__ gtH, const __nv_bfloat16* __restrict__ gtL,
    const __nv_bfloat16* __restrict__ wskH, const __nv_bfloat16* __restrict__ wskL,
    const __nv_bfloat16* __restrict__ we1H, const __nv_bfloat16* __restrict__ we1L,
    const float* __restrict__ bias,
    __nv_bfloat16* __restrict__ y1H, __nv_bfloat16* __restrict__ y1L)
{
    extern __shared__ char sm[];
    uint32_t sb = s2u(sm);
    int tid = threadIdx.x;
    int warp = tid >> 5, lane = tid & 31;
    int p0 = blockIdx.x << 7;
    int warp_p = (warp & 1) << 6;
    int warp_mA = (warp >> 1) << 6;
    int warp_mB = (warp >> 1) << 5;
    int arow = lane & 15, acol = (lane >> 4) << 3;
    int brow = lane & 7, bcol = ((lane >> 3) & 1) << 3;
    int prow = lane >> 2, mcol = (lane & 3) << 1;

    // ---- stage A ----
    float acc[4][8][4];
#pragma unroll
    for (int pt = 0; pt < 4; pt++)
#pragma unroll
        for (int nt = 0; nt < 8; nt++)
#pragma unroll
            for (int j = 0; j < 4; j++) acc[pt][nt][j] = 0.f;

    for (int kc = 0; kc < 6; kc++) {
        __syncthreads();
#pragma unroll
        for (int l = 0; l < 4; l++) {
            int idx = tid + (l << 8);
            int plane = idx >> 9;
            int r = (idx >> 2) & 127;
            int c = idx & 3;
            *(float4*)(sm + MG_OFF_SB + plane * MG_SBPL + r * 80 + c * 16) =
                *(const float4*)((plane ? gtL : gtH) + (long)(p0 + r) * 192 + kc * 32 + c * 8);
        }
#pragma unroll
        for (int l = 0; l < 8; l++) {
            int idx = tid + (l << 8);
            int plane = idx >> 10;
            int r = (idx >> 2) & 255;
            int c = idx & 3;
            *(float4*)(sm + MG_OFF_SW + plane * MG_SWPL + r * 80 + c * 16) =
                *(const float4*)((plane ? wskL : wskH) + (long)r * 192 + kc * 32 + c * 8);
        }
        __syncthreads();
#pragma unroll
        for (int ks = 0; ks < 2; ks++) {
            uint32_t aH[4][4], aL[4][4], bH[8][2], bL[8][2];
#pragma unroll
            for (int pt = 0; pt < 4; pt++) {
                uint32_t o = MG_OFF_SB + (uint32_t)((warp_p + (pt << 4) + arow) * 80 + (((ks << 4) + acol) << 1));
                ldm_x4(aH[pt], sb + o);
                ldm_x4(aL[pt], sb + MG_SBPL + o);
            }
#pragma unroll
            for (int nt = 0; nt < 8; nt++) {
                uint32_t o = MG_OFF_SW + (uint32_t)((warp_mA + (nt << 3) + brow) * 80 + (((ks << 4) + bcol) << 1));
                ldm_x2(bH[nt], sb + o);
                ldm_x2(bL[nt], sb + MG_SWPL + o);
            }
#pragma unroll
            for (int pt = 0; pt < 4; pt++)
#pragma unroll
                for (int nt = 0; nt < 8; nt++) {
                    mma16816(acc[pt][nt], aH[pt], bH[nt]);
                    mma16816(acc[pt][nt], aL[pt], bH[nt]);
                    mma16816(acc[pt][nt], aH[pt], bL[nt]);
                }
        }
    }

    // epilogue A: relu + split -> S smem
#pragma unroll
    for (int pt = 0; pt < 4; pt++)
#pragma unroll
        for (int half = 0; half < 2; half++) {
            int pl = warp_p + (pt << 4) + prow + (half << 3);
#pragma unroll
            for (int nt = 0; nt < 8; nt++) {
                float v0 = fmaxf(acc[pt][nt][half * 2], 0.f);
                float v1 = fmaxf(acc[pt][nt][half * 2 + 1], 0.f);
                int m = warp_mA + (nt << 3) + mcol;
                uint32_t hw, lw;
                split2(v0, v1, hw, lw);
                *(uint32_t*)(sm + MG_OFF_S + pl * 528 + m * 2) = hw;
                *(uint32_t*)(sm + MG_OFF_S + MG_SPL + pl * 528 + m * 2) = lw;
            }
        }
    __syncthreads();

    // ---- stage B ----
    float acc2[4][4][4];
#pragma unroll
    for (int pt = 0; pt < 4; pt++)
#pragma unroll
        for (int nt = 0; nt < 4; nt++)
#pragma unroll
            for (int j = 0; j < 4; j++) acc2[pt][nt][j] = 0.f;

    for (int kc = 0; kc < 8; kc++) {
        __syncthreads();
#pragma unroll
        for (int l = 0; l < 4; l++) {
            int idx = tid + (l << 8);
            int plane = idx >> 9;
            int r = (idx >> 2) & 127;
            int c = idx & 3;
            *(float4*)(sm + MG_OFF_SW + plane * MG_SWPL + r * 80 + c * 16) =
                *(const float4*)((plane ? we1L : we1H) + (long)r * 256 + kc * 32 + c * 8);
        }
        __syncthreads();
#pragma unroll
        for (int ks = 0; ks < 2; ks++) {
            uint32_t aH[4][4], aL[4][4], bH[4][2], bL[4][2];
#pragma unroll
            for (int pt = 0; pt < 4; pt++) {
                uint32_t o = MG_OFF_S + (uint32_t)((warp_p + (pt << 4) + arow) * 528 + (((kc << 5) + (ks << 4) + acol) << 1));
                ldm_x4(aH[pt], sb + o);
                ldm_x4(aL[pt], sb + MG_SPL + o);
            }
#pragma unroll
            for (int nt = 0; nt < 4; nt++) {
                uint32_t o = MG_OFF_SW + (uint32_t)((warp_mB + (nt << 3) + brow) * 80 + (((ks << 4) + bcol) << 1));
                ldm_x2(bH[nt], sb + o);
                ldm_x2(bL[nt], sb + MG_SWPL + o);
            }
#pragma unroll
            for (int pt = 0; pt < 4; pt++)
#pragma unroll
                for (int nt = 0; nt < 4; nt++) {
                    mma16816(acc2[pt][nt], aH[pt], bH[nt]);
                    mma16816(acc2[pt][nt], aL[pt], bH[nt]);
                    mma16816(acc2[pt][nt], aH[pt], bL[nt]);
                }
        }
    }

    // epilogue B: +bias, relu, split -> y1 pairs
#pragma unroll
    for (int pt = 0; pt < 4; pt++)
#pragma unroll
        for (int half = 0; half < 2; half++) {
            int p = p0 + warp_p + (pt << 4) + prow + (half << 3);
#pragma unroll
            for (int nt = 0; nt < 4; nt++) {
                int m = warp_mB + (nt << 3) + mcol;
                float v0 = fmaxf(acc2[pt][nt][half * 2] + __ldg(&bias[m]), 0.f);
                float v1 = fmaxf(acc2[pt][nt][half * 2 + 1] + __ldg(&bias[m + 1]), 0.f);
                uint32_t hw, lw;
                split2(v0, v1, hw, lw);
                *(uint32_t*)((char*)y1H + (long)p * 256 + m * 2) = hw;
                *(uint32_t*)((char*)y1L + (long)p * 256 + m * 2) = lw;
            }
        }
}

// ---------------- fused pool1 + end2 (mma) ----------------
#define E2_OFF_A 0
#define E2_APL   69632
#define E2_OFF_W 139264
#define E2_WPL   8704
#define E2_SMEM  156672

__global__ void __launch_bounds__(256, 1) end2_mma(
    const __nv_bfloat16* __restrict__ y1H, const __nv_bfloat16* __restrict__ y1L,
    const __nv_bfloat16* __restrict__ we2H, const __nv_bfloat16* __restrict__ we2L,
    const float* __restrict__ bias,
    __nv_bfloat16* __restrict__ y2H, __nv_bfloat16* __restrict__ y2L)
{
    extern __shared__ char sm[];
    uint32_t sb = s2u(sm);
    int tid = threadIdx.x;
    int tq = blockIdx.x;

    // A loader with fused max-pool (k=3,s=2 over t): 256 rows x 128 bf16 (16 chunks/row)
#pragma unroll
    for (int l = 0; l < 16; l++) {
        int idx = tid + (l << 8);
        int r = idx >> 4, c8 = idx & 15;
        long e = ((long)(2 * tq) * 256 + r) * 128 + (c8 << 3);
        float4 h0 = *(const float4*)(y1H + e);
        float4 h1 = *(const float4*)(y1H + e + 32768);
        float4 h2 = *(const float4*)(y1H + e + 65536);
        float4 l0 = *(const float4*)(y1L + e);
        float4 l1 = *(const float4*)(y1L + e + 32768);
        float4 l2 = *(const float4*)(y1L + e + 65536);
        uint32_t oh[4], ol[4];
#pragma unroll
        for (int w = 0; w < 4; w++) {
            float2 a0 = bf2f(((uint32_t*)&h0)[w]);
            float2 b0 = bf2f(((uint32_t*)&l0)[w]);
            float2 a1 = bf2f(((uint32_t*)&h1)[w]);
            float2 b1 = bf2f(((uint32_t*)&l1)[w]);
            float2 a2 = bf2f(((uint32_t*)&h2)[w]);
            float2 b2 = bf2f(((uint32_t*)&l2)[w]);
            float vx = fmaxf(fmaxf(a0.x + b0.x, a1.x + b1.x), a2.x + b2.x);
            float vy = fmaxf(fmaxf(a0.y + b0.y, a1.y + b1.y), a2.y + b2.y);
            split2(vx, vy, oh[w], ol[w]);
        }
        *(float4*)(sm + E2_OFF_A + r * 272 + c8 * 16) = *(float4*)oh;
        *(float4*)(sm + E2_OFF_A + E2_APL + r * 272 + c8 * 16) = *(float4*)ol;
    }
    // W loader: 32 rows x 128 bf16 (16 chunks/row) x 2 planes
#pragma unroll
    for (int l = 0; l < 4; l++) {
        int idx = tid + (l << 8);
        int plane = idx >> 9;
        int r = (idx >> 4) & 31;
        int c = idx & 15;
        *(float4*)(sm + E2_OFF_W + plane * E2_WPL + r * 272 + c * 16) =
            *(const float4*)((plane ? we2L : we2H) + r * 128 + c * 8);
    }
    __syncthreads();

    int warp = tid >> 5, lane = tid & 31;
    int warp_p = warp << 5;
    int arow = lane & 15, acol = (lane >> 4) << 3;
    int brow = lane & 7, bcol = ((lane >> 3) & 1) << 3;
    int prow = lane >> 2, mcol = (lane & 3) << 1;

    float acc[2][4][4];
#pragma unroll
    for (int pt = 0; pt < 2; pt++)
#pragma unroll
        for (int nt = 0; nt < 4; nt++)
#pragma unroll
            for (int j = 0; j < 4; j++) acc[pt][nt][j] = 0.f;

#pragma unroll
    for (int ks = 0; ks < 8; ks++) {
        uint32_t aH[2][4], aL[2][4], bH[4][2], bL[4][2];
#pragma unroll
        for (int pt = 0; pt < 2; pt++) {
            uint32_t o = E2_OFF_A + (uint32_t)((warp_p + (pt << 4) + arow) * 272 + (((ks << 4) + acol) << 1));
            ldm_x4(aH[pt], sb + o);
            ldm_x4(aL[pt], sb + E2_APL + o);
        }
#pragma unroll
        for (int nt = 0; nt < 4; nt++) {
            uint32_t o = E2_OFF_W + (uint32_t)(((nt << 3) + brow) * 272 + (((ks << 4) + bcol) << 1));
            ldm_x2(bH[nt], sb + o);
            ldm_x2(bL[nt], sb + E2_WPL + o);
        }
#pragma unroll
        for (int pt = 0; pt < 2; pt++)
#pragma unroll
            for (int nt = 0; nt < 4; nt++) {
                mma16816(acc[pt][nt], aH[pt], bH[nt]);
                mma16816(acc[pt][nt], aL[pt], bH[nt]);
                mma16816(acc[pt][nt], aH[pt], bL[nt]);
            }
    }

#pragma unroll
    for (int pt = 0; pt < 2; pt++)
#pragma unroll
        for (int half = 0; half < 2; half++) {
            long pp = (long)tq * 256 + warp_p + (pt << 4) + prow + (half << 3);
#pragma unroll
            for (int nt = 0; nt < 4; nt++) {
                int m = (nt << 3) + mcol;
                float v0 = fmaxf(acc[pt][nt][half * 2] + __ldg(&bias[m]), 0.f);
                float v1 = fmaxf(acc[pt][nt][half * 2 + 1] + __ldg(&bias[m + 1]), 0.f);
                uint32_t hw, lw;
                split2(v0, v1, hw, lw);
                *(uint32_t*)((char*)y2H + pp * 64 + m * 2) = hw;
                *(uint32_t*)((char*)y2L + pp * 64 + m * 2) = lw;
            }
        }
}

// ---------------- pool2 on bf16 pairs ----------------
__global__ void pool2_kernel(const __nv_bfloat16* __restrict__ y2H, const __nv_bfloat16* __restrict__ y2L,
                             __nv_bfloat16* __restrict__ p2H, __nv_bfloat16* __restrict__ p2L)
{
    int idx = blockIdx.x * 256 + threadIdx.x;
    if (idx >= 81152 * 16) return;
    int u = idx & 15;
    int ppp = idx >> 4;
    int b = ppp & 255, tq = ppp >> 8;
    const uint32_t* H = (const uint32_t*)y2H;
    const uint32_t* L = (const uint32_t*)y2L;
    long r0 = ((long)(2 * tq) * 256 + b) * 16 + u;
    float2 a0 = bf2f(H[r0]),        b0 = bf2f(L[r0]);
    float2 a1 = bf2f(H[r0 + 4096]), b1 = bf2f(L[r0 + 4096]);
    float2 a2 = bf2f(H[r0 + 8192]), b2 = bf2f(L[r0 + 8192]);
    float vx = fmaxf(fmaxf(a0.x + b0.x, a1.x + b1.x), a2.x + b2.x);
    float vy = fmaxf(fmaxf(a0.y + b0.y, a1.y + b1.y), a2.y + b2.y);
    uint32_t hw, lw;
    split2(vx, vy, hw, lw);
    ((uint32_t*)p2H)[(long)ppp * 16 + u] = hw;
    ((uint32_t*)p2L)[(long)ppp * 16 + u] = lw;
}

// ---------------- fc1 via mma: D[256b][1024m], K'=t*32+c, split-K=8 ----------------
__global__ void __launch_bounds__(256, 1) fc1_mma(
    const __nv_bfloat16* __restrict__ p2H, const __nv_bfloat16* __restrict__ p2L,
    const __nv_bfloat16* __restrict__ wH, const __nv_bfloat16* __restrict__ wL,
    float* __restrict__ part)
{
    __shared__ __align__(16) char sm[40960];
    uint32_t sb = s2u(sm);
    int tid = threadIdx.x;
    int b0 = blockIdx.x << 7, m0 = blockIdx.y << 7, z = blockIdx.z;
    int t1 = z * 40 + 40; if (t1 > 317) t1 = 317;

    int warp = tid >> 5, lane = tid & 31;
    int warp_p = (warp & 1) << 6;
    int warp_m = (warp >> 1) << 5;
    int arow = lane & 15, acol = (lane >> 4) << 3;
    int brow = lane & 7, bcol = ((lane >> 3) & 1) << 3;
    int prow = lane >> 2, mcol = (lane & 3) << 1;

    float acc[4][4][4];
#pragma unroll
    for (int pt = 0; pt < 4; pt++)
#pragma unroll
        for (int nt = 0; nt < 4; nt++)
#pragma unroll
            for (int j = 0; j < 4; j++) acc[pt][nt][j] = 0.f;

    for (int t = z * 40; t < t1; t++) {
        __syncthreads();
#pragma unroll
        for (int l = 0; l < 4; l++) {
            int idx = tid + (l << 8);
            int plane = idx >> 9;
            int r = (idx >> 2) & 127;
            int c = idx & 3;
            *(float4*)(sm + plane * 10240 + r * 80 + c * 16) =
                *(const float4*)((plane ? p2L : p2H) + (long)(t * 256 + b0 + r) * 32 + c * 8);
        }
#pragma unroll
        for (int l = 0; l < 4; l++) {
            int idx = tid + (l << 8);
            int plane = idx >> 9;
            int r = (idx >> 2) & 127;
            int c = idx & 3;
            *(float4*)(sm + 20480 + plane * 10240 + r * 80 + c * 16) =
                *(const float4*)((plane ? wL : wH) + (long)(m0 + r) * 10144 + t * 32 + c * 8);
        }
        __syncthreads();
#pragma unroll
        for (int ks = 0; ks < 2; ks++) {
            uint32_t aH[4][4], aL[4][4], bH[4][2], bL[4][2];
#pragma unroll
            for (int pt = 0; pt < 4; pt++) {
                uint32_t o = (uint32_t)((warp_p + (pt << 4) + arow) * 80 + (((ks << 4) + acol) << 1));
                ldm_x4(aH[pt], sb + o);
                ldm_x4(aL[pt], sb + 10240 + o);
            }
#pragma unroll
            for (int nt = 0; nt < 4; nt++) {
                uint32_t o = 20480 + (uint32_t)((warp_m + (nt << 3) + brow) * 80 + (((ks << 4) + bcol) << 1));
                ldm_x2(bH[nt], sb + o);
                ldm_x2(bL[nt], sb + 10240 + o);
            }
#pragma unroll
            for (int pt = 0; pt < 4; pt++)
#pragma unroll
                for (int nt = 0; nt < 4; nt++) {
                    mma16816(acc[pt][nt], aH[pt], bH[nt]);
                    mma16816(acc[pt][nt], aL[pt], bH[nt]);
                    mma16816(acc[pt][nt], aH[pt], bL[nt]);
                }
        }
    }

#pragma unroll
    for (int pt = 0; pt < 4; pt++)
#pragma unroll
        for (int half = 0; half < 2; half++) {
            int b = b0 + warp_p + (pt << 4) + prow + (half << 3);
#pragma unroll
            for (int nt = 0; nt < 4; nt++) {
                int m = m0 + warp_m + (nt << 3) + mcol;
                part[(long)z * 262144 + m * 256 + b] = acc[pt][nt][half * 2];
                part[(long)z * 262144 + (m + 1) * 256 + b] = acc[pt][nt][half * 2 + 1];
            }
        }
}

// ---------------- 64x64 fp32 GEMM with split-K (fc2 only) ----------------
template <class AL, class BL, class EP>
__global__ void __launch_bounds__(256) gemm64_kernel(int totKB, int splitKB, AL al, BL bl, EP ep)
{
    __shared__ float As[32][68];
    __shared__ float Bs[32][68];
    int mBase = blockIdx.y << 6;
    int pBase = blockIdx.x << 6;
    int kb0 = blockIdx.z * splitKB;
    int kb1 = kb0 + splitKB; if (kb1 > totKB) kb1 = totKB;
    int tid = threadIdx.x;
    int tx = tid & 15, ty = tid >> 4;
    float acc[4][4];
#pragma unroll
    for (int i = 0; i < 4; i++)
#pragma unroll
        for (int j = 0; j < 4; j++) acc[i][j] = 0.f;

    for (int kb = kb0; kb < kb1; kb++) {
        int k0 = kb << 5;
#pragma unroll
        for (int i = 0; i < 8; i++) {
            int idx = tid + (i << 8);
            int m = idx >> 5, k = idx & 31;
            As[k][m] = al(mBase + m, k0 + k);
        }
#pragma unroll
        for (int i = 0; i < 8; i++) {
            int idx = tid + (i << 8);
            int k = idx >> 6, p = idx & 63;
            Bs[k][p] = bl(k0 + k, pBase + p);
        }
        __syncthreads();
#pragma unroll
        for (int k = 0; k < 32; k++) {
            float4 a4 = *(const float4*)&As[k][ty << 2];
            float4 b4 = *(const float4*)&Bs[k][tx << 2];
            float a[4] = {a4.x, a4.y, a4.z, a4.w};
            float bb[4] = {b4.x, b4.y, b4.z, b4.w};
#pragma unroll
            for (int i = 0; i < 4; i++)
#pragma unroll
                for (int j = 0; j < 4; j++) acc[i][j] += a[i] * bb[j];
        }
        __syncthreads();
    }
#pragma unroll
    for (int i = 0; i < 4; i++) {
        int m = mBase + (ty << 2) + i;
#pragma unroll
        for (int j = 0; j < 4; j++) {
            int p = pBase + (tx << 2) + j;
            ep.store(m, p, acc[i][j]);
        }
    }
}

struct ALRowG {
    const float* A; int K, M;
    __device__ float operator()(int m, int k) const {
        return (m < M) ? A[m * K + k] : 0.f;
    }
};
struct BLRow {
    const float* B; int N;
    __device__ float operator()(int k, int p) const { return B[k * N + p]; }
};
struct EPPart {
    float* out; int Mstride;
    __device__ void store(int m, int p, float v) const {
        out[blockIdx.z * Mstride + m * 256 + p] = v;
    }
};

// ---------------- split-K reduce + bias + relu ----------------
__global__ void reduce_kernel(const float* __restrict__ part, const float* __restrict__ bias,
                              float* __restrict__ out, int S, int Mstride, int total)
{
    int idx = blockIdx.x * 256 + threadIdx.x;
    if (idx >= total) return;
    int m = idx >> 8;
    float s = 0.f;
    for (int z = 0; z < S; z++) s += part[z * Mstride + idx];
    out[idx] = fmaxf(s + bias[m], 0.f);
}

// ---------------- fc3 + softmax + argmax ----------------
__global__ void fc3_softmax_kernel(const float* __restrict__ F2, const float* __restrict__ W3,
                                   const float* __restrict__ B3, float* __restrict__ out)
{
    int b = threadIdx.x;
    float l0 = B3[0], l1 = B3[1];
    for (int k = 0; k < 256; k++) {
        float v = F2[k * 256 + b];
        l0 += W3[k] * v;
        l1 += W3[256 + k] * v;
    }
    out[2 * b] = l0;
    out[2 * b + 1] = l1;
    float mx = fmaxf(l0, l1);
    float e0 = __expf(l0 - mx), e1 = __expf(l1 - mx);
    float inv = 1.f / (e0 + e1);
    out[512 + 2 * b] = e0 * inv;
    out[512 + 2 * b + 1] = e1 * inv;
    out[1024 + b] = (l1 > l0) ? 1.f : 0.f;
}

// ---------------- host orchestration ----------------
extern "C" void kernel_launch(void* const* d_in, const int* in_sizes, int n_in,
                              void* d_out, int out_size)
{
    const float* x        = (const float*)d_in[0];
    const float* start_w  = (const float*)d_in[1];
    const float* filter_w = (const float*)d_in[2];
    const float* gate_w   = (const float*)d_in[3];
    const float* res_w    = (const float*)d_in[4];
    const float* skip_w   = (const float*)d_in[5];
    const float* end1_w   = (const float*)d_in[6];
    const float* end1_b   = (const float*)d_in[7];
    const float* end2_w   = (const float*)d_in[8];
    const float* end2_b   = (const float*)d_in[9];
    const float* fc_w1    = (const float*)d_in[10];
    const float* fc_b1    = (const float*)d_in[11];
    const float* fc_w2    = (const float*)d_in[12];
    const float* fc_b2    = (const float*)d_in[13];
    const float* fc_w3    = (const float*)d_in[14];
    const float* fc_b3    = (const float*)d_in[15];

    float *r1, *r2, *G, *skipbuf, *y1, *y2, *p2, *f1p, *f1, *f2p, *f2;
    __nv_bfloat16 *wtc, *wl;
    cudaGetSymbolAddress((void**)&r1, g_r1);
    cudaGetSymbolAddress((void**)&r2, g_r2);
    cudaGetSymbolAddress((void**)&G, g_G);
    cudaGetSymbolAddress((void**)&skipbuf, g_skip);
    cudaGetSymbolAddress((void**)&y1, g_y1);
    cudaGetSymbolAddress((void**)&y2, g_y2);
    cudaGetSymbolAddress((void**)&p2, g_p2);
    cudaGetSymbolAddress((void**)&f1p, g_f1p);
    cudaGetSymbolAddress((void**)&f1, g_f1);
    cudaGetSymbolAddress((void**)&f2p, g_f2p);
    cudaGetSymbolAddress((void**)&f2, g_f2);
    cudaGetSymbolAddress((void**)&wtc, g_wtc);
    cudaGetSymbolAddress((void**)&wl, g_wlay);

    __nv_bfloat16* gtH = (__nv_bfloat16*)G;
    __nv_bfloat16* gtL = gtH + (long)NP * 192;
    __nv_bfloat16* wskH = wtc;
    __nv_bfloat16* wskL = wtc + 49152;
    __nv_bfloat16* we1H = wtc + 98304;
    __nv_bfloat16* we1L = wtc + 131072;

    __nv_bfloat16* s1H = (__nv_bfloat16*)r1;
    __nv_bfloat16* s1L = s1H + 10485760;
    __nv_bfloat16* s2H = (__nv_bfloat16*)r2;
    __nv_bfloat16* s2L = s2H + 10485760;

    __nv_bfloat16* y1H = (__nv_bfloat16*)y1;
    __nv_bfloat16* y1L = y1H + (long)NP * 128;
    __nv_bfloat16* y2H = (__nv_bfloat16*)y2;
    __nv_bfloat16* y2L = y2H + (long)162560 * 32;
    __nv_bfloat16* p2H = (__nv_bfloat16*)p2;
    __nv_bfloat16* p2L = p2H + (long)81152 * 32;

    __nv_bfloat16* wf1H = (__nv_bfloat16*)skipbuf;
    __nv_bfloat16* wf1L = wf1H + 10387456;
    __nv_bfloat16* we2H = wf1L + 10387456;
    __nv_bfloat16* we2L = we2H + 4096;

    cudaFuncSetAttribute(layer_mma, cudaFuncAttributeMaxDynamicSharedMemorySize, L_SMEM);
    cudaFuncSetAttribute(mega_gemm, cudaFuncAttributeMaxDynamicSharedMemorySize, MG_SMEM);
    cudaFuncSetAttribute(end2_mma, cudaFuncAttributeMaxDynamicSharedMemorySize, E2_SMEM);

    // x -> xT (fp32, reuse y1 buffer as scratch) -> start conv -> stream planes
    {
        dim3 gx(40, 8, 5);
        xpose_kernel<<<gx, 256>>>(x, y1);
        startflat_kernel<<<40960, 256>>>(y1, start_w, s1H, s1L);
    }
    prepw_kernel<<<320, 256>>>(skip_w, end1_w, wtc);
    prepl_kernel<<<120, 256>>>(filter_w, gate_w, res_w, wl);
    {
        dim3 gp(10, 1024);
        prepfc_kernel<<<gp, 256>>>(fc_w1, wf1H, wf1L);
        prepe2_kernel<<<16, 256>>>(end2_w, we2H, we2L);
    }

    // layers
    const int QQ[6]  = {327424, 327168, 326656, 326400, 326144, 325632};
    const int NR[6]  = {256, 512, 1024, 256, 512, 1024};
    const int SS[6]  = {0, 256, 512, 0, 256, 512};
    const int OFF[6] = {1792, 1536, 1024, 768, 512, 0};

    __nv_bfloat16 *curH = s1H, *curL = s1L, *nxtH = s2H, *nxtL = s2L;
    for (int i = 0; i < 6; i++) {
        int nblk = QQ[i] >> 7;
        layer_mma<<<nblk, 256, L_SMEM>>>(curH, curL, wl + i * 10240,
                                         gtH, gtL, nxtH, nxtL,
                                         NR[i], SS[i], OFF[i], i * 64, (i < 5) ? 1 : 0);
        __nv_bfloat16* t;
        t = curH; curH = nxtH; nxtH = t;
        t = curL; curL = nxtL; nxtL = t;
    }

    // fused skip + end1 -> y1 pairs
    mega_gemm<<<NP / 128, 256, MG_SMEM>>>(gtH, gtL, wskH, wskL, we1H, we1L, end1_b, y1H, y1L);

    // fused pool1 + end2 -> y2 pairs
    end2_mma<<<635, 256, E2_SMEM>>>(y1H, y1L, we2H, we2L, end2_b, y2H, y2L);

    // pool2 -> p2 pairs
    pool2_kernel<<<(81152 * 16 + 255) / 256, 256>>>(y2H, y2L, p2H, p2L);

    // fc1 (mma, split-K=8) -> partials -> reduce(+bias,relu) -> f1 fp32
    {
        dim3 gg(2, 8, 8);
        fc1_mma<<<gg, 256>>>(p2H, p2L, wf1H, wf1L, f1p);
        int total = 1024 * 256;
        reduce_kernel<<<(total + 255) / 256, 256>>>(f1p, fc_b1, f1, 8, total, total);
    }
    // fc2: 256 x 1024 x 256, fp32 split-K=4
    {
        ALRowG al = {fc_w2, 1024, 256};
        BLRow bl = {f1, 256};
        EPPart ep = {f2p, 256 * 256};
        dim3 gg(4, 4, 4);
        gemm64_kernel<<<gg, 256>>>(32, 8, al, bl, ep);
        int total = 256 * 256;
        reduce_kernel<<<(total + 255) / 256, 256>>>(f2p, fc_b2, f2, 4, total, total);
    }
    // fc3 + softmax + argmax
    fc3_softmax_kernel<<<1, 256>>>(f2, fc_w3, fc_b3, (float*)d_out);
}

// round 12
// speedup vs baseline: 6.2469x; 1.0313x over previous
#include <cuda_runtime.h>
#include <cuda_bf16.h>
#include <math.h>
#include <stdint.h>

#define NP 325632   // 1272 * 256 : columns of the big GEMMs, p = t*256 + b

// ---------------- scratch (device globals; no allocation) ----------------
__device__ float g_r1[10485760];     // stream ping: bf16 planes XH/XL [q][32]
__device__ float g_r2[10485760];     // stream pong
__device__ float g_G[62521344];      // bf16 planes: GtH [NP][192], GtL [NP][192]
__device__ float g_skip[83361792];   // reused: wfc1H/L bf16 [1024][10144], we2H/L [32][128]
__device__ float g_y1[41680896];     // bf16 planes y1H/[NP][128], y1L
__device__ float g_y2[5201920];      // bf16 planes y2H/[162560][32], y2L
__device__ float g_p2[2596864];      // bf16 planes p2H/[81152][32], p2L
__device__ float g_f1p[2097152];     // fc1 split-K partials 8 x 1024 x 256
__device__ float g_f1[262144];       // 1024 x 256
__device__ float g_f2p[262144];      // fc2 partials 4 x 256 x 256
__device__ float g_f2[65536];        // 256 x 256
__device__ __nv_bfloat16 g_wtc[163840]; // wskH[49152] wskL[49152] we1H[32768] we1L[32768]
__device__ __nv_bfloat16 g_wlay[61440]; // per-layer: WfgH[4096] WfgL[4096] WrH[1024] WrL[1024]

// ================= mma.sync helpers (sm_80+ portable) =================
__device__ __forceinline__ uint32_t s2u(const void* p) {
    uint32_t a;
    asm("{ .reg .u64 t; cvta.to.shared.u64 t, %1; cvt.u32.u64 %0, t; }" : "=r"(a) : "l"(p));
    return a;
}
__device__ __forceinline__ void ldm_x4(uint32_t* r, uint32_t addr) {
    asm volatile("ldmatrix.sync.aligned.m8n8.x4.shared.b16 {%0,%1,%2,%3}, [%4];"
                 : "=r"(r[0]), "=r"(r[1]), "=r"(r[2]), "=r"(r[3]) : "r"(addr));
}
__device__ __forceinline__ void ldm_x2(uint32_t* r, uint32_t addr) {
    asm volatile("ldmatrix.sync.aligned.m8n8.x2.shared.b16 {%0,%1}, [%2];"
                 : "=r"(r[0]), "=r"(r[1]) : "r"(addr));
}
__device__ __forceinline__ void mma16816(float* c, const uint32_t* a, const uint32_t* b) {
    asm volatile(
        "mma.sync.aligned.m16n8k16.row.col.f32.bf16.bf16.f32 "
        "{%0,%1,%2,%3}, {%4,%5,%6,%7}, {%8,%9}, {%0,%1,%2,%3};"
        : "+f"(c[0]), "+f"(c[1]), "+f"(c[2]), "+f"(c[3])
        : "r"(a[0]), "r"(a[1]), "r"(a[2]), "r"(a[3]), "r"(b[0]), "r"(b[1]));
}
__device__ __forceinline__ uint32_t pk16(__nv_bfloat16 a, __nv_bfloat16 b) {
    __nv_bfloat162 t;
    t.x = a; t.y = b;
    return *reinterpret_cast<uint32_t*>(&t);
}
__device__ __forceinline__ float2 bf2f(uint32_t u) {
    __nv_bfloat162 t = *reinterpret_cast<__nv_bfloat162*>(&u);
    return make_float2(__bfloat162float(t.x), __bfloat162float(t.y));
}
__device__ __forceinline__ void split2(float v0, float v1, uint32_t& h, uint32_t& l) {
    __nv_bfloat16 h0 = __float2bfloat16(v0), h1 = __float2bfloat16(v1);
    h = pk16(h0, h1);
    l = pk16(__float2bfloat16(v0 - __bfloat162float(h0)),
             __float2bfloat16(v1 - __bfloat162float(h1)));
}

// ---------------- fused x-transpose + start conv -> stream planes [q][32] ----------
__global__ void __launch_bounds__(256) start_fused(const float* __restrict__ x,
                                                   const float* __restrict__ w,
                                                   __nv_bfloat16* __restrict__ XH,
                                                   __nv_bfloat16* __restrict__ XL)
{
    __shared__ float xs[5][8][256];
    __shared__ float ws[32][5];
    int tid = threadIdx.x;
    int t0 = blockIdx.x << 3;
    if (tid < 160) ws[tid / 5][tid % 5] = w[tid];
#pragma unroll
    for (int l = 0; l < 40; l++) {
        int idx = tid + (l << 8);       // 10240 floats
        int t = idx & 7;
        int rem = idx >> 3;
        int i = rem % 5;
        int b = rem / 5;
        xs[i][t][b] = x[b * 6400 + i * 1280 + t0 + t];
    }
    __syncthreads();
#pragma unroll
    for (int j = 0; j < 8; j++) {
        float xv[5];
#pragma unroll
        for (int i = 0; i < 5; i++) xv[i] = xs[i][j][tid];
        long q = (long)(t0 + j) * 256 + tid;
        uint32_t hw[16], lw[16];
#pragma unroll
        for (int c2 = 0; c2 < 16; c2++) {
            float a0 = 0.f, a1 = 0.f;
#pragma unroll
            for (int i = 0; i < 5; i++) {
                a0 += ws[2 * c2][i] * xv[i];
                a1 += ws[2 * c2 + 1][i] * xv[i];
            }
            split2(a0, a1, hw[c2], lw[c2]);
        }
#pragma unroll
        for (int u = 0; u < 4; u++) {
            *(float4*)((char*)XH + q * 64 + u * 16) = ((float4*)hw)[u];
            *(float4*)((char*)XL + q * 64 + u * 16) = ((float4*)lw)[u];
        }
    }
}

// ---------------- weight prep for skip/end1 ----------------
__global__ void prepw_kernel(const float* __restrict__ sw, const float* __restrict__ e1,
                             __nv_bfloat16* __restrict__ wt)
{
    int idx = blockIdx.x * 256 + threadIdx.x;
    if (idx < 49152) {
        int m = idx / 192, k = idx - m * 192;
        float v = sw[(k >> 5) * 8192 + m * 32 + (k & 31)];
        __nv_bfloat16 h = __float2bfloat16(v);
        wt[idx] = h;
        wt[49152 + idx] = __float2bfloat16(v - __bfloat162float(h));
    } else if (idx < 81920) {
        int i2 = idx - 49152;
        float v = e1[i2];
        __nv_bfloat16 h = __float2bfloat16(v);
        wt[98304 + i2] = h;
        wt[131072 + i2] = __float2bfloat16(v - __bfloat162float(h));
    }
}

// ---------------- per-layer weight prep: Wfg [64m][64k] + Wr [32][32], hi/lo ---------
__global__ void prepl_kernel(const float* __restrict__ fw, const float* __restrict__ gw,
                             const float* __restrict__ rw, __nv_bfloat16* __restrict__ wl)
{
    int idx = blockIdx.x * 256 + threadIdx.x;
    if (idx < 24576) {
        int lay = idx >> 12;
        int r = idx & 4095;
        int m = r >> 6, k = r & 63;
        const float* src = ((m < 32) ? fw : gw) + lay * 2048 + (m & 31) * 64 + (k & 31) * 2 + (k >> 5);
        float v = *src;
        __nv_bfloat16 h = __float2bfloat16(v);
        wl[lay * 10240 + r] = h;
        wl[lay * 10240 + 4096 + r] = __float2bfloat16(v - __bfloat162float(h));
    } else if (idx < 30720) {
        int j = idx - 24576;
        int lay = j >> 10;
        int r = j & 1023;
        float v = rw[lay * 1024 + r];
        __nv_bfloat16 h = __float2bfloat16(v);
        wl[lay * 10240 + 8192 + r] = h;
        wl[lay * 10240 + 9216 + r] = __float2bfloat16(v - __bfloat162float(h));
    }
}

// ---------------- fc1 weight prep: [m][c*317+t] -> bf16 hi/lo [m][t*32+c] ----------
__global__ void prepfc_kernel(const float* __restrict__ w1,
                              __nv_bfloat16* __restrict__ WH, __nv_bfloat16* __restrict__ WL)
{
    __shared__ float S[32][33];
    int m = blockIdx.y;
    int t0 = blockIdx.x << 5;
    int a = threadIdx.x & 31;
    int b8 = threadIdx.x >> 5;
#pragma unroll
    for (int l = 0; l < 4; l++) {
        int c = b8 + (l << 3);
        int t = t0 + a;
        S[c][a] = (t < 317) ? w1[m * 10144 + c * 317 + t] : 0.f;
    }
    __syncthreads();
#pragma unroll
    for (int l = 0; l < 4; l++) {
        int tt = b8 + (l << 3);
        int t = t0 + tt;
        if (t < 317) {
            float v = S[a][tt];
            __nv_bfloat16 h = __float2bfloat16(v);
            WH[m * 10144 + t * 32 + a] = h;
            WL[m * 10144 + t * 32 + a] = __float2bfloat16(v - __bfloat162float(h));
        }
    }
}

// ---------------- end2 weight prep ----------------
__global__ void prepe2_kernel(const float* __restrict__ e2,
                              __nv_bfloat16* __restrict__ H, __nv_bfloat16* __restrict__ L)
{
    int i = blockIdx.x * 256 + threadIdx.x;
    if (i < 4096) {
        float v = e2[i];
        __nv_bfloat16 h = __float2bfloat16(v);
        H[i] = h;
        L[i] = __float2bfloat16(v - __bfloat162float(h));
    }
}

// ---------------- fused layer via mma.sync ----------------
__device__ __forceinline__ float fast_gate(float f, float g)
{
    float ef = __expf(f + f);
    float th = 1.f - __fdividef(2.f, ef + 1.f);
    float sg = __fdividef(1.f, 1.f + __expf(-g));
    return th * sg;
}

// compact smem layout; R overlays W + part of WR (both dead after stage-2 MMA + sync)
// X: 0..36864, W: 36864..55296, WR: 55296..60416, H: 60416..80896, R overlay: 36864..57344
#define L_OFF_X  0
#define L_XPL    18432
#define L_OFF_W  36864
#define L_WPL    9216
#define L_OFF_WR 55296
#define L_WRPL   2560
#define L_OFF_H  60416
#define L_HPL    10240
#define L_OFF_R  36864          // overlay on W/WR (dead after stage-2 sync)
#define L_RPL    10240
#define L_SMEM   80896          // 2 CTAs/SM (161792 < 228KB)

__global__ void __launch_bounds__(256, 2) layer_mma(
    const __nv_bfloat16* __restrict__ XH, const __nv_bfloat16* __restrict__ XL,
    const __nv_bfloat16* __restrict__ wlay,
    __nv_bfloat16* __restrict__ gtH, __nv_bfloat16* __restrict__ gtL,
    __nv_bfloat16* __restrict__ RoutH, __nv_bfloat16* __restrict__ RoutL,
    int nr, int s, int off, int lay64, int writeRes)
{
    extern __shared__ char sm[];
    uint32_t sb = s2u(sm);
    int tid = threadIdx.x;
    int q0 = blockIdx.x << 7;

#pragma unroll
    for (int l = 0; l < 8; l++) {
        int idx = tid + (l << 8);
        int plane = idx >> 10;
        int r = (idx >> 3) & 127;
        int seg = idx & 7;
        int tap = seg >> 2;
        int qa = q0 + r - s + (tap ? nr : 0);
        char* dst = sm + L_OFF_X + plane * L_XPL + r * 144 + seg * 16;
        if (!tap && qa < 0) {
            *(float4*)dst = make_float4(0.f, 0.f, 0.f, 0.f);
        } else {
            const __nv_bfloat16* src = (plane ? XL : XH) + (long)qa * 32 + ((seg & 3) << 3);
            *(float4*)dst = *(const float4*)src;
        }
    }
#pragma unroll
    for (int l = 0; l < 4; l++) {
        int idx = tid + (l << 8);
        int plane = idx >> 9;
        int r = (idx >> 3) & 63;
        int cc = idx & 7;
        *(float4*)(sm + L_OFF_W + plane * L_WPL + r * 144 + cc * 16) =
            *(const float4*)(wlay + plane * 4096 + r * 64 + cc * 8);
    }
    {
        int idx = tid;
        int plane = idx >> 7;
        int r = (idx >> 2) & 31;
        int cc = idx & 3;
        *(float4*)(sm + L_OFF_WR + plane * L_WRPL + r * 80 + cc * 16) =
            *(const float4*)(wlay + 8192 + plane * 1024 + r * 32 + cc * 8);
    }
    __syncthreads();

    int warp = tid >> 5, lane = tid & 31;
    int warp_q = (warp & 3) << 5;
    int g = warp >> 2;
    int arow = lane & 15, acol = (lane >> 4) << 3;
    int brow = lane & 7, bcol = ((lane >> 3) & 1) << 3;

    float acc[2][4][4];
#pragma unroll
    for (int pt = 0; pt < 2; pt++)
#pragma unroll
        for (int nt = 0; nt < 4; nt++)
#pragma unroll
            for (int j = 0; j < 4; j++) acc[pt][nt][j] = 0.f;

#pragma unroll
    for (int kc = 0; kc < 4; kc++) {
        uint32_t aH[2][4], aL[2][4], bH[4][2], bL[4][2];
#pragma unroll
        for (int pt = 0; pt < 2; pt++) {
            uint32_t o = L_OFF_X + (uint32_t)((warp_q + (pt << 4) + arow) * 144 + (((kc << 4) + acol) << 1));
            ldm_x4(aH[pt], sb + o);
            ldm_x4(aL[pt], sb + L_XPL + o);
        }
#pragma unroll
        for (int nt = 0; nt < 4; nt++) {
            int msm = (nt < 2) ? (g * 16 + nt * 8) : (32 + g * 16 + (nt - 2) * 8);
            uint32_t o = L_OFF_W + (uint32_t)((msm + brow) * 144 + (((kc << 4) + bcol) << 1));
            ldm_x2(bH[nt], sb + o);
            ldm_x2(bL[nt], sb + L_WPL + o);
        }
#pragma unroll
        for (int pt = 0; pt < 2; pt++)
#pragma unroll
            for (int nt = 0; nt < 4; nt++) {
                mma16816(acc[pt][nt], aH[pt], bH[nt]);
                mma16816(acc[pt][nt], aL[pt], bH[nt]);
                mma16816(acc[pt][nt], aH[pt], bL[nt]);
            }
    }

#pragma unroll
    for (int pt = 0; pt < 2; pt++)
#pragma unroll
        for (int nt = 0; nt < 2; nt++)
#pragma unroll
            for (int jh = 0; jh < 2; jh++) {
                float F0 = acc[pt][nt][jh * 2], F1 = acc[pt][nt][jh * 2 + 1];
                float G0 = acc[pt][nt + 2][jh * 2], G1 = acc[pt][nt + 2][jh * 2 + 1];
                float h0 = fast_gate(F0, G0);
                float h1 = fast_gate(F1, G1);
                int q = warp_q + (pt << 4) + (lane >> 2) + (jh << 3);
                int c0 = g * 16 + nt * 8 + ((lane & 3) << 1);
                uint32_t hw, lw;
                split2(h0, h1, hw, lw);
                *(uint32_t*)(sm + L_OFF_H + q * 80 + c0 * 2) = hw;
                *(uint32_t*)(sm + L_OFF_H + L_HPL + q * 80 + c0 * 2) = lw;
            }
    __syncthreads();

#pragma unroll
    for (int l = 0; l < 4; l++) {
        int idx = tid + (l << 8);
        int plane = idx >> 9;
        int r = (idx >> 2) & 127;
        int cc = idx & 3;
        int pg = q0 + r - off;
        if (pg >= 0) {
            float4 v = *(float4*)(sm + L_OFF_H + plane * L_HPL + r * 80 + cc * 16);
            char* d = (char*)(plane ? gtL : gtH) + (long)pg * 384 + lay64 + cc * 16;
            *(float4*)d = v;
        }
    }

    if (writeRes) {
        float acc2[2][2][4];
#pragma unroll
        for (int pt = 0; pt < 2; pt++)
#pragma unroll
            for (int nt = 0; nt < 2; nt++)
#pragma unroll
                for (int j = 0; j < 4; j++) acc2[pt][nt][j] = 0.f;

#pragma unroll
        for (int kc = 0; kc < 2; kc++) {
            uint32_t aH[2][4], aL[2][4], bH[2][2], bL[2][2];
#pragma unroll
            for (int pt = 0; pt < 2; pt++) {
                uint32_t o = L_OFF_H + (uint32_t)((warp_q + (pt << 4) + arow) * 80 + (((kc << 4) + acol) << 1));
                ldm_x4(aH[pt], sb + o);
                ldm_x4(aL[pt], sb + L_HPL + o);
            }
#pragma unroll
            for (int nt = 0; nt < 2; nt++) {
                uint32_t o = L_OFF_WR + (uint32_t)((g * 16 + nt * 8 + brow) * 80 + (((kc << 4) + bcol) << 1));
                ldm_x2(bH[nt], sb + o);
                ldm_x2(bL[nt], sb + L_WRPL + o);
            }
#pragma unroll
            for (int pt = 0; pt < 2; pt++)
#pragma unroll
                for (int nt = 0; nt < 2; nt++) {
                    mma16816(acc2[pt][nt], aH[pt], bH[nt]);
                    mma16816(acc2[pt][nt], aL[pt], bH[nt]);
                    mma16816(acc2[pt][nt], aH[pt], bL[nt]);
                }
        }
        __syncthreads();   // all W/WR reads complete before R overlays them

#pragma unroll
        for (int pt = 0; pt < 2; pt++)
#pragma unroll
            for (int nt = 0; nt < 2; nt++)
#pragma unroll
                for (int jh = 0; jh < 2; jh++) {
                    int q = warp_q + (pt << 4) + (lane >> 2) + (jh << 3);
                    int c0 = g * 16 + nt * 8 + ((lane & 3) << 1);
                    const __nv_bfloat16* xh = (const __nv_bfloat16*)(sm + L_OFF_X + q * 144 + (32 + c0) * 2);
                    const __nv_bfloat16* xl = (const __nv_bfloat16*)(sm + L_OFF_X + L_XPL + q * 144 + (32 + c0) * 2);
                    float xb0 = __bfloat162float(xh[0]) + __bfloat162float(xl[0]);
                    float xb1 = __bfloat162float(xh[1]) + __bfloat162float(xl[1]);
                    float v0 = acc2[pt][nt][jh * 2] + xb0;
                    float v1 = acc2[pt][nt][jh * 2 + 1] + xb1;
                    uint32_t hw, lw;
                    split2(v0, v1, hw, lw);
                    *(uint32_t*)(sm + L_OFF_R + q * 80 + c0 * 2) = hw;
                    *(uint32_t*)(sm + L_OFF_R + L_RPL + q * 80 + c0 * 2) = lw;
                }
        __syncthreads();

#pragma unroll
        for (int l = 0; l < 4; l++) {
            int idx = tid + (l << 8);
            int plane = idx >> 9;
            int r = (idx >> 2) & 127;
            int cc = idx & 3;
            float4 v = *(float4*)(sm + L_OFF_R + plane * L_RPL + r * 80 + cc * 16);
            __nv_bfloat16* d = (plane ? RoutL : RoutH) + (long)(q0 + r) * 32 + cc * 8;
            *(float4*)d = v;
        }
    }
}

// ---------------- fused skip+end1 megakernel ----------------
#define MG_OFF_SB 0
#define MG_SBPL   10240
#define MG_OFF_SW 20480
#define MG_SWPL   20480
#define MG_OFF_S  61440
#define MG_SPL    67584
#define MG_SMEM   196608

__global__ void __launch_bounds__(256, 1) mega_gemm(
    const __nv_bfloat16* __restrict__ gtH, const __nv_bfloat16* __restrict__ gtL,
    const __nv_bfloat16* __restrict__ wskH, const __nv_bfloat16* __restrict__ wskL,
    const __nv_bfloat16* __restrict__ we1H, const __nv_bfloat16* __restrict__ we1L,
    const float* __restrict__ bias,
    __nv_bfloat16* __restrict__ y1H, __nv_bfloat16* __restrict__ y1L)
{
    extern __shared__ char sm[];
    uint32_t sb = s2u(sm);
    int tid = threadIdx.x;
    int warp = tid >> 5, lane = tid & 31;
    int p0 = blockIdx.x << 7;
    int warp_p = (warp & 1) << 6;
    int warp_mA = (warp >> 1) << 6;
    int warp_mB = (warp >> 1) << 5;
    int arow = lane & 15, acol = (lane >> 4) << 3;
    int brow = lane & 7, bcol = ((lane >> 3) & 1) << 3;
    int prow = lane >> 2, mcol = (lane & 3) << 1;

    // ---- stage A ----
    float acc[4][8][4];
#pragma unroll
    for (int pt = 0; pt < 4; pt++)
#pragma unroll
        for (int nt = 0; nt < 8; nt++)
#pragma unroll
            for (int j = 0; j < 4; j++) acc[pt][nt][j] = 0.f;

    for (int kc = 0; kc < 6; kc++) {
        __syncthreads();
#pragma unroll
        for (int l = 0; l < 4; l++) {
            int idx = tid + (l << 8);
            int plane = idx >> 9;
            int r = (idx >> 2) & 127;
            int c = idx & 3;
            *(float4*)(sm + MG_OFF_SB + plane * MG_SBPL + r * 80 + c * 16) =
                *(const float4*)((plane ? gtL : gtH) + (long)(p0 + r) * 192 + kc * 32 + c * 8);
        }
#pragma unroll
        for (int l = 0; l < 8; l++) {
            int idx = tid + (l << 8);
            int plane = idx >> 10;
            int r = (idx >> 2) & 255;
            int c = idx & 3;
            *(float4*)(sm + MG_OFF_SW + plane * MG_SWPL + r * 80 + c * 16) =
                *(const float4*)((plane ? wskL : wskH) + (long)r * 192 + kc * 32 + c * 8);
        }
        __syncthreads();
#pragma unroll
        for (int ks = 0; ks < 2; ks++) {
            uint32_t aH[4][4], aL[4][4], bH[8][2], bL[8][2];
#pragma unroll
            for (int pt = 0; pt < 4; pt++) {
                uint32_t o = MG_OFF_SB + (uint32_t)((warp_p + (pt << 4) + arow) * 80 + (((ks << 4) + acol) << 1));
                ldm_x4(aH[pt], sb + o);
                ldm_x4(aL[pt], sb + MG_SBPL + o);
            }
#pragma unroll
            for (int nt = 0; nt < 8; nt++) {
                uint32_t o = MG_OFF_SW + (uint32_t)((warp_mA + (nt << 3) + brow) * 80 + (((ks << 4) + bcol) << 1));
                ldm_x2(bH[nt], sb + o);
                ldm_x2(bL[nt], sb + MG_SWPL + o);
            }
#pragma unroll
            for (int pt = 0; pt < 4; pt++)
#pragma unroll
                for (int nt = 0; nt < 8; nt++) {
                    mma16816(acc[pt][nt], aH[pt], bH[nt]);
                    mma16816(acc[pt][nt], aL[pt], bH[nt]);
                    mma16816(acc[pt][nt], aH[pt], bL[nt]);
                }
        }
    }

    // epilogue A: relu + split -> S smem
#pragma unroll
    for (int pt = 0; pt < 4; pt++)
#pragma unroll
        for (int half = 0; half < 2; half++) {
            int pl = warp_p + (pt << 4) + prow + (half << 3);
#pragma unroll
            for (int nt = 0; nt < 8; nt++) {
                float v0 = fmaxf(acc[pt][nt][half * 2], 0.f);
                float v1 = fmaxf(acc[pt][nt][half * 2 + 1], 0.f);
                int m = warp_mA + (nt << 3) + mcol;
                uint32_t hw, lw;
                split2(v0, v1, hw, lw);
                *(uint32_t*)(sm + MG_OFF_S + pl * 528 + m * 2) = hw;
                *(uint32_t*)(sm + MG_OFF_S + MG_SPL + pl * 528 + m * 2) = lw;
            }
        }
    __syncthreads();

    // ---- stage B (64 K-columns of we1 per chunk, pitch 160) ----
    float acc2[4][4][4];
#pragma unroll
    for (int pt = 0; pt < 4; pt++)
#pragma unroll
        for (int nt = 0; nt < 4; nt++)
#pragma unroll
            for (int j = 0; j < 4; j++) acc2[pt][nt][j] = 0.f;

    for (int kc2 = 0; kc2 < 4; kc2++) {
        __syncthreads();
#pragma unroll
        for (int l = 0; l < 8; l++) {
            int idx = tid + (l << 8);      // 2048 chunks: 2 planes x 128 rows x 8 chunks
            int plane = idx >> 10;
            int r = (idx >> 3) & 127;
            int c = idx & 7;
            *(float4*)(sm + MG_OFF_SW + plane * MG_SWPL + r * 160 + c * 16) =
                *(const float4*)((plane ? we1L : we1H) + (long)r * 256 + kc2 * 64 + c * 8);
        }
        __syncthreads();
#pragma unroll
        for (int ks = 0; ks < 4; ks++) {
            uint32_t aH[4][4], aL[4][4], bH[4][2], bL[4][2];
#pragma unroll
            for (int pt = 0; pt < 4; pt++) {
                uint32_t o = MG_OFF_S + (uint32_t)((warp_p + (pt << 4) + arow) * 528 + (((kc2 << 6) + (ks << 4) + acol) << 1));
                ldm_x4(aH[pt], sb + o);
                ldm_x4(aL[pt], sb + MG_SPL + o);
            }
#pragma unroll
            for (int nt = 0; nt < 4; nt++) {
                uint32_t o = MG_OFF_SW + (uint32_t)((warp_mB + (nt << 3) + brow) * 160 + (((ks << 4) + bcol) << 1));
                ldm_x2(bH[nt], sb + o);
                ldm_x2(bL[nt], sb + MG_SWPL + o);
            }
#pragma unroll
            for (int pt = 0; pt < 4; pt++)
#pragma unroll
                for (int nt = 0; nt < 4; nt++) {
                    mma16816(acc2[pt][nt], aH[pt], bH[nt]);
                    mma16816(acc2[pt][nt], aL[pt], bH[nt]);
                    mma16816(acc2[pt][nt], aH[pt], bL[nt]);
                }
        }
    }

    // epilogue B: +bias, relu, split -> y1 pairs
#pragma unroll
    for (int pt = 0; pt < 4; pt++)
#pragma unroll
        for (int half = 0; half < 2; half++) {
            int p = p0 + warp_p + (pt << 4) + prow + (half << 3);
#pragma unroll
            for (int nt = 0; nt < 4; nt++) {
                int m = warp_mB + (nt << 3) + mcol;
                float v0 = fmaxf(acc2[pt][nt][half * 2] + __ldg(&bias[m]), 0.f);
                float v1 = fmaxf(acc2[pt][nt][half * 2 + 1] + __ldg(&bias[m + 1]), 0.f);
                uint32_t hw, lw;
                split2(v0, v1, hw, lw);
                *(uint32_t*)((char*)y1H + (long)p * 256 + m * 2) = hw;
                *(uint32_t*)((char*)y1L + (long)p * 256 + m * 2) = lw;
            }
        }
}

// ---------------- fused pool1 + end2 (mma) ----------------
#define E2_OFF_A 0
#define E2_APL   69632
#define E2_OFF_W 139264
#define E2_WPL   8704
#define E2_SMEM  156672

__global__ void __launch_bounds__(256, 1) end2_mma(
    const __nv_bfloat16* __restrict__ y1H, const __nv_bfloat16* __restrict__ y1L,
    const __nv_bfloat16* __restrict__ we2H, const __nv_bfloat16* __restrict__ we2L,
    const float* __restrict__ bias,
    __nv_bfloat16* __restrict__ y2H, __nv_bfloat16* __restrict__ y2L)
{
    extern __shared__ char sm[];
    uint32_t sb = s2u(sm);
    int tid = threadIdx.x;
    int tq = blockIdx.x;

#pragma unroll
    for (int l = 0; l < 16; l++) {
        int idx = tid + (l << 8);
        int r = idx >> 4, c8 = idx & 15;
        long e = ((long)(2 * tq) * 256 + r) * 128 + (c8 << 3);
        float4 h0 = *(const float4*)(y1H + e);
        float4 h1 = *(const float4*)(y1H + e + 32768);
        float4 h2 = *(const float4*)(y1H + e + 65536);
        float4 l0 = *(const float4*)(y1L + e);
        float4 l1 = *(const float4*)(y1L + e + 32768);
        float4 l2 = *(const float4*)(y1L + e + 65536);
        uint32_t oh[4], ol[4];
#pragma unroll
        for (int w = 0; w < 4; w++) {
            float2 a0 = bf2f(((uint32_t*)&h0)[w]);
            float2 b0 = bf2f(((uint32_t*)&l0)[w]);
            float2 a1 = bf2f(((uint32_t*)&h1)[w]);
            float2 b1 = bf2f(((uint32_t*)&l1)[w]);
            float2 a2 = bf2f(((uint32_t*)&h2)[w]);
            float2 b2 = bf2f(((uint32_t*)&l2)[w]);
            float vx = fmaxf(fmaxf(a0.x + b0.x, a1.x + b1.x), a2.x + b2.x);
            float vy = fmaxf(fmaxf(a0.y + b0.y, a1.y + b1.y), a2.y + b2.y);
            split2(vx, vy, oh[w], ol[w]);
        }
        *(float4*)(sm + E2_OFF_A + r * 272 + c8 * 16) = *(float4*)oh;
        *(float4*)(sm + E2_OFF_A + E2_APL + r * 272 + c8 * 16) = *(float4*)ol;
    }
#pragma unroll
    for (int l = 0; l < 4; l++) {
        int idx = tid + (l << 8);
        int plane = idx >> 9;
        int r = (idx >> 4) & 31;
        int c = idx & 15;
        *(float4*)(sm + E2_OFF_W + plane * E2_WPL + r * 272 + c * 16) =
            *(const float4*)((plane ? we2L : we2H) + r * 128 + c * 8);
    }
    __syncthreads();

    int warp = tid >> 5, lane = tid & 31;
    int warp_p = warp << 5;
    int arow = lane & 15, acol = (lane >> 4) << 3;
    int brow = lane & 7, bcol = ((lane >> 3) & 1) << 3;
    int prow = lane >> 2, mcol = (lane & 3) << 1;

    float acc[2][4][4];
#pragma unroll
    for (int pt = 0; pt < 2; pt++)
#pragma unroll
        for (int nt = 0; nt < 4; nt++)
#pragma unroll
            for (int j = 0; j < 4; j++) acc[pt][nt][j] = 0.f;

#pragma unroll
    for (int ks = 0; ks < 8; ks++) {
        uint32_t aH[2][4], aL[2][4], bH[4][2], bL[4][2];
#pragma unroll
        for (int pt = 0; pt < 2; pt++) {
            uint32_t o = E2_OFF_A + (uint32_t)((warp_p + (pt << 4) + arow) * 272 + (((ks << 4) + acol) << 1));
            ldm_x4(aH[pt], sb + o);
            ldm_x4(aL[pt], sb + E2_APL + o);
        }
#pragma unroll
        for (int nt = 0; nt < 4; nt++) {
            uint32_t o = E2_OFF_W + (uint32_t)(((nt << 3) + brow) * 272 + (((ks << 4) + bcol) << 1));
            ldm_x2(bH[nt], sb + o);
            ldm_x2(bL[nt], sb + E2_WPL + o);
        }
#pragma unroll
        for (int pt = 0; pt < 2; pt++)
#pragma unroll
            for (int nt = 0; nt < 4; nt++) {
                mma16816(acc[pt][nt], aH[pt], bH[nt]);
                mma16816(acc[pt][nt], aL[pt], bH[nt]);
                mma16816(acc[pt][nt], aH[pt], bL[nt]);
            }
    }

#pragma unroll
    for (int pt = 0; pt < 2; pt++)
#pragma unroll
        for (int half = 0; half < 2; half++) {
            long pp = (long)tq * 256 + warp_p + (pt << 4) + prow + (half << 3);
#pragma unroll
            for (int nt = 0; nt < 4; nt++) {
                int m = (nt << 3) + mcol;
                float v0 = fmaxf(acc[pt][nt][half * 2] + __ldg(&bias[m]), 0.f);
                float v1 = fmaxf(acc[pt][nt][half * 2 + 1] + __ldg(&bias[m + 1]), 0.f);
                uint32_t hw, lw;
                split2(v0, v1, hw, lw);
                *(uint32_t*)((char*)y2H + pp * 64 + m * 2) = hw;
                *(uint32_t*)((char*)y2L + pp * 64 + m * 2) = lw;
            }
        }
}

// ---------------- pool2 on bf16 pairs ----------------
__global__ void pool2_kernel(const __nv_bfloat16* __restrict__ y2H, const __nv_bfloat16* __restrict__ y2L,
                             __nv_bfloat16* __restrict__ p2H, __nv_bfloat16* __restrict__ p2L)
{
    int idx = blockIdx.x * 256 + threadIdx.x;
    if (idx >= 81152 * 16) return;
    int u = idx & 15;
    int ppp = idx >> 4;
    int b = ppp & 255, tq = ppp >> 8;
    const uint32_t* H = (const uint32_t*)y2H;
    const uint32_t* L = (const uint32_t*)y2L;
    long r0 = ((long)(2 * tq) * 256 + b) * 16 + u;
    float2 a0 = bf2f(H[r0]),        b0 = bf2f(L[r0]);
    float2 a1 = bf2f(H[r0 + 4096]), b1 = bf2f(L[r0 + 4096]);
    float2 a2 = bf2f(H[r0 + 8192]), b2 = bf2f(L[r0 + 8192]);
    float vx = fmaxf(fmaxf(a0.x + b0.x, a1.x + b1.x), a2.x + b2.x);
    float vy = fmaxf(fmaxf(a0.y + b0.y, a1.y + b1.y), a2.y + b2.y);
    uint32_t hw, lw;
    split2(vx, vy, hw, lw);
    ((uint32_t*)p2H)[(long)ppp * 16 + u] = hw;
    ((uint32_t*)p2L)[(long)ppp * 16 + u] = lw;
}

// ---------------- fc1 via mma: D[256b][1024m], K'=t*32+c, split-K=8 ----------------
__global__ void __launch_bounds__(256, 1) fc1_mma(
    const __nv_bfloat16* __restrict__ p2H, const __nv_bfloat16* __restrict__ p2L,
    const __nv_bfloat16* __restrict__ wH, const __nv_bfloat16* __restrict__ wL,
    float* __restrict__ part)
{
    __shared__ __align__(16) char sm[40960];
    uint32_t sb = s2u(sm);
    int tid = threadIdx.x;
    int b0 = blockIdx.x << 7, m0 = blockIdx.y << 7, z = blockIdx.z;
    int t1 = z * 40 + 40; if (t1 > 317) t1 = 317;

    int warp = tid >> 5, lane = tid & 31;
    int warp_p = (warp & 1) << 6;
    int warp_m = (warp >> 1) << 5;
    int arow = lane & 15, acol = (lane >> 4) << 3;
    int brow = lane & 7, bcol = ((lane >> 3) & 1) << 3;
    int prow = lane >> 2, mcol = (lane & 3) << 1;

    float acc[4][4][4];
#pragma unroll
    for (int pt = 0; pt < 4; pt++)
#pragma unroll
        for (int nt = 0; nt < 4; nt++)
#pragma unroll
            for (int j = 0; j < 4; j++) acc[pt][nt][j] = 0.f;

    for (int t = z * 40; t < t1; t++) {
        __syncthreads();
#pragma unroll
        for (int l = 0; l < 4; l++) {
            int idx = tid + (l << 8);
            int plane = idx >> 9;
            int r = (idx >> 2) & 127;
            int c = idx & 3;
            *(float4*)(sm + plane * 10240 + r * 80 + c * 16) =
                *(const float4*)((plane ? p2L : p2H) + (long)(t * 256 + b0 + r) * 32 + c * 8);
        }
#pragma unroll
        for (int l = 0; l < 4; l++) {
            int idx = tid + (l << 8);
            int plane = idx >> 9;
            int r = (idx >> 2) & 127;
            int c = idx & 3;
            *(float4*)(sm + 20480 + plane * 10240 + r * 80 + c * 16) =
                *(const float4*)((plane ? wL : wH) + (long)(m0 + r) * 10144 + t * 32 + c * 8);
        }
        __syncthreads();
#pragma unroll
        for (int ks = 0; ks < 2; ks++) {
            uint32_t aH[4][4], aL[4][4], bH[4][2], bL[4][2];
#pragma unroll
            for (int pt = 0; pt < 4; pt++) {
                uint32_t o = (uint32_t)((warp_p + (pt << 4) + arow) * 80 + (((ks << 4) + acol) << 1));
                ldm_x4(aH[pt], sb + o);
                ldm_x4(aL[pt], sb + 10240 + o);
            }
#pragma unroll
            for (int nt = 0; nt < 4; nt++) {
                uint32_t o = 20480 + (uint32_t)((warp_m + (nt << 3) + brow) * 80 + (((ks << 4) + bcol) << 1));
                ldm_x2(bH[nt], sb + o);
                ldm_x2(bL[nt], sb + 10240 + o);
            }
#pragma unroll
            for (int pt = 0; pt < 4; pt++)
#pragma unroll
                for (int nt = 0; nt < 4; nt++) {
                    mma16816(acc[pt][nt], aH[pt], bH[nt]);
                    mma16816(acc[pt][nt], aL[pt], bH[nt]);
                    mma16816(acc[pt][nt], aH[pt], bL[nt]);
                }
        }
    }

#pragma unroll
    for (int pt = 0; pt < 4; pt++)
#pragma unroll
        for (int half = 0; half < 2; half++) {
            int b = b0 + warp_p + (pt << 4) + prow + (half << 3);
#pragma unroll
            for (int nt = 0; nt < 4; nt++) {
                int m = m0 + warp_m + (nt << 3) + mcol;
                part[(long)z * 262144 + m * 256 + b] = acc[pt][nt][half * 2];
                part[(long)z * 262144 + (m + 1) * 256 + b] = acc[pt][nt][half * 2 + 1];
            }
        }
}

// ---------------- 64x64 fp32 GEMM with split-K (fc2 only) ----------------
template <class AL, class BL, class EP>
__global__ void __launch_bounds__(256) gemm64_kernel(int totKB, int splitKB, AL al, BL bl, EP ep)
{
    __shared__ float As[32][68];
    __shared__ float Bs[32][68];
    int mBase = blockIdx.y << 6;
    int pBase = blockIdx.x << 6;
    int kb0 = blockIdx.z * splitKB;
    int kb1 = kb0 + splitKB; if (kb1 > totKB) kb1 = totKB;
    int tid = threadIdx.x;
    int tx = tid & 15, ty = tid >> 4;
    float acc[4][4];
#pragma unroll
    for (int i = 0; i < 4; i++)
#pragma unroll
        for (int j = 0; j < 4; j++) acc[i][j] = 0.f;

    for (int kb = kb0; kb < kb1; kb++) {
        int k0 = kb << 5;
#pragma unroll
        for (int i = 0; i < 8; i++) {
            int idx = tid + (i << 8);
            int m = idx >> 5, k = idx & 31;
            As[k][m] = al(mBase + m, k0 + k);
        }
#pragma unroll
        for (int i = 0; i < 8; i++) {
            int idx = tid + (i << 8);
            int k = idx >> 6, p = idx & 63;
            Bs[k][p] = bl(k0 + k, pBase + p);
        }
        __syncthreads();
#pragma unroll
        for (int k = 0; k < 32; k++) {
            float4 a4 = *(const float4*)&As[k][ty << 2];
            float4 b4 = *(const float4*)&Bs[k][tx << 2];
            float a[4] = {a4.x, a4.y, a4.z, a4.w};
            float bb[4] = {b4.x, b4.y, b4.z, b4.w};
#pragma unroll
            for (int i = 0; i < 4; i++)
#pragma unroll
                for (int j = 0; j < 4; j++) acc[i][j] += a[i] * bb[j];
        }
        __syncthreads();
    }
#pragma unroll
    for (int i = 0; i < 4; i++) {
        int m = mBase + (ty << 2) + i;
#pragma unroll
        for (int j = 0; j < 4; j++) {
            int p = pBase + (tx << 2) + j;
            ep.store(m, p, acc[i][j]);
        }
    }
}

struct ALRowG {
    const float* A; int K, M;
    __device__ float operator()(int m, int k) const {
        return (m < M) ? A[m * K + k] : 0.f;
    }
};
struct BLRow {
    const float* B; int N;
    __device__ float operator()(int k, int p) const { return B[k * N + p]; }
};
struct EPPart {
    float* out; int Mstride;
    __device__ void store(int m, int p, float v) const {
        out[blockIdx.z * Mstride + m * 256 + p] = v;
    }
};

// ---------------- split-K reduce + bias + relu ----------------
__global__ void reduce_kernel(const float* __restrict__ part, const float* __restrict__ bias,
                              float* __restrict__ out, int S, int Mstride, int total)
{
    int idx = blockIdx.x * 256 + threadIdx.x;
    if (idx >= total) return;
    int m = idx >> 8;
    float s = 0.f;
    for (int z = 0; z < S; z++) s += part[z * Mstride + idx];
    out[idx] = fmaxf(s + bias[m], 0.f);
}

// ---------------- fc3 + softmax + argmax ----------------
__global__ void fc3_softmax_kernel(const float* __restrict__ F2, const float* __restrict__ W3,
                                   const float* __restrict__ B3, float* __restrict__ out)
{
    int b = threadIdx.x;
    float l0 = B3[0], l1 = B3[1];
    for (int k = 0; k < 256; k++) {
        float v = F2[k * 256 + b];
        l0 += W3[k] * v;
        l1 += W3[256 + k] * v;
    }
    out[2 * b] = l0;
    out[2 * b + 1] = l1;
    float mx = fmaxf(l0, l1);
    float e0 = __expf(l0 - mx), e1 = __expf(l1 - mx);
    float inv = 1.f / (e0 + e1);
    out[512 + 2 * b] = e0 * inv;
    out[512 + 2 * b + 1] = e1 * inv;
    out[1024 + b] = (l1 > l0) ? 1.f : 0.f;
}

// ---------------- host orchestration ----------------
extern "C" void kernel_launch(void* const* d_in, const int* in_sizes, int n_in,
                              void* d_out, int out_size)
{
    const float* x        = (const float*)d_in[0];
    const float* start_w  = (const float*)d_in[1];
    const float* filter_w = (const float*)d_in[2];
    const float* gate_w   = (const float*)d_in[3];
    const float* res_w    = (const float*)d_in[4];
    const float* skip_w   = (const float*)d_in[5];
    const float* end1_w   = (const float*)d_in[6];
    const float* end1_b   = (const float*)d_in[7];
    const float* end2_w   = (const float*)d_in[8];
    const float* end2_b   = (const float*)d_in[9];
    const float* fc_w1    = (const float*)d_in[10];
    const float* fc_b1    = (const float*)d_in[11];
    const float* fc_w2    = (const float*)d_in[12];
    const float* fc_b2    = (const float*)d_in[13];
    const float* fc_w3    = (const float*)d_in[14];
    const float* fc_b3    = (const float*)d_in[15];

    float *r1, *r2, *G, *skipbuf, *y1, *y2, *p2, *f1p, *f1, *f2p, *f2;
    __nv_bfloat16 *wtc, *wl;
    cudaGetSymbolAddress((void**)&r1, g_r1);
    cudaGetSymbolAddress((void**)&r2, g_r2);
    cudaGetSymbolAddress((void**)&G, g_G);
    cudaGetSymbolAddress((void**)&skipbuf, g_skip);
    cudaGetSymbolAddress((void**)&y1, g_y1);
    cudaGetSymbolAddress((void**)&y2, g_y2);
    cudaGetSymbolAddress((void**)&p2, g_p2);
    cudaGetSymbolAddress((void**)&f1p, g_f1p);
    cudaGetSymbolAddress((void**)&f1, g_f1);
    cudaGetSymbolAddress((void**)&f2p, g_f2p);
    cudaGetSymbolAddress((void**)&f2, g_f2);
    cudaGetSymbolAddress((void**)&wtc, g_wtc);
    cudaGetSymbolAddress((void**)&wl, g_wlay);

    __nv_bfloat16* gtH = (__nv_bfloat16*)G;
    __nv_bfloat16* gtL = gtH + (long)NP * 192;
    __nv_bfloat16* wskH = wtc;
    __nv_bfloat16* wskL = wtc + 49152;
    __nv_bfloat16* we1H = wtc + 98304;
    __nv_bfloat16* we1L = wtc + 131072;

    __nv_bfloat16* s1H = (__nv_bfloat16*)r1;
    __nv_bfloat16* s1L = s1H + 10485760;
    __nv_bfloat16* s2H = (__nv_bfloat16*)r2;
    __nv_bfloat16* s2L = s2H + 10485760;

    __nv_bfloat16* y1H = (__nv_bfloat16*)y1;
    __nv_bfloat16* y1L = y1H + (long)NP * 128;
    __nv_bfloat16* y2H = (__nv_bfloat16*)y2;
    __nv_bfloat16* y2L = y2H + (long)162560 * 32;
    __nv_bfloat16* p2H = (__nv_bfloat16*)p2;
    __nv_bfloat16* p2L = p2H + (long)81152 * 32;

    __nv_bfloat16* wf1H = (__nv_bfloat16*)skipbuf;
    __nv_bfloat16* wf1L = wf1H + 10387456;
    __nv_bfloat16* we2H = wf1L + 10387456;
    __nv_bfloat16* we2L = we2H + 4096;

    cudaFuncSetAttribute(layer_mma, cudaFuncAttributeMaxDynamicSharedMemorySize, L_SMEM);
    cudaFuncSetAttribute(mega_gemm, cudaFuncAttributeMaxDynamicSharedMemorySize, MG_SMEM);
    cudaFuncSetAttribute(end2_mma, cudaFuncAttributeMaxDynamicSharedMemorySize, E2_SMEM);

    // fused transpose + start conv -> stream planes in r1
    start_fused<<<160, 256>>>(x, start_w, s1H, s1L);

    prepw_kernel<<<320, 256>>>(skip_w, end1_w, wtc);
    prepl_kernel<<<120, 256>>>(filter_w, gate_w, res_w, wl);
    {
        dim3 gp(10, 1024);
        prepfc_kernel<<<gp, 256>>>(fc_w1, wf1H, wf1L);
        prepe2_kernel<<<16, 256>>>(end2_w, we2H, we2L);
    }

    // layers
    const int QQ[6]  = {327424, 327168, 326656, 326400, 326144, 325632};
    const int NR[6]  = {256, 512, 1024, 256, 512, 1024};
    const int SS[6]  = {0, 256, 512, 0, 256, 512};
    const int OFF[6] = {1792, 1536, 1024, 768, 512, 0};

    __nv_bfloat16 *curH = s1H, *curL = s1L, *nxtH = s2H, *nxtL = s2L;
    for (int i = 0; i < 6; i++) {
        int nblk = QQ[i] >> 7;
        layer_mma<<<nblk, 256, L_SMEM>>>(curH, curL, wl + i * 10240,
                                         gtH, gtL, nxtH, nxtL,
                                         NR[i], SS[i], OFF[i], i * 64, (i < 5) ? 1 : 0);
        __nv_bfloat16* t;
        t = curH; curH = nxtH; nxtH = t;
        t = curL; curL = nxtL; nxtL = t;
    }

    // fused skip + end1 -> y1 pairs
    mega_gemm<<<NP / 128, 256, MG_SMEM>>>(gtH, gtL, wskH, wskL, we1H, we1L, end1_b, y1H, y1L);

    // fused pool1 + end2 -> y2 pairs
    end2_mma<<<635, 256, E2_SMEM>>>(y1H, y1L, we2H, we2L, end2_b, y2H, y2L);

    // pool2 -> p2 pairs
    pool2_kernel<<<(81152 * 16 + 255) / 256, 256>>>(y2H, y2L, p2H, p2L);

    // fc1 (mma, split-K=8) -> partials -> reduce(+bias,relu) -> f1 fp32
    {
        dim3 gg(2, 8, 8);
        fc1_mma<<<gg, 256>>>(p2H, p2L, wf1H, wf1L, f1p);
        int total = 1024 * 256;
        reduce_kernel<<<(total + 255) / 256, 256>>>(f1p, fc_b1, f1, 8, total, total);
    }
    // fc2: 256 x 1024 x 256, fp32 split-K=4
    {
        ALRowG al = {fc_w2, 1024, 256};
        BLRow bl = {f1, 256};
        EPPart ep = {f2p, 256 * 256};
        dim3 gg(4, 4, 4);
        gemm64_kernel<<<gg, 256>>>(32, 8, al, bl, ep);
        int total = 256 * 256;
        reduce_kernel<<<(total + 255) / 256, 256>>>(f2p, fc_b2, f2, 4, total, total);
    }
    // fc3 + softmax + argmax
    fc3_softmax_kernel<<<1, 256>>>(f2, fc_w3, fc_b3, (float*)d_out);
}